// round 1
// baseline (speedup 1.0000x reference)
#include <cuda_runtime.h>
#include <math.h>

#define C_ 768
#define DQ 16
#define HQ 32
#define WQ 32
#define NQ 16384
#define D2 8
#define H2 16
#define W2 16
#define N2 2048
#define KCONV 6144

#define NQ_DST 2048
#define NQ_A 14336
#define RQ 8192
#define UNMQ 6144
#define NQTOK 8192

#define NKV_DST 256
#define NKV_A 1792
#define RKV 1024
#define UNMKV 768
#define NKVTOK 1024

#define NH 8
#define DH 96

// ---------------- scratch (static device memory; no allocations) ----------------
__device__ float g_xi2c[(size_t)N2 * KCONV];      // im2col for SR conv
__device__ float g_wt[(size_t)C_ * KCONV];        // transposed conv weights
__device__ float g_xk[N2 * C_];                   // conv+LN output (in-place LN)
__device__ float g_invnq[NQ];
__device__ float g_invnk[N2];
__device__ int g_atok_q[NQ_A];
__device__ int g_btok_q[NQ_DST];
__device__ int g_atok_k[NKV_A];
__device__ int g_btok_k[NKV_DST];
__device__ unsigned long long g_nm_q[NQ_A];       // packed (mono(max)<<32 | ~argmax)
__device__ unsigned long long g_nm_k[NKV_A];
__device__ unsigned long long g_thr[2];
__device__ int g_srcn_q[RQ], g_srcd_q[RQ], g_unm_q[UNMQ];
__device__ int g_srcn_k[RKV], g_srcd_k[RKV], g_unm_k[UNMKV];
__device__ int g_ctr[4];
__device__ float g_cnt_q[NQ_DST], g_cnt_k[NKV_DST];
__device__ float g_xq[NQTOK * C_];
__device__ float g_xkm[NKVTOK * C_];
__device__ float g_qb[NQTOK * C_];
__device__ float g_kv[NKVTOK * 2 * C_];
__device__ float g_sc[(size_t)NH * NQTOK * NKVTOK];   // attention scores (268MB)
__device__ float g_ao[NQTOK * C_];
__device__ float g_fp[NQTOK * C_];

// ---------------- helpers ----------------
struct BsmP {
    int* atok; int* btok;
    unsigned long long* nm; unsigned long long* thr;
    int* srcn; int* srcd; int* unm;
    int* csrc; int* cunm;
    float* cnt; float* xm;
    const float* invn;
    int NA, NB, R, UNM;
};

__device__ __forceinline__ BsmP getp(int w) {
    BsmP p;
    if (w == 0) {
        p.atok = g_atok_q; p.btok = g_btok_q; p.nm = g_nm_q; p.thr = &g_thr[0];
        p.srcn = g_srcn_q; p.srcd = g_srcd_q; p.unm = g_unm_q;
        p.csrc = &g_ctr[0]; p.cunm = &g_ctr[1];
        p.cnt = g_cnt_q; p.xm = g_xq; p.invn = g_invnq;
        p.NA = NQ_A; p.NB = NQ_DST; p.R = RQ; p.UNM = UNMQ;
    } else {
        p.atok = g_atok_k; p.btok = g_btok_k; p.nm = g_nm_k; p.thr = &g_thr[1];
        p.srcn = g_srcn_k; p.srcd = g_srcd_k; p.unm = g_unm_k;
        p.csrc = &g_ctr[2]; p.cunm = &g_ctr[3];
        p.cnt = g_cnt_k; p.xm = g_xkm; p.invn = g_invnk;
        p.NA = NKV_A; p.NB = NKV_DST; p.R = RKV; p.UNM = UNMKV;
    }
    return p;
}

__device__ __forceinline__ unsigned int fmono(float f) {
    unsigned int b = __float_as_uint(f);
    return b ^ ((b & 0x80000000u) ? 0xFFFFFFFFu : 0x80000000u);
}

__device__ __forceinline__ float blockReduce(float v, int ismax) {
    __shared__ float sh[40];
    __syncthreads();
    #pragma unroll
    for (int o = 16; o > 0; o >>= 1) {
        float u = __shfl_down_sync(0xffffffffu, v, o);
        v = ismax ? fmaxf(v, u) : (v + u);
    }
    if ((threadIdx.x & 31) == 0) sh[threadIdx.x >> 5] = v;
    __syncthreads();
    if (threadIdx.x == 0) {
        int nw = (blockDim.x + 31) >> 5;
        float r = sh[0];
        for (int i = 1; i < nw; i++) r = ismax ? fmaxf(r, sh[i]) : (r + sh[i]);
        sh[39] = r;
    }
    __syncthreads();
    return sh[39];
}

// number of dst (all-even-coordinate) tokens with flat index < n
__device__ __forceinline__ int dst_before(int z, int y, int x, int HH, int WW) {
    int planes = ((z + 1) >> 1) * ((HH >> 1) * (WW >> 1));
    int extra = 0;
    if ((z & 1) == 0) {
        extra = ((y + 1) >> 1) * (WW >> 1);
        if ((y & 1) == 0) extra += ((x + 1) >> 1);
    }
    return planes + extra;
}

// ---------------- setup kernels ----------------
__global__ void k_reset() {
    int t = blockIdx.x * blockDim.x + threadIdx.x;
    if (t < NQ_A) g_nm_q[t] = 0ull;
    if (t < NKV_A) g_nm_k[t] = 0ull;
    if (t < 4) g_ctr[t] = 0;
}

__global__ void k_tokmap(int w, int DD, int HH, int WW) {
    BsmP p = getp(w);
    int n = blockIdx.x * blockDim.x + threadIdx.x;
    int NN = DD * HH * WW;
    if (n >= NN) return;
    int z = n / (HH * WW); int rem = n % (HH * WW); int y = rem / WW; int x = rem % WW;
    int db = dst_before(z, y, x, HH, WW);
    bool isdst = (((z | y | x) & 1) == 0);
    if (isdst) p.btok[db] = n; else p.atok[n - db] = n;
}

__global__ void k_invn_x(const float* __restrict__ X) {
    int m = blockIdx.x;
    float ss = 0.f;
    for (int c = threadIdx.x; c < C_; c += 256) { float v = X[m * C_ + c]; ss += v * v; }
    ss = blockReduce(ss, 0);
    if (threadIdx.x == 0) g_invnq[m] = rsqrtf(ss);
}

__global__ void k_wtrans(const float* __restrict__ srw) {
    int t = blockIdx.x * blockDim.x + threadIdx.x;
    if (t >= C_ * KCONV) return;
    int o = t / KCONV, k = t % KCONV;
    int dzyx = k / C_, i = k % C_;
    g_wt[t] = srw[o * KCONV + i * 8 + dzyx];
}

__global__ void k_im2col(const float* __restrict__ x) {
    int t = blockIdx.x * blockDim.x + threadIdx.x;
    if (t >= N2 * KCONV) return;
    int m = t / KCONV, k = t % KCONV;
    int dzyx = k / C_, i = k % C_;
    int z2 = m / (H2 * W2), y2 = (m / W2) % H2, x2 = m % W2;
    int z = 2 * z2 + (dzyx >> 2), y = 2 * y2 + ((dzyx >> 1) & 1), xx = 2 * x2 + (dzyx & 1);
    g_xi2c[t] = x[(z * (HQ * WQ) + y * WQ + xx) * C_ + i];
}

// LN in place on g_xk, also computes row inv-norm of LN output
__global__ void k_ln(const float* __restrict__ g, const float* __restrict__ b) {
    int m = blockIdx.x;
    float s = 0.f, ss = 0.f;
    for (int c = threadIdx.x; c < C_; c += 256) { float v = g_xk[m * C_ + c]; s += v; ss += v * v; }
    s = blockReduce(s, 0);
    ss = blockReduce(ss, 0);
    float mean = s * (1.0f / C_);
    float var = ss * (1.0f / C_) - mean * mean;
    float rstd = rsqrtf(var + 1e-5f);
    float s2 = 0.f;
    for (int c = threadIdx.x; c < C_; c += 256) {
        float v = (g_xk[m * C_ + c] - mean) * rstd * g[c] + b[c];
        g_xk[m * C_ + c] = v;
        s2 += v * v;
    }
    s2 = blockReduce(s2, 0);
    if (threadIdx.x == 0) g_invnk[m] = rsqrtf(s2);
}

// ---------------- generic fp32 GEMM: C[M,N] = alpha * A[M,K] @ B[N,K]^T (+bias) ----------------
__global__ void __launch_bounds__(256)
k_gemm_nt(const float* __restrict__ A, int lda, const float* __restrict__ B, int ldb,
          float* __restrict__ Cm, int ldc, int M, int N, int K,
          const float* __restrict__ bias, float alpha) {
    __shared__ float As[16][68], Bs[16][68];
    int m0 = blockIdx.y * 64, n0 = blockIdx.x * 64;
    int tx = threadIdx.x, ty = threadIdx.y;
    int tid = ty * 16 + tx;
    float acc[4][4] = {};
    for (int k0 = 0; k0 < K; k0 += 16) {
        #pragma unroll
        for (int i = 0; i < 4; i++) {
            int idx = tid + i * 256; int r = idx >> 4; int kk = idx & 15;
            int mm = m0 + r, kg = k0 + kk;
            As[kk][r] = (mm < M && kg < K) ? A[(size_t)mm * lda + kg] : 0.f;
            int nn = n0 + r;
            Bs[kk][r] = (nn < N && kg < K) ? B[(size_t)nn * ldb + kg] : 0.f;
        }
        __syncthreads();
        #pragma unroll
        for (int kk = 0; kk < 16; kk++) {
            float ra[4], rb[4];
            #pragma unroll
            for (int i = 0; i < 4; i++) ra[i] = As[kk][ty * 4 + i];
            #pragma unroll
            for (int j = 0; j < 4; j++) rb[j] = Bs[kk][tx * 4 + j];
            #pragma unroll
            for (int i = 0; i < 4; i++)
                #pragma unroll
                for (int j = 0; j < 4; j++) acc[i][j] += ra[i] * rb[j];
        }
        __syncthreads();
    }
    #pragma unroll
    for (int i = 0; i < 4; i++) {
        int mm = m0 + ty * 4 + i; if (mm >= M) continue;
        #pragma unroll
        for (int j = 0; j < 4; j++) {
            int nn = n0 + tx * 4 + j; if (nn >= N) continue;
            float v = acc[i][j] * alpha;
            if (bias) v += bias[nn];
            Cm[(size_t)mm * ldc + nn] = v;
        }
    }
}

// C[M,N] = A[M,K] @ B[K,N]  (B non-transposed)
__global__ void __launch_bounds__(256)
k_gemm_nn(const float* __restrict__ A, int lda, const float* __restrict__ B, int ldb,
          float* __restrict__ Cm, int ldc, int M, int N, int K) {
    __shared__ float As[16][68], Bs[16][68];
    int m0 = blockIdx.y * 64, n0 = blockIdx.x * 64;
    int tx = threadIdx.x, ty = threadIdx.y;
    int tid = ty * 16 + tx;
    float acc[4][4] = {};
    for (int k0 = 0; k0 < K; k0 += 16) {
        #pragma unroll
        for (int i = 0; i < 4; i++) {
            int idx = tid + i * 256;
            { int r = idx >> 4; int kk = idx & 15;
              int mm = m0 + r, kg = k0 + kk;
              As[kk][r] = (mm < M && kg < K) ? A[(size_t)mm * lda + kg] : 0.f; }
            { int kk = idx >> 6; int c = idx & 63;
              int kg = k0 + kk, nn = n0 + c;
              Bs[kk][c] = (kg < K && nn < N) ? B[(size_t)kg * ldb + nn] : 0.f; }
        }
        __syncthreads();
        #pragma unroll
        for (int kk = 0; kk < 16; kk++) {
            float ra[4], rb[4];
            #pragma unroll
            for (int i = 0; i < 4; i++) ra[i] = As[kk][ty * 4 + i];
            #pragma unroll
            for (int j = 0; j < 4; j++) rb[j] = Bs[kk][tx * 4 + j];
            #pragma unroll
            for (int i = 0; i < 4; i++)
                #pragma unroll
                for (int j = 0; j < 4; j++) acc[i][j] += ra[i] * rb[j];
        }
        __syncthreads();
    }
    #pragma unroll
    for (int i = 0; i < 4; i++) {
        int mm = m0 + ty * 4 + i; if (mm >= M) continue;
        #pragma unroll
        for (int j = 0; j < 4; j++) {
            int nn = n0 + tx * 4 + j; if (nn >= N) continue;
            Cm[(size_t)mm * ldc + nn] = acc[i][j];
        }
    }
}

// ---------------- fused similarity GEMM + rowwise packed max/argmax ----------------
__global__ void __launch_bounds__(256)
k_scores(int w, const float* __restrict__ X) {
    BsmP p = getp(w);
    __shared__ float As[16][68], Bs[16][68];
    __shared__ int arow[64], brow[64];
    __shared__ float ainv[64], binv[64];
    __shared__ unsigned long long sred[64][17];
    int m0 = blockIdx.y * 64, n0 = blockIdx.x * 64;
    int tx = threadIdx.x, ty = threadIdx.y;
    int tid = ty * 16 + tx;
    if (tid < 64) {
        int mm = m0 + tid;
        int an = (mm < p.NA) ? p.atok[mm] : -1;
        arow[tid] = an; ainv[tid] = (an >= 0) ? p.invn[an] : 0.f;
        int nn = n0 + tid;
        int bn = (nn < p.NB) ? p.btok[nn] : -1;
        brow[tid] = bn; binv[tid] = (bn >= 0) ? p.invn[bn] : 0.f;
    }
    __syncthreads();
    float acc[4][4] = {};
    for (int k0 = 0; k0 < C_; k0 += 16) {
        #pragma unroll
        for (int i = 0; i < 4; i++) {
            int idx = tid + i * 256; int r = idx >> 4; int kk = idx & 15;
            int an = arow[r];
            As[kk][r] = (an >= 0) ? X[an * C_ + k0 + kk] : 0.f;
            int bn = brow[r];
            Bs[kk][r] = (bn >= 0) ? X[bn * C_ + k0 + kk] : 0.f;
        }
        __syncthreads();
        #pragma unroll
        for (int kk = 0; kk < 16; kk++) {
            float ra[4], rb[4];
            #pragma unroll
            for (int i = 0; i < 4; i++) ra[i] = As[kk][ty * 4 + i];
            #pragma unroll
            for (int j = 0; j < 4; j++) rb[j] = Bs[kk][tx * 4 + j];
            #pragma unroll
            for (int i = 0; i < 4; i++)
                #pragma unroll
                for (int j = 0; j < 4; j++) acc[i][j] += ra[i] * rb[j];
        }
        __syncthreads();
    }
    // epilogue: per-thread max over 4 cols per row, packed with (~j) for argmax ties
    #pragma unroll
    for (int i = 0; i < 4; i++) {
        int row = ty * 4 + i;
        float aiv = ainv[row];
        unsigned long long best = 0ull;
        #pragma unroll
        for (int j = 0; j < 4; j++) {
            int col = tx * 4 + j;
            int gj = n0 + col;
            if (brow[col] >= 0) {
                float v = acc[i][j] * aiv * binv[col];
                unsigned long long key = ((unsigned long long)fmono(v) << 32) |
                                         (unsigned long long)(0xFFFFFFFFu - (unsigned)gj);
                if (key > best) best = key;
            }
        }
        sred[row][tx] = best;
    }
    __syncthreads();
    if (tid < 64) {
        int mm = m0 + tid;
        if (mm < p.NA) {
            unsigned long long b = 0ull;
            #pragma unroll
            for (int t = 0; t < 16; t++) b = max(b, sred[tid][t]);
            atomicMax(&p.nm[mm], b);
        }
    }
}

// ---------------- exact top-r radix select on 64-bit keys ----------------
__global__ void k_select(int w) {
    BsmP p = getp(w);
    __shared__ unsigned int hist[256];
    __shared__ unsigned long long s_pref, s_mask;
    __shared__ int s_need;
    if (threadIdx.x == 0) { s_pref = 0ull; s_mask = 0ull; s_need = p.R; }
    __syncthreads();
    for (int shift = 56; shift >= 0; shift -= 8) {
        hist[threadIdx.x] = 0u;
        __syncthreads();
        unsigned long long pref = s_pref, mask = s_mask;
        for (int m = threadIdx.x; m < p.NA; m += 256) {
            unsigned long long key = (p.nm[m] & 0xFFFFFFFF00000000ull) |
                                     (unsigned long long)(0xFFFFFFFFu - (unsigned)m);
            if ((key & mask) == pref)
                atomicAdd(&hist[(unsigned)(key >> shift) & 255u], 1u);
        }
        __syncthreads();
        if (threadIdx.x == 0) {
            int need = s_need, cum = 0, d;
            for (d = 255; d >= 0; d--) {
                int h = (int)hist[d];
                if (cum + h >= need) break;
                cum += h;
            }
            s_need = need - cum;
            s_pref = s_pref | (((unsigned long long)d) << shift);
            s_mask = s_mask | (255ull << shift);
        }
        __syncthreads();
    }
    if (threadIdx.x == 0) *p.thr = s_pref;
}

__global__ void k_classify(int w) {
    BsmP p = getp(w);
    int m = blockIdx.x * blockDim.x + threadIdx.x;
    if (m >= p.NA) return;
    unsigned long long pk = p.nm[m];
    unsigned long long key = (pk & 0xFFFFFFFF00000000ull) |
                             (unsigned long long)(0xFFFFFFFFu - (unsigned)m);
    if (key >= *p.thr) {
        int s = atomicAdd(p.csrc, 1);
        p.srcn[s] = p.atok[m];
        p.srcd[s] = (int)(0xFFFFFFFFu - (unsigned)(pk & 0xFFFFFFFFull));
    } else {
        int s = atomicAdd(p.cunm, 1);
        p.unm[s] = p.atok[m];
    }
}

// ---------------- merge ----------------
__global__ void k_minit(int w, const float* __restrict__ X) {
    BsmP p = getp(w); int j = blockIdx.x;
    int n = p.btok[j];
    for (int c = threadIdx.x; c < C_; c += blockDim.x)
        p.xm[(p.UNM + j) * C_ + c] = X[n * C_ + c];
    if (threadIdx.x == 0) p.cnt[j] = 1.f;
}
__global__ void k_maccum(int w, const float* __restrict__ X) {
    BsmP p = getp(w); int s = blockIdx.x;
    int n = p.srcn[s]; int dj = p.srcd[s];
    for (int c = threadIdx.x; c < C_; c += blockDim.x)
        atomicAdd(&p.xm[(p.UNM + dj) * C_ + c], X[n * C_ + c]);
    if (threadIdx.x == 0) atomicAdd(&p.cnt[dj], 1.f);
}
__global__ void k_mdiv(int w) {
    BsmP p = getp(w); int j = blockIdx.x;
    float inv = 1.f / p.cnt[j];
    for (int c = threadIdx.x; c < C_; c += blockDim.x)
        p.xm[(p.UNM + j) * C_ + c] *= inv;
}
__global__ void k_mgather(int w, const float* __restrict__ X) {
    BsmP p = getp(w); int i = blockIdx.x;
    int n = p.unm[i];
    for (int c = threadIdx.x; c < C_; c += blockDim.x)
        p.xm[i * C_ + c] = X[n * C_ + c];
}

// ---------------- softmax ----------------
__global__ void k_softmax() {
    size_t row = blockIdx.x;
    float* pp = g_sc + row * NKVTOK;
    float mx = -3.4e38f;
    for (int c = threadIdx.x; c < NKVTOK; c += 256) mx = fmaxf(mx, pp[c]);
    mx = blockReduce(mx, 1);
    float s = 0.f;
    for (int c = threadIdx.x; c < NKVTOK; c += 256) {
        float e = expf(pp[c] - mx); pp[c] = e; s += e;
    }
    s = blockReduce(s, 0);
    float inv = 1.f / s;
    for (int c = threadIdx.x; c < NKVTOK; c += 256) pp[c] *= inv;
}

// ---------------- unmerge ----------------
__global__ void k_unmerge_dst(const float* __restrict__ fp, float* __restrict__ out) {
    int j = blockIdx.x; int n = g_btok_q[j];
    for (int c = threadIdx.x; c < C_; c += blockDim.x)
        out[n * C_ + c] = fp[(UNMQ + j) * C_ + c];
}
__global__ void k_unmerge_unm(const float* __restrict__ fp, float* __restrict__ out) {
    int i = blockIdx.x; int n = g_unm_q[i];
    for (int c = threadIdx.x; c < C_; c += blockDim.x)
        out[n * C_ + c] = fp[i * C_ + c];
}
__global__ void k_unmerge_src(const float* __restrict__ fp, float* __restrict__ out) {
    int s = blockIdx.x; int n = g_srcn_q[s]; int dj = g_srcd_q[s];
    for (int c = threadIdx.x; c < C_; c += blockDim.x)
        out[n * C_ + c] = fp[(UNMQ + dj) * C_ + c];
}

// ---------------- host ----------------
extern "C" void kernel_launch(void* const* d_in, const int* in_sizes, int n_in,
                              void* d_out, int out_size) {
    const float* x   = (const float*)d_in[0];
    const float* srw = (const float*)d_in[1];
    const float* srb = (const float*)d_in[2];
    const float* lng = (const float*)d_in[3];
    const float* lnb = (const float*)d_in[4];
    const float* Wq  = (const float*)d_in[5];
    const float* Wkv = (const float*)d_in[6];
    const float* Wp  = (const float*)d_in[7];
    const float* bpb = (const float*)d_in[8];
    float* out = (float*)d_out;

    void *vp;
    float *p_xi2c, *p_wt, *p_xk, *p_xq, *p_xkm, *p_qb, *p_kv, *p_sc, *p_ao, *p_fp;
    cudaGetSymbolAddress(&vp, g_xi2c); p_xi2c = (float*)vp;
    cudaGetSymbolAddress(&vp, g_wt);   p_wt   = (float*)vp;
    cudaGetSymbolAddress(&vp, g_xk);   p_xk   = (float*)vp;
    cudaGetSymbolAddress(&vp, g_xq);   p_xq   = (float*)vp;
    cudaGetSymbolAddress(&vp, g_xkm);  p_xkm  = (float*)vp;
    cudaGetSymbolAddress(&vp, g_qb);   p_qb   = (float*)vp;
    cudaGetSymbolAddress(&vp, g_kv);   p_kv   = (float*)vp;
    cudaGetSymbolAddress(&vp, g_sc);   p_sc   = (float*)vp;
    cudaGetSymbolAddress(&vp, g_ao);   p_ao   = (float*)vp;
    cudaGetSymbolAddress(&vp, g_fp);   p_fp   = (float*)vp;

    dim3 blk(16, 16);

    k_reset<<<(NQ_A + 255) / 256, 256>>>();
    k_tokmap<<<(NQ + 255) / 256, 256>>>(0, DQ, HQ, WQ);
    k_tokmap<<<(N2 + 255) / 256, 256>>>(1, D2, H2, W2);
    k_invn_x<<<NQ, 256>>>(x);
    k_wtrans<<<(C_ * KCONV + 255) / 256, 256>>>(srw);
    k_im2col<<<(N2 * KCONV + 255) / 256, 256>>>(x);

    // SR conv as GEMM (+bias), then fused LN + inv-norm
    k_gemm_nt<<<dim3(C_ / 64, N2 / 64), blk>>>(p_xi2c, KCONV, p_wt, KCONV,
                                               p_xk, C_, N2, C_, KCONV, srb, 1.f);
    k_ln<<<N2, 256>>>(lng, lnb);

    // Q-side BSM: similarity max, exact top-RQ select, classify, merge
    k_scores<<<dim3(NQ_DST / 64, NQ_A / 64), blk>>>(0, x);
    k_select<<<1, 256>>>(0);
    k_classify<<<(NQ_A + 255) / 256, 256>>>(0);
    k_minit<<<NQ_DST, 256>>>(0, x);
    k_maccum<<<RQ, 256>>>(0, x);
    k_mdiv<<<NQ_DST, 256>>>(0);
    k_mgather<<<UNMQ, 256>>>(0, x);

    // KV-side BSM on LN'd conv output
    k_scores<<<dim3(NKV_DST / 64, NKV_A / 64), blk>>>(1, p_xk);
    k_select<<<1, 256>>>(1);
    k_classify<<<(NKV_A + 255) / 256, 256>>>(1);
    k_minit<<<NKV_DST, 256>>>(1, p_xk);
    k_maccum<<<RKV, 256>>>(1, p_xk);
    k_mdiv<<<NKV_DST, 256>>>(1);
    k_mgather<<<UNMKV, 256>>>(1, p_xk);

    // projections
    k_gemm_nt<<<dim3(C_ / 64, NQTOK / 64), blk>>>(p_xq, C_, Wq, C_,
                                                  p_qb, C_, NQTOK, C_, C_, nullptr, 1.f);
    k_gemm_nt<<<dim3(2 * C_ / 64, NKVTOK / 64), blk>>>(p_xkm, C_, Wkv, C_,
                                                       p_kv, 2 * C_, NKVTOK, 2 * C_, C_, nullptr, 1.f);

    // attention (two-pass): scores per head, softmax, attn@v
    float scale = 1.0f / sqrtf((float)DH);
    for (int h = 0; h < NH; h++) {
        k_gemm_nt<<<dim3(NKVTOK / 64, NQTOK / 64), blk>>>(
            p_qb + h * DH, C_, p_kv + h * DH, 2 * C_,
            p_sc + (size_t)h * NQTOK * NKVTOK, NKVTOK,
            NQTOK, NKVTOK, DH, nullptr, scale);
    }
    k_softmax<<<NH * NQTOK, 256>>>();
    for (int h = 0; h < NH; h++) {
        k_gemm_nn<<<dim3((DH + 63) / 64, NQTOK / 64), blk>>>(
            p_sc + (size_t)h * NQTOK * NKVTOK, NKVTOK,
            p_kv + C_ + h * DH, 2 * C_,
            p_ao + h * DH, C_, NQTOK, DH, NKVTOK);
    }

    // output projection + bias, then unmerge scatter
    k_gemm_nt<<<dim3(C_ / 64, NQTOK / 64), blk>>>(p_ao, C_, Wp, C_,
                                                  p_fp, C_, NQTOK, C_, C_, bpb, 1.f);
    k_unmerge_dst<<<NQ_DST, 256>>>(p_fp, out);
    k_unmerge_unm<<<UNMQ, 256>>>(p_fp, out);
    k_unmerge_src<<<RQ, 256>>>(p_fp, out);
}

// round 3
// speedup vs baseline: 1.0045x; 1.0045x over previous
#include <cuda_runtime.h>
#include <math.h>

#define C_ 768
#define DQ 16
#define HQ 32
#define WQ 32
#define NQ 16384
#define D2 8
#define H2 16
#define W2 16
#define N2 2048
#define KCONV 6144

#define NQ_DST 2048
#define NQ_A 14336
#define RQ 8192
#define UNMQ 6144
#define NQTOK 8192

#define NKV_DST 256
#define NKV_A 1792
#define RKV 1024
#define UNMKV 768
#define NKVTOK 1024

#define NH 8
#define DH 96

typedef unsigned long long ull;

// ---------------- scratch (static device memory; no allocations) ----------------
__device__ float g_xi2c[(size_t)N2 * KCONV];
__device__ float g_wt[(size_t)C_ * KCONV];
__device__ float g_xk[N2 * C_];
__device__ float g_invnq[NQ];
__device__ float g_invnk[N2];
__device__ int g_atok_q[NQ_A];
__device__ int g_btok_q[NQ_DST];
__device__ int g_atok_k[NKV_A];
__device__ int g_btok_k[NKV_DST];
__device__ ull g_nm_q[NQ_A];
__device__ ull g_nm_k[NKV_A];
__device__ ull g_thr[2];
__device__ int g_srcn_q[RQ], g_srcd_q[RQ], g_unm_q[UNMQ];
__device__ int g_srcn_k[RKV], g_srcd_k[RKV], g_unm_k[UNMKV];
__device__ int g_ctr[4];
__device__ float g_cnt_q[NQ_DST], g_cnt_k[NKV_DST];
__device__ float g_xq[NQTOK * C_];
__device__ float g_xkm[NKVTOK * C_];
__device__ float g_qb[NQTOK * C_];
__device__ float g_kv[NKVTOK * 2 * C_];
__device__ float g_vt[NH * DH * NKVTOK];
__device__ float g_sc[(size_t)NH * NQTOK * NKVTOK];
__device__ float g_ao[NQTOK * C_];
__device__ float g_fp[NQTOK * C_];

// ---------------- f32x2 helpers ----------------
__device__ __forceinline__ ull fma2(ull a, ull b, ull c) {
    ull d;
    asm("fma.rn.f32x2 %0, %1, %2, %3;" : "=l"(d) : "l"(a), "l"(b), "l"(c));
    return d;
}
__device__ __forceinline__ ull pack2(float x) {
    ull d;
    asm("mov.b64 %0, {%1, %1};" : "=l"(d) : "r"(__float_as_uint(x)));
    return d;
}
__device__ __forceinline__ float lo32(ull v) { return __uint_as_float((unsigned)v); }
__device__ __forceinline__ float hi32(ull v) { return __uint_as_float((unsigned)(v >> 32)); }

// ---------------- helpers ----------------
struct BsmP {
    int* atok; int* btok;
    ull* nm; ull* thr;
    int* srcn; int* srcd; int* unm;
    int* csrc; int* cunm;
    float* cnt; float* xm;
    const float* invn;
    int NA, NB, R, UNM;
};

__device__ __forceinline__ BsmP getp(int w) {
    BsmP p;
    if (w == 0) {
        p.atok = g_atok_q; p.btok = g_btok_q; p.nm = g_nm_q; p.thr = &g_thr[0];
        p.srcn = g_srcn_q; p.srcd = g_srcd_q; p.unm = g_unm_q;
        p.csrc = &g_ctr[0]; p.cunm = &g_ctr[1];
        p.cnt = g_cnt_q; p.xm = g_xq; p.invn = g_invnq;
        p.NA = NQ_A; p.NB = NQ_DST; p.R = RQ; p.UNM = UNMQ;
    } else {
        p.atok = g_atok_k; p.btok = g_btok_k; p.nm = g_nm_k; p.thr = &g_thr[1];
        p.srcn = g_srcn_k; p.srcd = g_srcd_k; p.unm = g_unm_k;
        p.csrc = &g_ctr[2]; p.cunm = &g_ctr[3];
        p.cnt = g_cnt_k; p.xm = g_xkm; p.invn = g_invnk;
        p.NA = NKV_A; p.NB = NKV_DST; p.R = RKV; p.UNM = UNMKV;
    }
    return p;
}

__device__ __forceinline__ unsigned int fmono(float f) {
    unsigned int b = __float_as_uint(f);
    return b ^ ((b & 0x80000000u) ? 0xFFFFFFFFu : 0x80000000u);
}

__device__ __forceinline__ float blockReduce(float v, int ismax) {
    __shared__ float sh[40];
    __syncthreads();
    #pragma unroll
    for (int o = 16; o > 0; o >>= 1) {
        float u = __shfl_down_sync(0xffffffffu, v, o);
        v = ismax ? fmaxf(v, u) : (v + u);
    }
    if ((threadIdx.x & 31) == 0) sh[threadIdx.x >> 5] = v;
    __syncthreads();
    if (threadIdx.x == 0) {
        int nw = (blockDim.x + 31) >> 5;
        float r = sh[0];
        for (int i = 1; i < nw; i++) r = ismax ? fmaxf(r, sh[i]) : (r + sh[i]);
        sh[39] = r;
    }
    __syncthreads();
    return sh[39];
}

__device__ __forceinline__ int dst_before(int z, int y, int x, int HH, int WW) {
    int planes = ((z + 1) >> 1) * ((HH >> 1) * (WW >> 1));
    int extra = 0;
    if ((z & 1) == 0) {
        extra = ((y + 1) >> 1) * (WW >> 1);
        if ((y & 1) == 0) extra += ((x + 1) >> 1);
    }
    return planes + extra;
}

// ---------------- setup kernels ----------------
__global__ void k_reset() {
    int t = blockIdx.x * blockDim.x + threadIdx.x;
    if (t < NQ_A) g_nm_q[t] = 0ull;
    if (t < NKV_A) g_nm_k[t] = 0ull;
    if (t < 4) g_ctr[t] = 0;
}

__global__ void k_tokmap(int w, int DD, int HH, int WW) {
    BsmP p = getp(w);
    int n = blockIdx.x * blockDim.x + threadIdx.x;
    int NN = DD * HH * WW;
    if (n >= NN) return;
    int z = n / (HH * WW); int rem = n % (HH * WW); int y = rem / WW; int x = rem % WW;
    int db = dst_before(z, y, x, HH, WW);
    bool isdst = (((z | y | x) & 1) == 0);
    if (isdst) p.btok[db] = n; else p.atok[n - db] = n;
}

__global__ void k_invn_x(const float* __restrict__ X) {
    int m = blockIdx.x;
    float ss = 0.f;
    const float4* row = (const float4*)(X + (size_t)m * C_);
    for (int c = threadIdx.x; c < C_ / 4; c += 64) {
        float4 v = row[c];
        ss += v.x * v.x + v.y * v.y + v.z * v.z + v.w * v.w;
    }
    ss = blockReduce(ss, 0);
    if (threadIdx.x == 0) g_invnq[m] = rsqrtf(ss);
}

__global__ void k_wtrans(const float* __restrict__ srw) {
    int t = blockIdx.x * blockDim.x + threadIdx.x;
    if (t >= C_ * KCONV) return;
    int o = t / KCONV, k = t % KCONV;
    int dzyx = k / C_, i = k % C_;
    g_wt[t] = srw[o * KCONV + i * 8 + dzyx];
}

__global__ void k_im2col(const float* __restrict__ x) {
    int t = blockIdx.x * blockDim.x + threadIdx.x;
    if (t >= N2 * KCONV) return;
    int m = t / KCONV, k = t % KCONV;
    int dzyx = k / C_, i = k % C_;
    int z2 = m / (H2 * W2), y2 = (m / W2) % H2, x2 = m % W2;
    int z = 2 * z2 + (dzyx >> 2), y = 2 * y2 + ((dzyx >> 1) & 1), xx = 2 * x2 + (dzyx & 1);
    g_xi2c[t] = x[(size_t)(z * (HQ * WQ) + y * WQ + xx) * C_ + i];
}

__global__ void k_ln(const float* __restrict__ g, const float* __restrict__ b) {
    int m = blockIdx.x;
    float s = 0.f, ss = 0.f;
    for (int c = threadIdx.x; c < C_; c += 256) { float v = g_xk[m * C_ + c]; s += v; ss += v * v; }
    s = blockReduce(s, 0);
    ss = blockReduce(ss, 0);
    float mean = s * (1.0f / C_);
    float var = ss * (1.0f / C_) - mean * mean;
    float rstd = rsqrtf(var + 1e-5f);
    float s2 = 0.f;
    for (int c = threadIdx.x; c < C_; c += 256) {
        float v = (g_xk[m * C_ + c] - mean) * rstd * g[c] + b[c];
        g_xk[m * C_ + c] = v;
        s2 += v * v;
    }
    s2 = blockReduce(s2, 0);
    if (threadIdx.x == 0) g_invnk[m] = rsqrtf(s2);
}

// ---------------- f32x2 packed GEMM: C[M,N] = alpha*A[M,K]@B[N,K]^T (+bias) ----------------
// 128x128 tile, BK=16, 256 threads, 8x8 microtile via fma.rn.f32x2
#define BM 128
#define BN 128
#define BK 16
#define LDAS 132

__global__ void __launch_bounds__(256)
k_gemm2_nt(const float* __restrict__ A, int lda, const float* __restrict__ B, int ldb,
           float* __restrict__ Cm, int ldc, int M, int N, int K,
           const float* __restrict__ bias, float alpha) {
    __shared__ float As[BK][LDAS], Bs[BK][LDAS];
    int m0 = blockIdx.y * BM, n0 = blockIdx.x * BN;
    int tid = threadIdx.x;
    int tx = tid & 15, ty = tid >> 4;
    ull acc[8][4];
    #pragma unroll
    for (int i = 0; i < 8; i++)
        #pragma unroll
        for (int j = 0; j < 4; j++) acc[i][j] = 0ull;

    for (int k0 = 0; k0 < K; k0 += BK) {
        #pragma unroll
        for (int it = 0; it < 2; it++) {
            int c = tid + it * 256;
            int r = c >> 2, kq = (c & 3) << 2;
            int mm = m0 + r;
            float4 va = make_float4(0.f, 0.f, 0.f, 0.f);
            if (mm < M) va = *(const float4*)(A + (size_t)mm * lda + k0 + kq);
            As[kq + 0][r] = va.x; As[kq + 1][r] = va.y; As[kq + 2][r] = va.z; As[kq + 3][r] = va.w;
            int nn = n0 + r;
            float4 vb = make_float4(0.f, 0.f, 0.f, 0.f);
            if (nn < N) vb = *(const float4*)(B + (size_t)nn * ldb + k0 + kq);
            Bs[kq + 0][r] = vb.x; Bs[kq + 1][r] = vb.y; Bs[kq + 2][r] = vb.z; Bs[kq + 3][r] = vb.w;
        }
        __syncthreads();
        #pragma unroll
        for (int kk = 0; kk < BK; kk++) {
            float4 a0 = *(const float4*)&As[kk][ty * 8];
            float4 a1 = *(const float4*)&As[kk][ty * 8 + 4];
            longlong2 b0 = *(const longlong2*)&Bs[kk][tx * 8];
            longlong2 b1 = *(const longlong2*)&Bs[kk][tx * 8 + 4];
            float av[8] = {a0.x, a0.y, a0.z, a0.w, a1.x, a1.y, a1.z, a1.w};
            #pragma unroll
            for (int i = 0; i < 8; i++) {
                ull pa = pack2(av[i]);
                acc[i][0] = fma2(pa, (ull)b0.x, acc[i][0]);
                acc[i][1] = fma2(pa, (ull)b0.y, acc[i][1]);
                acc[i][2] = fma2(pa, (ull)b1.x, acc[i][2]);
                acc[i][3] = fma2(pa, (ull)b1.y, acc[i][3]);
            }
        }
        __syncthreads();
    }
    #pragma unroll
    for (int i = 0; i < 8; i++) {
        int mm = m0 + ty * 8 + i;
        if (mm >= M) continue;
        float v[8];
        #pragma unroll
        for (int j2 = 0; j2 < 4; j2++) { v[2 * j2] = lo32(acc[i][j2]); v[2 * j2 + 1] = hi32(acc[i][j2]); }
        int nb = n0 + tx * 8;
        if (nb + 8 <= N) {
            float4 o0, o1;
            o0.x = v[0] * alpha; o0.y = v[1] * alpha; o0.z = v[2] * alpha; o0.w = v[3] * alpha;
            o1.x = v[4] * alpha; o1.y = v[5] * alpha; o1.z = v[6] * alpha; o1.w = v[7] * alpha;
            if (bias) {
                o0.x += bias[nb + 0]; o0.y += bias[nb + 1]; o0.z += bias[nb + 2]; o0.w += bias[nb + 3];
                o1.x += bias[nb + 4]; o1.y += bias[nb + 5]; o1.z += bias[nb + 6]; o1.w += bias[nb + 7];
            }
            *(float4*)(Cm + (size_t)mm * ldc + nb) = o0;
            *(float4*)(Cm + (size_t)mm * ldc + nb + 4) = o1;
        } else {
            #pragma unroll
            for (int j = 0; j < 8; j++) {
                int nn = nb + j;
                if (nn < N) {
                    float o = v[j] * alpha;
                    if (bias) o += bias[nn];
                    Cm[(size_t)mm * ldc + nn] = o;
                }
            }
        }
    }
}

// ---------------- fused similarity GEMM + rowwise packed max/argmax (f32x2) ----------------
__global__ void __launch_bounds__(256)
k_scores2(int w, const float* __restrict__ X) {
    BsmP p = getp(w);
    __shared__ float As[BK][LDAS], Bs[BK][LDAS];
    __shared__ int arow[128], brow[128];
    __shared__ float ainv[128], binv[128];
    int m0 = blockIdx.y * BM, n0 = blockIdx.x * BN;
    int tid = threadIdx.x;
    int tx = tid & 15, ty = tid >> 4;
    if (tid < 128) {
        int an = p.atok[m0 + tid];
        arow[tid] = an; ainv[tid] = p.invn[an];
        int bn = p.btok[n0 + tid];
        brow[tid] = bn; binv[tid] = p.invn[bn];
    }
    __syncthreads();
    ull acc[8][4];
    #pragma unroll
    for (int i = 0; i < 8; i++)
        #pragma unroll
        for (int j = 0; j < 4; j++) acc[i][j] = 0ull;

    for (int k0 = 0; k0 < C_; k0 += BK) {
        #pragma unroll
        for (int it = 0; it < 2; it++) {
            int c = tid + it * 256;
            int r = c >> 2, kq = (c & 3) << 2;
            float4 va = *(const float4*)(X + (size_t)arow[r] * C_ + k0 + kq);
            As[kq + 0][r] = va.x; As[kq + 1][r] = va.y; As[kq + 2][r] = va.z; As[kq + 3][r] = va.w;
            float4 vb = *(const float4*)(X + (size_t)brow[r] * C_ + k0 + kq);
            Bs[kq + 0][r] = vb.x; Bs[kq + 1][r] = vb.y; Bs[kq + 2][r] = vb.z; Bs[kq + 3][r] = vb.w;
        }
        __syncthreads();
        #pragma unroll
        for (int kk = 0; kk < BK; kk++) {
            float4 a0 = *(const float4*)&As[kk][ty * 8];
            float4 a1 = *(const float4*)&As[kk][ty * 8 + 4];
            longlong2 b0 = *(const longlong2*)&Bs[kk][tx * 8];
            longlong2 b1 = *(const longlong2*)&Bs[kk][tx * 8 + 4];
            float av[8] = {a0.x, a0.y, a0.z, a0.w, a1.x, a1.y, a1.z, a1.w};
            #pragma unroll
            for (int i = 0; i < 8; i++) {
                ull pa = pack2(av[i]);
                acc[i][0] = fma2(pa, (ull)b0.x, acc[i][0]);
                acc[i][1] = fma2(pa, (ull)b0.y, acc[i][1]);
                acc[i][2] = fma2(pa, (ull)b1.x, acc[i][2]);
                acc[i][3] = fma2(pa, (ull)b1.y, acc[i][3]);
            }
        }
        __syncthreads();
    }
    // epilogue: per-row packed max/argmax, half-warp shuffle reduce, atomicMax
    #pragma unroll
    for (int i = 0; i < 8; i++) {
        int row = ty * 8 + i;
        float aiv = ainv[row];
        ull best = 0ull;
        #pragma unroll
        for (int j2 = 0; j2 < 4; j2++) {
            int c0 = tx * 8 + 2 * j2;
            float lo = lo32(acc[i][j2]) * aiv * binv[c0];
            float hi = hi32(acc[i][j2]) * aiv * binv[c0 + 1];
            int g0 = n0 + c0;
            ull klo = ((ull)fmono(lo) << 32) | (ull)(0xFFFFFFFFu - (unsigned)g0);
            ull khi = ((ull)fmono(hi) << 32) | (ull)(0xFFFFFFFFu - (unsigned)(g0 + 1));
            ull kb = klo > khi ? klo : khi;
            if (kb > best) best = kb;
        }
        {
            ull o;
            o = __shfl_xor_sync(0xffffffffu, best, 8);  if (o > best) best = o;
            o = __shfl_xor_sync(0xffffffffu, best, 4);  if (o > best) best = o;
            o = __shfl_xor_sync(0xffffffffu, best, 2);  if (o > best) best = o;
            o = __shfl_xor_sync(0xffffffffu, best, 1);  if (o > best) best = o;
        }
        if (tx == 0) atomicMax(&p.nm[m0 + row], best);
    }
}

// ---------------- exact top-r radix select ----------------
__global__ void k_select(int w) {
    BsmP p = getp(w);
    __shared__ unsigned int hist[256];
    __shared__ ull s_pref, s_mask;
    __shared__ int s_need;
    if (threadIdx.x == 0) { s_pref = 0ull; s_mask = 0ull; s_need = p.R; }
    __syncthreads();
    for (int shift = 56; shift >= 0; shift -= 8) {
        hist[threadIdx.x] = 0u;
        __syncthreads();
        ull pref = s_pref, mask = s_mask;
        for (int m = threadIdx.x; m < p.NA; m += 256) {
            ull key = (p.nm[m] & 0xFFFFFFFF00000000ull) |
                      (ull)(0xFFFFFFFFu - (unsigned)m);
            if ((key & mask) == pref)
                atomicAdd(&hist[(unsigned)(key >> shift) & 255u], 1u);
        }
        __syncthreads();
        if (threadIdx.x == 0) {
            int need = s_need, cum = 0, d;
            for (d = 255; d >= 0; d--) {
                int h = (int)hist[d];
                if (cum + h >= need) break;
                cum += h;
            }
            s_need = need - cum;
            s_pref = s_pref | (((ull)d) << shift);
            s_mask = s_mask | (255ull << shift);
        }
        __syncthreads();
    }
    if (threadIdx.x == 0) *p.thr = s_pref;
}

__global__ void k_classify(int w) {
    BsmP p = getp(w);
    int m = blockIdx.x * blockDim.x + threadIdx.x;
    if (m >= p.NA) return;
    ull pk = p.nm[m];
    ull key = (pk & 0xFFFFFFFF00000000ull) | (ull)(0xFFFFFFFFu - (unsigned)m);
    if (key >= *p.thr) {
        int s = atomicAdd(p.csrc, 1);
        p.srcn[s] = p.atok[m];
        p.srcd[s] = (int)(0xFFFFFFFFu - (unsigned)(pk & 0xFFFFFFFFull));
    } else {
        int s = atomicAdd(p.cunm, 1);
        p.unm[s] = p.atok[m];
    }
}

// ---------------- merge ----------------
__global__ void k_minit(int w, const float* __restrict__ X) {
    BsmP p = getp(w); int j = blockIdx.x;
    int n = p.btok[j];
    for (int c = threadIdx.x; c < C_; c += blockDim.x)
        p.xm[(size_t)(p.UNM + j) * C_ + c] = X[(size_t)n * C_ + c];
    if (threadIdx.x == 0) p.cnt[j] = 1.f;
}
__global__ void k_maccum(int w, const float* __restrict__ X) {
    BsmP p = getp(w); int s = blockIdx.x;
    int n = p.srcn[s]; int dj = p.srcd[s];
    for (int c = threadIdx.x; c < C_; c += blockDim.x)
        atomicAdd(&p.xm[(size_t)(p.UNM + dj) * C_ + c], X[(size_t)n * C_ + c]);
    if (threadIdx.x == 0) atomicAdd(&p.cnt[dj], 1.f);
}
__global__ void k_mdiv(int w) {
    BsmP p = getp(w); int j = blockIdx.x;
    float inv = 1.f / p.cnt[j];
    for (int c = threadIdx.x; c < C_; c += blockDim.x)
        p.xm[(size_t)(p.UNM + j) * C_ + c] *= inv;
}
__global__ void k_mgather(int w, const float* __restrict__ X) {
    BsmP p = getp(w); int i = blockIdx.x;
    int n = p.unm[i];
    for (int c = threadIdx.x; c < C_; c += blockDim.x)
        p.xm[(size_t)i * C_ + c] = X[(size_t)n * C_ + c];
}

// ---------------- V transpose (per head) ----------------
__global__ void k_vt() {
    int t = blockIdx.x * blockDim.x + threadIdx.x;
    if (t >= NH * DH * NKVTOK) return;
    int h = t / (DH * NKVTOK);
    int d = (t / NKVTOK) % DH;
    int k = t % NKVTOK;
    g_vt[t] = g_kv[(size_t)k * (2 * C_) + C_ + h * DH + d];
}

// ---------------- softmax ----------------
__global__ void k_softmax() {
    size_t row = blockIdx.x;
    float* pp = g_sc + row * NKVTOK;
    float mx = -3.4e38f;
    for (int c = threadIdx.x; c < NKVTOK; c += 256) mx = fmaxf(mx, pp[c]);
    mx = blockReduce(mx, 1);
    float s = 0.f;
    for (int c = threadIdx.x; c < NKVTOK; c += 256) {
        float e = expf(pp[c] - mx); pp[c] = e; s += e;
    }
    s = blockReduce(s, 0);
    float inv = 1.f / s;
    for (int c = threadIdx.x; c < NKVTOK; c += 256) pp[c] *= inv;
}

// ---------------- unmerge ----------------
__global__ void k_unmerge_dst(const float* __restrict__ fp, float* __restrict__ out) {
    int j = blockIdx.x; int n = g_btok_q[j];
    for (int c = threadIdx.x; c < C_; c += blockDim.x)
        out[(size_t)n * C_ + c] = fp[(size_t)(UNMQ + j) * C_ + c];
}
__global__ void k_unmerge_unm(const float* __restrict__ fp, float* __restrict__ out) {
    int i = blockIdx.x; int n = g_unm_q[i];
    for (int c = threadIdx.x; c < C_; c += blockDim.x)
        out[(size_t)n * C_ + c] = fp[(size_t)i * C_ + c];
}
__global__ void k_unmerge_src(const float* __restrict__ fp, float* __restrict__ out) {
    int s = blockIdx.x; int n = g_srcn_q[s]; int dj = g_srcd_q[s];
    for (int c = threadIdx.x; c < C_; c += blockDim.x)
        out[(size_t)n * C_ + c] = fp[(size_t)(UNMQ + dj) * C_ + c];
}

// ---------------- host ----------------
extern "C" void kernel_launch(void* const* d_in, const int* in_sizes, int n_in,
                              void* d_out, int out_size) {
    const float* x   = (const float*)d_in[0];
    const float* srw = (const float*)d_in[1];
    const float* srb = (const float*)d_in[2];
    const float* lng = (const float*)d_in[3];
    const float* lnb = (const float*)d_in[4];
    const float* Wq  = (const float*)d_in[5];
    const float* Wkv = (const float*)d_in[6];
    const float* Wp  = (const float*)d_in[7];
    const float* bpb = (const float*)d_in[8];
    float* out = (float*)d_out;

    void *vp;
    float *p_xi2c, *p_wt, *p_xk, *p_xq, *p_xkm, *p_qb, *p_kv, *p_vt, *p_sc, *p_ao, *p_fp;
    cudaGetSymbolAddress(&vp, g_xi2c); p_xi2c = (float*)vp;
    cudaGetSymbolAddress(&vp, g_wt);   p_wt   = (float*)vp;
    cudaGetSymbolAddress(&vp, g_xk);   p_xk   = (float*)vp;
    cudaGetSymbolAddress(&vp, g_xq);   p_xq   = (float*)vp;
    cudaGetSymbolAddress(&vp, g_xkm);  p_xkm  = (float*)vp;
    cudaGetSymbolAddress(&vp, g_qb);   p_qb   = (float*)vp;
    cudaGetSymbolAddress(&vp, g_kv);   p_kv   = (float*)vp;
    cudaGetSymbolAddress(&vp, g_vt);   p_vt   = (float*)vp;
    cudaGetSymbolAddress(&vp, g_sc);   p_sc   = (float*)vp;
    cudaGetSymbolAddress(&vp, g_ao);   p_ao   = (float*)vp;
    cudaGetSymbolAddress(&vp, g_fp);   p_fp   = (float*)vp;

    k_reset<<<(NQ_A + 255) / 256, 256>>>();
    k_tokmap<<<(NQ + 255) / 256, 256>>>(0, DQ, HQ, WQ);
    k_tokmap<<<(N2 + 255) / 256, 256>>>(1, D2, H2, W2);
    k_invn_x<<<NQ, 64>>>(x);
    k_wtrans<<<(C_ * KCONV + 255) / 256, 256>>>(srw);
    k_im2col<<<(N2 * KCONV + 255) / 256, 256>>>(x);

    // SR conv as GEMM (+bias), then fused LN + inv-norm
    k_gemm2_nt<<<dim3(C_ / BN, N2 / BM), 256>>>(p_xi2c, KCONV, p_wt, KCONV,
                                                p_xk, C_, N2, C_, KCONV, srb, 1.f);
    k_ln<<<N2, 256>>>(lng, lnb);

    // Q-side BSM
    k_scores2<<<dim3(NQ_DST / BN, NQ_A / BM), 256>>>(0, x);
    k_select<<<1, 256>>>(0);
    k_classify<<<(NQ_A + 255) / 256, 256>>>(0);
    k_minit<<<NQ_DST, 256>>>(0, x);
    k_maccum<<<RQ, 256>>>(0, x);
    k_mdiv<<<NQ_DST, 256>>>(0);
    k_mgather<<<UNMQ, 256>>>(0, x);

    // KV-side BSM
    k_scores2<<<dim3(NKV_DST / BN, NKV_A / BM), 256>>>(1, p_xk);
    k_select<<<1, 256>>>(1);
    k_classify<<<(NKV_A + 255) / 256, 256>>>(1);
    k_minit<<<NKV_DST, 256>>>(1, p_xk);
    k_maccum<<<RKV, 256>>>(1, p_xk);
    k_mdiv<<<NKV_DST, 256>>>(1);
    k_mgather<<<UNMKV, 256>>>(1, p_xk);

    // projections
    k_gemm2_nt<<<dim3(C_ / BN, NQTOK / BM), 256>>>(p_xq, C_, Wq, C_,
                                                   p_qb, C_, NQTOK, C_, C_, nullptr, 1.f);
    k_gemm2_nt<<<dim3(2 * C_ / BN, NKVTOK / BM), 256>>>(p_xkm, C_, Wkv, C_,
                                                        p_kv, 2 * C_, NKVTOK, 2 * C_, C_, nullptr, 1.f);
    k_vt<<<(NH * DH * NKVTOK + 255) / 256, 256>>>();

    // attention (two-pass)
    float scale = 1.0f / sqrtf((float)DH);
    for (int h = 0; h < NH; h++) {
        k_gemm2_nt<<<dim3(NKVTOK / BN, NQTOK / BM), 256>>>(
            p_qb + h * DH, C_, p_kv + h * DH, 2 * C_,
            p_sc + (size_t)h * NQTOK * NKVTOK, NKVTOK,
            NQTOK, NKVTOK, DH, nullptr, scale);
    }
    k_softmax<<<NH * NQTOK, 256>>>();
    for (int h = 0; h < NH; h++) {
        k_gemm2_nt<<<dim3(1, NQTOK / BM), 256>>>(
            p_sc + (size_t)h * NQTOK * NKVTOK, NKVTOK,
            p_vt + (size_t)h * DH * NKVTOK, NKVTOK,
            p_ao + h * DH, C_, NQTOK, DH, NKVTOK, nullptr, 1.f);
    }

    // output projection + bias, then unmerge scatter
    k_gemm2_nt<<<dim3(C_ / BN, NQTOK / BM), 256>>>(p_ao, C_, Wp, C_,
                                                   p_fp, C_, NQTOK, C_, C_, bpb, 1.f);
    k_unmerge_dst<<<NQ_DST, 256>>>(p_fp, out);
    k_unmerge_unm<<<UNMQ, 256>>>(p_fp, out);
    k_unmerge_src<<<RQ, 256>>>(p_fp, out);
}

// round 11
// speedup vs baseline: 1.4014x; 1.3952x over previous
#include <cuda_runtime.h>
#include <cuda_bf16.h>
#include <math.h>

#define C_ 768
#define DQ 16
#define HQ 32
#define WQ 32
#define NQ 16384
#define D2 8
#define H2 16
#define W2 16
#define N2 2048
#define KCONV 6144

#define NQ_DST 2048
#define NQ_A 14336
#define RQ 8192
#define UNMQ 6144
#define NQTOK 8192

#define NKV_DST 256
#define NKV_A 1792
#define RKV 1024
#define UNMKV 768
#define NKVTOK 1024

#define NH 8
#define DH 96

typedef unsigned long long ull;

// ---------------- scratch (static device memory; no allocations) ----------------
__device__ float g_xi2c[(size_t)N2 * KCONV];
__device__ float g_wt[(size_t)C_ * KCONV];
__device__ float g_xk[N2 * C_];
__device__ float g_invnq[NQ];
__device__ float g_invnk[N2];
__device__ int g_atok_q[NQ_A];
__device__ int g_btok_q[NQ_DST];
__device__ int g_atok_k[NKV_A];
__device__ int g_btok_k[NKV_DST];
__device__ ull g_nm_q[NQ_A];
__device__ ull g_nm_k[NKV_A];
__device__ unsigned g_apxmax[NQ_A];
__device__ ull g_thr[2];
__device__ int g_srcn_q[RQ], g_srcd_q[RQ], g_unm_q[UNMQ];
__device__ int g_srcn_k[RKV], g_srcd_k[RKV], g_unm_k[UNMKV];
__device__ int g_ctr[4];
__device__ float g_cnt_q[NQ_DST], g_cnt_k[NKV_DST];
__device__ float g_xq[NQTOK * C_];
__device__ float g_xkm[NKVTOK * C_];
__device__ float g_qb[NQTOK * C_];
__device__ float g_kv[NKVTOK * 2 * C_];
__device__ float g_vt[NH * DH * NKVTOK];
__device__ float g_sc[(size_t)NH * NQTOK * NKVTOK];   // reused: scores-Q matrix, then attention
__device__ float g_ao[NQTOK * C_];
__device__ float g_fp[NQTOK * C_];
__device__ __nv_bfloat16 g_abf[(size_t)NQ_A * C_];
__device__ __nv_bfloat16 g_bbf[(size_t)NQ_DST * C_];

// ---------------- f32x2 helpers ----------------
__device__ __forceinline__ ull fma2(ull a, ull b, ull c) {
    ull d;
    asm("fma.rn.f32x2 %0, %1, %2, %3;" : "=l"(d) : "l"(a), "l"(b), "l"(c));
    return d;
}
__device__ __forceinline__ ull pack2(float x) {
    ull d;
    asm("mov.b64 %0, {%1, %1};" : "=l"(d) : "r"(__float_as_uint(x)));
    return d;
}
__device__ __forceinline__ float lo32(ull v) { return __uint_as_float((unsigned)v); }
__device__ __forceinline__ float hi32(ull v) { return __uint_as_float((unsigned)(v >> 32)); }

// ---------------- misc helpers ----------------
struct BsmP {
    int* atok; int* btok;
    ull* nm; ull* thr;
    int* srcn; int* srcd; int* unm;
    int* csrc; int* cunm;
    float* cnt; float* xm;
    const float* invn;
    int NA, NB, R, UNM;
};

__device__ __forceinline__ BsmP getp(int w) {
    BsmP p;
    if (w == 0) {
        p.atok = g_atok_q; p.btok = g_btok_q; p.nm = g_nm_q; p.thr = &g_thr[0];
        p.srcn = g_srcn_q; p.srcd = g_srcd_q; p.unm = g_unm_q;
        p.csrc = &g_ctr[0]; p.cunm = &g_ctr[1];
        p.cnt = g_cnt_q; p.xm = g_xq; p.invn = g_invnq;
        p.NA = NQ_A; p.NB = NQ_DST; p.R = RQ; p.UNM = UNMQ;
    } else {
        p.atok = g_atok_k; p.btok = g_btok_k; p.nm = g_nm_k; p.thr = &g_thr[1];
        p.srcn = g_srcn_k; p.srcd = g_srcd_k; p.unm = g_unm_k;
        p.csrc = &g_ctr[2]; p.cunm = &g_ctr[3];
        p.cnt = g_cnt_k; p.xm = g_xkm; p.invn = g_invnk;
        p.NA = NKV_A; p.NB = NKV_DST; p.R = RKV; p.UNM = UNMKV;
    }
    return p;
}

__device__ __forceinline__ unsigned int fmono(float f) {
    unsigned int b = __float_as_uint(f);
    return b ^ ((b & 0x80000000u) ? 0xFFFFFFFFu : 0x80000000u);
}
__device__ __forceinline__ float unmono(unsigned u) {
    unsigned b = (u & 0x80000000u) ? (u ^ 0x80000000u) : ~u;
    return __uint_as_float(b);
}

__device__ __forceinline__ float blockReduce(float v, int ismax) {
    __shared__ float sh[40];
    __syncthreads();
    #pragma unroll
    for (int o = 16; o > 0; o >>= 1) {
        float u = __shfl_down_sync(0xffffffffu, v, o);
        v = ismax ? fmaxf(v, u) : (v + u);
    }
    if ((threadIdx.x & 31) == 0) sh[threadIdx.x >> 5] = v;
    __syncthreads();
    if (threadIdx.x == 0) {
        int nw = (blockDim.x + 31) >> 5;
        float r = sh[0];
        for (int i = 1; i < nw; i++) r = ismax ? fmaxf(r, sh[i]) : (r + sh[i]);
        sh[39] = r;
    }
    __syncthreads();
    return sh[39];
}

__device__ __forceinline__ int dst_before(int z, int y, int x, int HH, int WW) {
    int planes = ((z + 1) >> 1) * ((HH >> 1) * (WW >> 1));
    int extra = 0;
    if ((z & 1) == 0) {
        extra = ((y + 1) >> 1) * (WW >> 1);
        if ((y & 1) == 0) extra += ((x + 1) >> 1);
    }
    return planes + extra;
}

// ---------------- setup kernels ----------------
__global__ void k_reset() {
    int t = blockIdx.x * blockDim.x + threadIdx.x;
    if (t < NQ_A) { g_nm_q[t] = 0ull; g_apxmax[t] = 0u; }
    if (t < NKV_A) g_nm_k[t] = 0ull;
    if (t < 4) g_ctr[t] = 0;
}

__global__ void k_tokmap(int w, int DD, int HH, int WW) {
    BsmP p = getp(w);
    int n = blockIdx.x * blockDim.x + threadIdx.x;
    int NN = DD * HH * WW;
    if (n >= NN) return;
    int z = n / (HH * WW); int rem = n % (HH * WW); int y = rem / WW; int x = rem % WW;
    int db = dst_before(z, y, x, HH, WW);
    bool isdst = (((z | y | x) & 1) == 0);
    if (isdst) p.btok[db] = n; else p.atok[n - db] = n;
}

__global__ void k_invn_x(const float* __restrict__ X) {
    int m = blockIdx.x;
    float ss = 0.f;
    const float4* row = (const float4*)(X + (size_t)m * C_);
    for (int c = threadIdx.x; c < C_ / 4; c += 64) {
        float4 v = row[c];
        ss += v.x * v.x + v.y * v.y + v.z * v.z + v.w * v.w;
    }
    ss = blockReduce(ss, 0);
    if (threadIdx.x == 0) g_invnq[m] = rsqrtf(ss);
}

__global__ void k_wtrans(const float* __restrict__ srw) {
    int t = blockIdx.x * blockDim.x + threadIdx.x;
    if (t >= C_ * KCONV) return;
    int o = t / KCONV, k = t % KCONV;
    int dzyx = k / C_, i = k % C_;
    g_wt[t] = srw[o * KCONV + i * 8 + dzyx];
}

__global__ void k_im2col(const float* __restrict__ x) {
    int t = blockIdx.x * blockDim.x + threadIdx.x;
    if (t >= N2 * KCONV) return;
    int m = t / KCONV, k = t % KCONV;
    int dzyx = k / C_, i = k % C_;
    int z2 = m / (H2 * W2), y2 = (m / W2) % H2, x2 = m % W2;
    int z = 2 * z2 + (dzyx >> 2), y = 2 * y2 + ((dzyx >> 1) & 1), xx = 2 * x2 + (dzyx & 1);
    g_xi2c[t] = x[(size_t)(z * (HQ * WQ) + y * WQ + xx) * C_ + i];
}

__global__ void k_ln(const float* __restrict__ g, const float* __restrict__ b) {
    int m = blockIdx.x;
    float s = 0.f, ss = 0.f;
    for (int c = threadIdx.x; c < C_; c += 256) { float v = g_xk[m * C_ + c]; s += v; ss += v * v; }
    s = blockReduce(s, 0);
    ss = blockReduce(ss, 0);
    float mean = s * (1.0f / C_);
    float var = ss * (1.0f / C_) - mean * mean;
    float rstd = rsqrtf(var + 1e-5f);
    float s2 = 0.f;
    for (int c = threadIdx.x; c < C_; c += 256) {
        float v = (g_xk[m * C_ + c] - mean) * rstd * g[c] + b[c];
        g_xk[m * C_ + c] = v;
        s2 += v * v;
    }
    s2 = blockReduce(s2, 0);
    if (threadIdx.x == 0) g_invnk[m] = rsqrtf(s2);
}

// bf16 copies of gathered a/b rows for the MMA scores GEMM
__global__ void k_tobf_a(const float* __restrict__ X) {
    int t = blockIdx.x * blockDim.x + threadIdx.x;
    if (t >= NQ_A * (C_ / 4)) return;
    int row = t / (C_ / 4), u = t % (C_ / 4);
    int an = g_atok_q[row];
    float4 v = ((const float4*)(X + (size_t)an * C_))[u];
    unsigned short s0 = __bfloat16_as_ushort(__float2bfloat16(v.x));
    unsigned short s1 = __bfloat16_as_ushort(__float2bfloat16(v.y));
    unsigned short s2 = __bfloat16_as_ushort(__float2bfloat16(v.z));
    unsigned short s3 = __bfloat16_as_ushort(__float2bfloat16(v.w));
    uint2 w;
    w.x = (unsigned)s0 | ((unsigned)s1 << 16);
    w.y = (unsigned)s2 | ((unsigned)s3 << 16);
    *(uint2*)(&g_abf[(size_t)row * C_ + u * 4]) = w;
}
__global__ void k_tobf_b(const float* __restrict__ X) {
    int t = blockIdx.x * blockDim.x + threadIdx.x;
    if (t >= NQ_DST * (C_ / 4)) return;
    int row = t / (C_ / 4), u = t % (C_ / 4);
    int bn = g_btok_q[row];
    float4 v = ((const float4*)(X + (size_t)bn * C_))[u];
    unsigned short s0 = __bfloat16_as_ushort(__float2bfloat16(v.x));
    unsigned short s1 = __bfloat16_as_ushort(__float2bfloat16(v.y));
    unsigned short s2 = __bfloat16_as_ushort(__float2bfloat16(v.z));
    unsigned short s3 = __bfloat16_as_ushort(__float2bfloat16(v.w));
    uint2 w;
    w.x = (unsigned)s0 | ((unsigned)s1 << 16);
    w.y = (unsigned)s2 | ((unsigned)s3 << 16);
    *(uint2*)(&g_bbf[(size_t)row * C_ + u * 4]) = w;
}

// ---------------- bf16 mma.sync scores GEMM (approx pass) ----------------
// 128x128 block tile, 8 warps (4x2), warp = 32x64 via 2x8 m16n8k16 tiles.
// D = A[128,768] @ B[128,768]^T; scaled scores -> g_sc, rowmax -> g_apxmax.
#define LDK 40

__global__ void __launch_bounds__(256)
k_scores_mma() {
    __shared__ __nv_bfloat16 As[128 * LDK], Bs[128 * LDK];
    __shared__ float s_ainv[128], s_binv[128];
    int tid = threadIdx.x;
    int wid = tid >> 5, lane = tid & 31;
    int g = lane >> 2, t = lane & 3;
    int warp_m = wid >> 1, warp_n = wid & 1;
    int m0 = blockIdx.y * 128, n0 = blockIdx.x * 128;

    if (tid < 128) {
        s_ainv[tid] = g_invnq[g_atok_q[m0 + tid]];
        s_binv[tid] = g_invnq[g_btok_q[n0 + tid]];
    }

    float acc[2][8][4];
    #pragma unroll
    for (int mt = 0; mt < 2; mt++)
        #pragma unroll
        for (int nt = 0; nt < 8; nt++)
            #pragma unroll
            for (int j = 0; j < 4; j++) acc[mt][nt][j] = 0.f;

    for (int k0 = 0; k0 < C_; k0 += 32) {
        __syncthreads();
        #pragma unroll
        for (int i = 0; i < 4; i++) {
            int q = tid + i * 256;
            int r = q >> 3, u = q & 7;
            *(ull*)&As[r * LDK + u * 4] = *(const ull*)&g_abf[(size_t)(m0 + r) * C_ + k0 + u * 4];
            *(ull*)&Bs[r * LDK + u * 4] = *(const ull*)&g_bbf[(size_t)(n0 + r) * C_ + k0 + u * 4];
        }
        __syncthreads();
        #pragma unroll
        for (int ks = 0; ks < 2; ks++) {
            int koff = ks * 16;
            unsigned afr[2][4];
            #pragma unroll
            for (int mt = 0; mt < 2; mt++) {
                int r = warp_m * 32 + mt * 16 + g;
                afr[mt][0] = *(const unsigned*)&As[r * LDK + koff + t * 2];
                afr[mt][1] = *(const unsigned*)&As[(r + 8) * LDK + koff + t * 2];
                afr[mt][2] = *(const unsigned*)&As[r * LDK + koff + t * 2 + 8];
                afr[mt][3] = *(const unsigned*)&As[(r + 8) * LDK + koff + t * 2 + 8];
            }
            #pragma unroll
            for (int nt = 0; nt < 8; nt++) {
                int c = warp_n * 64 + nt * 8 + g;
                unsigned b0 = *(const unsigned*)&Bs[c * LDK + koff + t * 2];
                unsigned b1 = *(const unsigned*)&Bs[c * LDK + koff + t * 2 + 8];
                #pragma unroll
                for (int mt = 0; mt < 2; mt++) {
                    asm volatile(
                        "mma.sync.aligned.m16n8k16.row.col.f32.bf16.bf16.f32 "
                        "{%0,%1,%2,%3}, {%4,%5,%6,%7}, {%8,%9}, {%0,%1,%2,%3};"
                        : "+f"(acc[mt][nt][0]), "+f"(acc[mt][nt][1]),
                          "+f"(acc[mt][nt][2]), "+f"(acc[mt][nt][3])
                        : "r"(afr[mt][0]), "r"(afr[mt][1]),
                          "r"(afr[mt][2]), "r"(afr[mt][3]),
                          "r"(b0), "r"(b1));
                }
            }
        }
    }

    // epilogue: scale + store + rowmax
    #pragma unroll
    for (int mt = 0; mt < 2; mt++) {
        int rloc0 = warp_m * 32 + mt * 16 + g;
        int rloc1 = rloc0 + 8;
        float aiv0 = s_ainv[rloc0], aiv1 = s_ainv[rloc1];
        float mx0 = -3.4e38f, mx1 = -3.4e38f;
        float* d0 = g_sc + (size_t)(m0 + rloc0) * NQ_DST + n0;
        float* d1 = g_sc + (size_t)(m0 + rloc1) * NQ_DST + n0;
        #pragma unroll
        for (int nt = 0; nt < 8; nt++) {
            int cloc = warp_n * 64 + nt * 8 + t * 2;
            float bi0 = s_binv[cloc], bi1 = s_binv[cloc + 1];
            float v00 = acc[mt][nt][0] * aiv0 * bi0;
            float v01 = acc[mt][nt][1] * aiv0 * bi1;
            float v10 = acc[mt][nt][2] * aiv1 * bi0;
            float v11 = acc[mt][nt][3] * aiv1 * bi1;
            *(float2*)(d0 + cloc) = make_float2(v00, v01);
            *(float2*)(d1 + cloc) = make_float2(v10, v11);
            mx0 = fmaxf(mx0, fmaxf(v00, v01));
            mx1 = fmaxf(mx1, fmaxf(v10, v11));
        }
        mx0 = fmaxf(mx0, __shfl_xor_sync(0xffffffffu, mx0, 1));
        mx0 = fmaxf(mx0, __shfl_xor_sync(0xffffffffu, mx0, 2));
        mx1 = fmaxf(mx1, __shfl_xor_sync(0xffffffffu, mx1, 1));
        mx1 = fmaxf(mx1, __shfl_xor_sync(0xffffffffu, mx1, 2));
        if (t == 0) {
            atomicMax(&g_apxmax[m0 + rloc0], fmono(mx0));
            atomicMax(&g_apxmax[m0 + rloc1], fmono(mx1));
        }
    }
}

// ---------------- exact refinement of rowmax/argmax ----------------
#define RMARGIN 0.01f
__global__ void __launch_bounds__(128)
k_refine(const float* __restrict__ X) {
    int row = blockIdx.x;
    int tid = threadIdx.x;
    float amax = unmono(g_apxmax[row]);
    float thr = amax - RMARGIN;
    int an = g_atok_q[row];
    float aiv = g_invnq[an];
    const float4* Xa = (const float4*)(X + (size_t)an * C_);
    const float* srow = g_sc + (size_t)row * NQ_DST;
    ull best = 0ull;
    for (int j = tid; j < NQ_DST; j += 128) {
        if (srow[j] >= thr) {
            int bn = g_btok_q[j];
            const float4* Xb = (const float4*)(X + (size_t)bn * C_);
            float s = 0.f;
            #pragma unroll 4
            for (int u = 0; u < C_ / 4; u++) {
                float4 a = Xa[u], b = Xb[u];
                s += a.x * b.x + a.y * b.y + a.z * b.z + a.w * b.w;
            }
            float val = s * aiv * g_invnq[bn];
            ull key = ((ull)fmono(val) << 32) | (ull)(0xFFFFFFFFu - (unsigned)j);
            if (key > best) best = key;
        }
    }
    #pragma unroll
    for (int o = 16; o > 0; o >>= 1) {
        ull u = __shfl_xor_sync(0xffffffffu, best, o);
        if (u > best) best = u;
    }
    __shared__ ull sred[4];
    if ((tid & 31) == 0) sred[tid >> 5] = best;
    __syncthreads();
    if (tid == 0) {
        ull b = sred[0];
        for (int i = 1; i < 4; i++) if (sred[i] > b) b = sred[i];
        g_nm_q[row] = b;
    }
}

// ---------------- f32x2 packed GEMM body: C = alpha*A@B^T (+bias) ----------------
#define BM 128
#define BN 128
#define BK 16
#define LDAS 132

__device__ __forceinline__ void
gemm2_body(const float* __restrict__ A, int lda, const float* __restrict__ B, int ldb,
           float* __restrict__ Cm, int ldc, int M, int N, int K,
           const float* __restrict__ bias, float alpha) {
    __shared__ float As[BK][LDAS], Bs[BK][LDAS];
    int m0 = blockIdx.y * BM, n0 = blockIdx.x * BN;
    int tid = threadIdx.x;
    int tx = tid & 15, ty = tid >> 4;
    ull acc[8][4];
    #pragma unroll
    for (int i = 0; i < 8; i++)
        #pragma unroll
        for (int j = 0; j < 4; j++) acc[i][j] = 0ull;

    for (int k0 = 0; k0 < K; k0 += BK) {
        #pragma unroll
        for (int it = 0; it < 2; it++) {
            int c = tid + it * 256;
            int r = c >> 2, kq = (c & 3) << 2;
            int mm = m0 + r;
            float4 va = make_float4(0.f, 0.f, 0.f, 0.f);
            if (mm < M) va = *(const float4*)(A + (size_t)mm * lda + k0 + kq);
            As[kq + 0][r] = va.x; As[kq + 1][r] = va.y; As[kq + 2][r] = va.z; As[kq + 3][r] = va.w;
            int nn = n0 + r;
            float4 vb = make_float4(0.f, 0.f, 0.f, 0.f);
            if (nn < N) vb = *(const float4*)(B + (size_t)nn * ldb + k0 + kq);
            Bs[kq + 0][r] = vb.x; Bs[kq + 1][r] = vb.y; Bs[kq + 2][r] = vb.z; Bs[kq + 3][r] = vb.w;
        }
        __syncthreads();
        #pragma unroll
        for (int kk = 0; kk < BK; kk++) {
            float4 a0 = *(const float4*)&As[kk][ty * 8];
            float4 a1 = *(const float4*)&As[kk][ty * 8 + 4];
            longlong2 b0 = *(const longlong2*)&Bs[kk][tx * 8];
            longlong2 b1 = *(const longlong2*)&Bs[kk][tx * 8 + 4];
            float av[8] = {a0.x, a0.y, a0.z, a0.w, a1.x, a1.y, a1.z, a1.w};
            #pragma unroll
            for (int i = 0; i < 8; i++) {
                ull pa = pack2(av[i]);
                acc[i][0] = fma2(pa, (ull)b0.x, acc[i][0]);
                acc[i][1] = fma2(pa, (ull)b0.y, acc[i][1]);
                acc[i][2] = fma2(pa, (ull)b1.x, acc[i][2]);
                acc[i][3] = fma2(pa, (ull)b1.y, acc[i][3]);
            }
        }
        __syncthreads();
    }
    #pragma unroll
    for (int i = 0; i < 8; i++) {
        int mm = m0 + ty * 8 + i;
        if (mm >= M) continue;
        float v[8];
        #pragma unroll
        for (int j2 = 0; j2 < 4; j2++) { v[2 * j2] = lo32(acc[i][j2]); v[2 * j2 + 1] = hi32(acc[i][j2]); }
        int nb = n0 + tx * 8;
        if (nb + 8 <= N) {
            float4 o0, o1;
            o0.x = v[0] * alpha; o0.y = v[1] * alpha; o0.z = v[2] * alpha; o0.w = v[3] * alpha;
            o1.x = v[4] * alpha; o1.y = v[5] * alpha; o1.z = v[6] * alpha; o1.w = v[7] * alpha;
            if (bias) {
                o0.x += bias[nb + 0]; o0.y += bias[nb + 1]; o0.z += bias[nb + 2]; o0.w += bias[nb + 3];
                o1.x += bias[nb + 4]; o1.y += bias[nb + 5]; o1.z += bias[nb + 6]; o1.w += bias[nb + 7];
            }
            *(float4*)(Cm + (size_t)mm * ldc + nb) = o0;
            *(float4*)(Cm + (size_t)mm * ldc + nb + 4) = o1;
        } else {
            #pragma unroll
            for (int j = 0; j < 8; j++) {
                int nn = nb + j;
                if (nn < N) {
                    float o = v[j] * alpha;
                    if (bias) o += bias[nn];
                    Cm[(size_t)mm * ldc + nn] = o;
                }
            }
        }
    }
}

__global__ void __launch_bounds__(256)
k_gemm2_nt(const float* __restrict__ A, int lda, const float* __restrict__ B, int ldb,
           float* __restrict__ Cm, int ldc, int M, int N, int K,
           const float* __restrict__ bias, float alpha) {
    gemm2_body(A, lda, B, ldb, Cm, ldc, M, N, K, bias, alpha);
}

__global__ void __launch_bounds__(256)
k_attn_qk(float scale) {
    int h = blockIdx.z;
    gemm2_body(g_qb + h * DH, C_, g_kv + h * DH, 2 * C_,
               g_sc + (size_t)h * NQTOK * NKVTOK, NKVTOK,
               NQTOK, NKVTOK, DH, nullptr, scale);
}

__global__ void __launch_bounds__(256)
k_attn_av() {
    int h = blockIdx.z;
    gemm2_body(g_sc + (size_t)h * NQTOK * NKVTOK, NKVTOK,
               g_vt + (size_t)h * DH * NKVTOK, NKVTOK,
               g_ao + h * DH, C_, NQTOK, DH, NKVTOK, nullptr, 1.f);
}

// ---------------- fused similarity GEMM + rowwise packed max/argmax (KV side) ----------------
__global__ void __launch_bounds__(256)
k_scores2(int w, const float* __restrict__ X) {
    BsmP p = getp(w);
    __shared__ float As[BK][LDAS], Bs[BK][LDAS];
    __shared__ int arow[128], brow[128];
    __shared__ float ainv[128], binv[128];
    int m0 = blockIdx.y * BM, n0 = blockIdx.x * BN;
    int tid = threadIdx.x;
    int tx = tid & 15, ty = tid >> 4;
    if (tid < 128) {
        int an = p.atok[m0 + tid];
        arow[tid] = an; ainv[tid] = p.invn[an];
        int bn = p.btok[n0 + tid];
        brow[tid] = bn; binv[tid] = p.invn[bn];
    }
    __syncthreads();
    ull acc[8][4];
    #pragma unroll
    for (int i = 0; i < 8; i++)
        #pragma unroll
        for (int j = 0; j < 4; j++) acc[i][j] = 0ull;

    for (int k0 = 0; k0 < C_; k0 += BK) {
        #pragma unroll
        for (int it = 0; it < 2; it++) {
            int c = tid + it * 256;
            int r = c >> 2, kq = (c & 3) << 2;
            float4 va = *(const float4*)(X + (size_t)arow[r] * C_ + k0 + kq);
            As[kq + 0][r] = va.x; As[kq + 1][r] = va.y; As[kq + 2][r] = va.z; As[kq + 3][r] = va.w;
            float4 vb = *(const float4*)(X + (size_t)brow[r] * C_ + k0 + kq);
            Bs[kq + 0][r] = vb.x; Bs[kq + 1][r] = vb.y; Bs[kq + 2][r] = vb.z; Bs[kq + 3][r] = vb.w;
        }
        __syncthreads();
        #pragma unroll
        for (int kk = 0; kk < BK; kk++) {
            float4 a0 = *(const float4*)&As[kk][ty * 8];
            float4 a1 = *(const float4*)&As[kk][ty * 8 + 4];
            longlong2 b0 = *(const longlong2*)&Bs[kk][tx * 8];
            longlong2 b1 = *(const longlong2*)&Bs[kk][tx * 8 + 4];
            float av[8] = {a0.x, a0.y, a0.z, a0.w, a1.x, a1.y, a1.z, a1.w};
            #pragma unroll
            for (int i = 0; i < 8; i++) {
                ull pa = pack2(av[i]);
                acc[i][0] = fma2(pa, (ull)b0.x, acc[i][0]);
                acc[i][1] = fma2(pa, (ull)b0.y, acc[i][1]);
                acc[i][2] = fma2(pa, (ull)b1.x, acc[i][2]);
                acc[i][3] = fma2(pa, (ull)b1.y, acc[i][3]);
            }
        }
        __syncthreads();
    }
    #pragma unroll
    for (int i = 0; i < 8; i++) {
        int row = ty * 8 + i;
        float aiv = ainv[row];
        ull best = 0ull;
        #pragma unroll
        for (int j2 = 0; j2 < 4; j2++) {
            int c0 = tx * 8 + 2 * j2;
            float lo = lo32(acc[i][j2]) * aiv * binv[c0];
            float hi = hi32(acc[i][j2]) * aiv * binv[c0 + 1];
            int g0 = n0 + c0;
            ull klo = ((ull)fmono(lo) << 32) | (ull)(0xFFFFFFFFu - (unsigned)g0);
            ull khi = ((ull)fmono(hi) << 32) | (ull)(0xFFFFFFFFu - (unsigned)(g0 + 1));
            ull kb = klo > khi ? klo : khi;
            if (kb > best) best = kb;
        }
        {
            ull o;
            o = __shfl_xor_sync(0xffffffffu, best, 8);  if (o > best) best = o;
            o = __shfl_xor_sync(0xffffffffu, best, 4);  if (o > best) best = o;
            o = __shfl_xor_sync(0xffffffffu, best, 2);  if (o > best) best = o;
            o = __shfl_xor_sync(0xffffffffu, best, 1);  if (o > best) best = o;
        }
        if (tx == 0) atomicMax(&p.nm[m0 + row], best);
    }
}

// ---------------- exact top-r radix select ----------------
__global__ void k_select(int w) {
    BsmP p = getp(w);
    __shared__ unsigned int hist[256];
    __shared__ ull s_pref, s_mask;
    __shared__ int s_need;
    if (threadIdx.x == 0) { s_pref = 0ull; s_mask = 0ull; s_need = p.R; }
    __syncthreads();
    for (int shift = 56; shift >= 0; shift -= 8) {
        hist[threadIdx.x] = 0u;
        __syncthreads();
        ull pref = s_pref, mask = s_mask;
        for (int m = threadIdx.x; m < p.NA; m += 256) {
            ull key = (p.nm[m] & 0xFFFFFFFF00000000ull) |
                      (ull)(0xFFFFFFFFu - (unsigned)m);
            if ((key & mask) == pref)
                atomicAdd(&hist[(unsigned)(key >> shift) & 255u], 1u);
        }
        __syncthreads();
        if (threadIdx.x == 0) {
            int need = s_need, cum = 0, d;
            for (d = 255; d >= 0; d--) {
                int h = (int)hist[d];
                if (cum + h >= need) break;
                cum += h;
            }
            s_need = need - cum;
            s_pref = s_pref | (((ull)d) << shift);
            s_mask = s_mask | (255ull << shift);
        }
        __syncthreads();
    }
    if (threadIdx.x == 0) *p.thr = s_pref;
}

__global__ void k_classify(int w) {
    BsmP p = getp(w);
    int m = blockIdx.x * blockDim.x + threadIdx.x;
    if (m >= p.NA) return;
    ull pk = p.nm[m];
    ull key = (pk & 0xFFFFFFFF00000000ull) | (ull)(0xFFFFFFFFu - (unsigned)m);
    if (key >= *p.thr) {
        int s = atomicAdd(p.csrc, 1);
        p.srcn[s] = p.atok[m];
        p.srcd[s] = (int)(0xFFFFFFFFu - (unsigned)(pk & 0xFFFFFFFFull));
    } else {
        int s = atomicAdd(p.cunm, 1);
        p.unm[s] = p.atok[m];
    }
}

// ---------------- merge ----------------
__global__ void k_minit(int w, const float* __restrict__ X) {
    BsmP p = getp(w); int j = blockIdx.x;
    int n = p.btok[j];
    for (int c = threadIdx.x; c < C_; c += blockDim.x)
        p.xm[(size_t)(p.UNM + j) * C_ + c] = X[(size_t)n * C_ + c];
    if (threadIdx.x == 0) p.cnt[j] = 1.f;
}
__global__ void k_maccum(int w, const float* __restrict__ X) {
    BsmP p = getp(w); int s = blockIdx.x;
    int n = p.srcn[s]; int dj = p.srcd[s];
    for (int c = threadIdx.x; c < C_; c += blockDim.x)
        atomicAdd(&p.xm[(size_t)(p.UNM + dj) * C_ + c], X[(size_t)n * C_ + c]);
    if (threadIdx.x == 0) atomicAdd(&p.cnt[dj], 1.f);
}
__global__ void k_mdiv(int w) {
    BsmP p = getp(w); int j = blockIdx.x;
    float inv = 1.f / p.cnt[j];
    for (int c = threadIdx.x; c < C_; c += blockDim.x)
        p.xm[(size_t)(p.UNM + j) * C_ + c] *= inv;
}
__global__ void k_mgather(int w, const float* __restrict__ X) {
    BsmP p = getp(w); int i = blockIdx.x;
    int n = p.unm[i];
    for (int c = threadIdx.x; c < C_; c += blockDim.x)
        p.xm[(size_t)i * C_ + c] = X[(size_t)n * C_ + c];
}

// ---------------- V transpose (per head) ----------------
__global__ void k_vt() {
    int t = blockIdx.x * blockDim.x + threadIdx.x;
    if (t >= NH * DH * NKVTOK) return;
    int h = t / (DH * NKVTOK);
    int d = (t / NKVTOK) % DH;
    int k = t % NKVTOK;
    g_vt[t] = g_kv[(size_t)k * (2 * C_) + C_ + h * DH + d];
}

// ---------------- softmax ----------------
__global__ void k_softmax() {
    size_t row = blockIdx.x;
    float* pp = g_sc + row * NKVTOK;
    float mx = -3.4e38f;
    for (int c = threadIdx.x; c < NKVTOK; c += 256) mx = fmaxf(mx, pp[c]);
    mx = blockReduce(mx, 1);
    float s = 0.f;
    for (int c = threadIdx.x; c < NKVTOK; c += 256) {
        float e = expf(pp[c] - mx); pp[c] = e; s += e;
    }
    s = blockReduce(s, 0);
    float inv = 1.f / s;
    for (int c = threadIdx.x; c < NKVTOK; c += 256) pp[c] *= inv;
}

// ---------------- unmerge ----------------
__global__ void k_unmerge_dst(const float* __restrict__ fp, float* __restrict__ out) {
    int j = blockIdx.x; int n = g_btok_q[j];
    for (int c = threadIdx.x; c < C_; c += blockDim.x)
        out[(size_t)n * C_ + c] = fp[(size_t)(UNMQ + j) * C_ + c];
}
__global__ void k_unmerge_unm(const float* __restrict__ fp, float* __restrict__ out) {
    int i = blockIdx.x; int n = g_unm_q[i];
    for (int c = threadIdx.x; c < C_; c += blockDim.x)
        out[(size_t)n * C_ + c] = fp[(size_t)i * C_ + c];
}
__global__ void k_unmerge_src(const float* __restrict__ fp, float* __restrict__ out) {
    int s = blockIdx.x; int n = g_srcn_q[s]; int dj = g_srcd_q[s];
    for (int c = threadIdx.x; c < C_; c += blockDim.x)
        out[(size_t)n * C_ + c] = fp[(size_t)(UNMQ + dj) * C_ + c];
}

// ---------------- host ----------------
extern "C" void kernel_launch(void* const* d_in, const int* in_sizes, int n_in,
                              void* d_out, int out_size) {
    const float* x   = (const float*)d_in[0];
    const float* srw = (const float*)d_in[1];
    const float* srb = (const float*)d_in[2];
    const float* lng = (const float*)d_in[3];
    const float* lnb = (const float*)d_in[4];
    const float* Wq  = (const float*)d_in[5];
    const float* Wkv = (const float*)d_in[6];
    const float* Wp  = (const float*)d_in[7];
    const float* bpb = (const float*)d_in[8];
    float* out = (float*)d_out;

    void *vp;
    float *p_xi2c, *p_wt, *p_xk, *p_xq, *p_xkm, *p_qb, *p_kv, *p_fp;
    cudaGetSymbolAddress(&vp, g_xi2c); p_xi2c = (float*)vp;
    cudaGetSymbolAddress(&vp, g_wt);   p_wt   = (float*)vp;
    cudaGetSymbolAddress(&vp, g_xk);   p_xk   = (float*)vp;
    cudaGetSymbolAddress(&vp, g_xq);   p_xq   = (float*)vp;
    cudaGetSymbolAddress(&vp, g_xkm);  p_xkm  = (float*)vp;
    cudaGetSymbolAddress(&vp, g_qb);   p_qb   = (float*)vp;
    cudaGetSymbolAddress(&vp, g_kv);   p_kv   = (float*)vp;
    cudaGetSymbolAddress(&vp, g_fp);   p_fp   = (float*)vp;
    float *p_ao; cudaGetSymbolAddress(&vp, g_ao); p_ao = (float*)vp;

    k_reset<<<(NQ_A + 255) / 256, 256>>>();
    k_tokmap<<<(NQ + 255) / 256, 256>>>(0, DQ, HQ, WQ);
    k_tokmap<<<(N2 + 255) / 256, 256>>>(1, D2, H2, W2);
    k_invn_x<<<NQ, 64>>>(x);
    k_wtrans<<<(C_ * KCONV + 255) / 256, 256>>>(srw);
    k_im2col<<<(N2 * KCONV + 255) / 256, 256>>>(x);

    // SR conv as GEMM (+bias), then fused LN + inv-norm
    k_gemm2_nt<<<dim3(C_ / BN, N2 / BM), 256>>>(p_xi2c, KCONV, p_wt, KCONV,
                                                p_xk, C_, N2, C_, KCONV, srb, 1.f);
    k_ln<<<N2, 256>>>(lng, lnb);

    // Q-side BSM: bf16 mma.sync approx scores + exact refinement
    k_tobf_a<<<(NQ_A * (C_ / 4) + 255) / 256, 256>>>(x);
    k_tobf_b<<<(NQ_DST * (C_ / 4) + 255) / 256, 256>>>(x);
    k_scores_mma<<<dim3(NQ_DST / 128, NQ_A / 128), 256>>>();
    k_refine<<<NQ_A, 128>>>(x);
    k_select<<<1, 256>>>(0);
    k_classify<<<(NQ_A + 255) / 256, 256>>>(0);
    k_minit<<<NQ_DST, 256>>>(0, x);
    k_maccum<<<RQ, 256>>>(0, x);
    k_mdiv<<<NQ_DST, 256>>>(0);
    k_mgather<<<UNMQ, 256>>>(0, x);

    // KV-side BSM (small; exact fp32 path)
    k_scores2<<<dim3(NKV_DST / BN, NKV_A / BM), 256>>>(1, p_xk);
    k_select<<<1, 256>>>(1);
    k_classify<<<(NKV_A + 255) / 256, 256>>>(1);
    k_minit<<<NKV_DST, 256>>>(1, p_xk);
    k_maccum<<<RKV, 256>>>(1, p_xk);
    k_mdiv<<<NKV_DST, 256>>>(1);
    k_mgather<<<UNMKV, 256>>>(1, p_xk);

    // projections
    k_gemm2_nt<<<dim3(C_ / BN, NQTOK / BM), 256>>>(p_xq, C_, Wq, C_,
                                                   p_qb, C_, NQTOK, C_, C_, nullptr, 1.f);
    k_gemm2_nt<<<dim3(2 * C_ / BN, NKVTOK / BM), 256>>>(p_xkm, C_, Wkv, C_,
                                                        p_kv, 2 * C_, NKVTOK, 2 * C_, C_, nullptr, 1.f);
    k_vt<<<(NH * DH * NKVTOK + 255) / 256, 256>>>();

    // attention (two-pass, batched over heads)
    float scale = 1.0f / sqrtf((float)DH);
    k_attn_qk<<<dim3(NKVTOK / BN, NQTOK / BM, NH), 256>>>(scale);
    k_softmax<<<NH * NQTOK, 256>>>();
    k_attn_av<<<dim3(1, NQTOK / BM, NH), 256>>>();

    // output projection + bias, then unmerge scatter
    k_gemm2_nt<<<dim3(C_ / BN, NQTOK / BM), 256>>>(p_ao, C_, Wp, C_,
                                                   p_fp, C_, NQTOK, C_, C_, bpb, 1.f);
    k_unmerge_dst<<<NQ_DST, 256>>>(p_fp, out);
    k_unmerge_unm<<<UNMQ, 256>>>(p_fp, out);
    k_unmerge_src<<<RQ, 256>>>(p_fp, out);
}

// round 12
// speedup vs baseline: 1.6258x; 1.1601x over previous
#include <cuda_runtime.h>
#include <cuda_bf16.h>
#include <math.h>

#define C_ 768
#define DQ 16
#define HQ 32
#define WQ 32
#define NQ 16384
#define D2 8
#define H2 16
#define W2 16
#define N2 2048
#define KCONV 6144

#define NQ_DST 2048
#define NQ_A 14336
#define RQ 8192
#define UNMQ 6144
#define NQTOK 8192

#define NKV_DST 256
#define NKV_A 1792
#define RKV 1024
#define UNMKV 768
#define NKVTOK 1024

#define NH 8
#define DH 96

typedef unsigned long long ull;

// ---------------- scratch (static device memory; no allocations) ----------------
__device__ float g_xi2c[(size_t)N2 * KCONV];
__device__ float g_wt[(size_t)C_ * KCONV];
__device__ float g_xk[N2 * C_];
__device__ float g_invnq[NQ];
__device__ float g_invnk[N2];
__device__ int g_atok_q[NQ_A];
__device__ int g_btok_q[NQ_DST];
__device__ int g_atok_k[NKV_A];
__device__ int g_btok_k[NKV_DST];
__device__ ull g_nm_q[NQ_A];
__device__ ull g_nm_k[NKV_A];
__device__ unsigned g_apxmax[NQ_A];
__device__ ull g_thr[2];
__device__ int g_srcn_q[RQ], g_srcd_q[RQ], g_unm_q[UNMQ];
__device__ int g_srcn_k[RKV], g_srcd_k[RKV], g_unm_k[UNMKV];
__device__ int g_ctr[4];
__device__ float g_cnt_q[NQ_DST], g_cnt_k[NKV_DST];
__device__ float g_xq[NQTOK * C_];
__device__ float g_xkm[NKVTOK * C_];
__device__ float g_qb[NQTOK * C_];
__device__ float g_kv[NKVTOK * 2 * C_];
__device__ float g_vt[NH * DH * NKVTOK];
__device__ float g_sc[(size_t)NH * NQTOK * NKVTOK];   // reused: scores-Q matrix, then attention
__device__ float g_ao[NQTOK * C_];
__device__ float g_fp[NQTOK * C_];
__device__ __nv_bfloat16 g_abf[(size_t)NQ_A * C_];
__device__ __nv_bfloat16 g_bbf[(size_t)NQ_DST * C_];

// ---------------- f32x2 helpers ----------------
__device__ __forceinline__ ull fma2(ull a, ull b, ull c) {
    ull d;
    asm("fma.rn.f32x2 %0, %1, %2, %3;" : "=l"(d) : "l"(a), "l"(b), "l"(c));
    return d;
}
__device__ __forceinline__ ull pack2(float x) {
    ull d;
    asm("mov.b64 %0, {%1, %1};" : "=l"(d) : "r"(__float_as_uint(x)));
    return d;
}
__device__ __forceinline__ float lo32(ull v) { return __uint_as_float((unsigned)v); }
__device__ __forceinline__ float hi32(ull v) { return __uint_as_float((unsigned)(v >> 32)); }

__device__ __forceinline__ unsigned f2tf(float f) {
    unsigned r;
    asm("cvt.rna.tf32.f32 %0, %1;" : "=r"(r) : "f"(f));
    return r;
}

// ---------------- misc helpers ----------------
struct BsmP {
    int* atok; int* btok;
    ull* nm; ull* thr;
    int* srcn; int* srcd; int* unm;
    int* csrc; int* cunm;
    float* cnt; float* xm;
    const float* invn;
    int NA, NB, R, UNM;
};

__device__ __forceinline__ BsmP getp(int w) {
    BsmP p;
    if (w == 0) {
        p.atok = g_atok_q; p.btok = g_btok_q; p.nm = g_nm_q; p.thr = &g_thr[0];
        p.srcn = g_srcn_q; p.srcd = g_srcd_q; p.unm = g_unm_q;
        p.csrc = &g_ctr[0]; p.cunm = &g_ctr[1];
        p.cnt = g_cnt_q; p.xm = g_xq; p.invn = g_invnq;
        p.NA = NQ_A; p.NB = NQ_DST; p.R = RQ; p.UNM = UNMQ;
    } else {
        p.atok = g_atok_k; p.btok = g_btok_k; p.nm = g_nm_k; p.thr = &g_thr[1];
        p.srcn = g_srcn_k; p.srcd = g_srcd_k; p.unm = g_unm_k;
        p.csrc = &g_ctr[2]; p.cunm = &g_ctr[3];
        p.cnt = g_cnt_k; p.xm = g_xkm; p.invn = g_invnk;
        p.NA = NKV_A; p.NB = NKV_DST; p.R = RKV; p.UNM = UNMKV;
    }
    return p;
}

__device__ __forceinline__ unsigned int fmono(float f) {
    unsigned int b = __float_as_uint(f);
    return b ^ ((b & 0x80000000u) ? 0xFFFFFFFFu : 0x80000000u);
}
__device__ __forceinline__ float unmono(unsigned u) {
    unsigned b = (u & 0x80000000u) ? (u ^ 0x80000000u) : ~u;
    return __uint_as_float(b);
}

__device__ __forceinline__ float blockReduce(float v, int ismax) {
    __shared__ float sh[40];
    __syncthreads();
    #pragma unroll
    for (int o = 16; o > 0; o >>= 1) {
        float u = __shfl_down_sync(0xffffffffu, v, o);
        v = ismax ? fmaxf(v, u) : (v + u);
    }
    if ((threadIdx.x & 31) == 0) sh[threadIdx.x >> 5] = v;
    __syncthreads();
    if (threadIdx.x == 0) {
        int nw = (blockDim.x + 31) >> 5;
        float r = sh[0];
        for (int i = 1; i < nw; i++) r = ismax ? fmaxf(r, sh[i]) : (r + sh[i]);
        sh[39] = r;
    }
    __syncthreads();
    return sh[39];
}

__device__ __forceinline__ int dst_before(int z, int y, int x, int HH, int WW) {
    int planes = ((z + 1) >> 1) * ((HH >> 1) * (WW >> 1));
    int extra = 0;
    if ((z & 1) == 0) {
        extra = ((y + 1) >> 1) * (WW >> 1);
        if ((y & 1) == 0) extra += ((x + 1) >> 1);
    }
    return planes + extra;
}

// ---------------- setup kernels ----------------
__global__ void k_reset() {
    int t = blockIdx.x * blockDim.x + threadIdx.x;
    if (t < NQ_A) { g_nm_q[t] = 0ull; g_apxmax[t] = 0u; }
    if (t < NKV_A) g_nm_k[t] = 0ull;
    if (t < 4) g_ctr[t] = 0;
}

__global__ void k_tokmap(int w, int DD, int HH, int WW) {
    BsmP p = getp(w);
    int n = blockIdx.x * blockDim.x + threadIdx.x;
    int NN = DD * HH * WW;
    if (n >= NN) return;
    int z = n / (HH * WW); int rem = n % (HH * WW); int y = rem / WW; int x = rem % WW;
    int db = dst_before(z, y, x, HH, WW);
    bool isdst = (((z | y | x) & 1) == 0);
    if (isdst) p.btok[db] = n; else p.atok[n - db] = n;
}

__global__ void k_invn_x(const float* __restrict__ X) {
    int m = blockIdx.x;
    float ss = 0.f;
    const float4* row = (const float4*)(X + (size_t)m * C_);
    for (int c = threadIdx.x; c < C_ / 4; c += 64) {
        float4 v = row[c];
        ss += v.x * v.x + v.y * v.y + v.z * v.z + v.w * v.w;
    }
    ss = blockReduce(ss, 0);
    if (threadIdx.x == 0) g_invnq[m] = rsqrtf(ss);
}

__global__ void k_wtrans(const float* __restrict__ srw) {
    int t = blockIdx.x * blockDim.x + threadIdx.x;
    if (t >= C_ * KCONV) return;
    int o = t / KCONV, k = t % KCONV;
    int dzyx = k / C_, i = k % C_;
    g_wt[t] = srw[o * KCONV + i * 8 + dzyx];
}

__global__ void k_im2col(const float* __restrict__ x) {
    int t = blockIdx.x * blockDim.x + threadIdx.x;
    if (t >= N2 * KCONV) return;
    int m = t / KCONV, k = t % KCONV;
    int dzyx = k / C_, i = k % C_;
    int z2 = m / (H2 * W2), y2 = (m / W2) % H2, x2 = m % W2;
    int z = 2 * z2 + (dzyx >> 2), y = 2 * y2 + ((dzyx >> 1) & 1), xx = 2 * x2 + (dzyx & 1);
    g_xi2c[t] = x[(size_t)(z * (HQ * WQ) + y * WQ + xx) * C_ + i];
}

__global__ void k_ln(const float* __restrict__ g, const float* __restrict__ b) {
    int m = blockIdx.x;
    float s = 0.f, ss = 0.f;
    for (int c = threadIdx.x; c < C_; c += 256) { float v = g_xk[m * C_ + c]; s += v; ss += v * v; }
    s = blockReduce(s, 0);
    ss = blockReduce(ss, 0);
    float mean = s * (1.0f / C_);
    float var = ss * (1.0f / C_) - mean * mean;
    float rstd = rsqrtf(var + 1e-5f);
    float s2 = 0.f;
    for (int c = threadIdx.x; c < C_; c += 256) {
        float v = (g_xk[m * C_ + c] - mean) * rstd * g[c] + b[c];
        g_xk[m * C_ + c] = v;
        s2 += v * v;
    }
    s2 = blockReduce(s2, 0);
    if (threadIdx.x == 0) g_invnk[m] = rsqrtf(s2);
}

// bf16 copies of gathered a/b rows for the MMA scores GEMM
__global__ void k_tobf_a(const float* __restrict__ X) {
    int t = blockIdx.x * blockDim.x + threadIdx.x;
    if (t >= NQ_A * (C_ / 4)) return;
    int row = t / (C_ / 4), u = t % (C_ / 4);
    int an = g_atok_q[row];
    float4 v = ((const float4*)(X + (size_t)an * C_))[u];
    unsigned short s0 = __bfloat16_as_ushort(__float2bfloat16(v.x));
    unsigned short s1 = __bfloat16_as_ushort(__float2bfloat16(v.y));
    unsigned short s2 = __bfloat16_as_ushort(__float2bfloat16(v.z));
    unsigned short s3 = __bfloat16_as_ushort(__float2bfloat16(v.w));
    uint2 w;
    w.x = (unsigned)s0 | ((unsigned)s1 << 16);
    w.y = (unsigned)s2 | ((unsigned)s3 << 16);
    *(uint2*)(&g_abf[(size_t)row * C_ + u * 4]) = w;
}
__global__ void k_tobf_b(const float* __restrict__ X) {
    int t = blockIdx.x * blockDim.x + threadIdx.x;
    if (t >= NQ_DST * (C_ / 4)) return;
    int row = t / (C_ / 4), u = t % (C_ / 4);
    int bn = g_btok_q[row];
    float4 v = ((const float4*)(X + (size_t)bn * C_))[u];
    unsigned short s0 = __bfloat16_as_ushort(__float2bfloat16(v.x));
    unsigned short s1 = __bfloat16_as_ushort(__float2bfloat16(v.y));
    unsigned short s2 = __bfloat16_as_ushort(__float2bfloat16(v.z));
    unsigned short s3 = __bfloat16_as_ushort(__float2bfloat16(v.w));
    uint2 w;
    w.x = (unsigned)s0 | ((unsigned)s1 << 16);
    w.y = (unsigned)s2 | ((unsigned)s3 << 16);
    *(uint2*)(&g_bbf[(size_t)row * C_ + u * 4]) = w;
}

// ---------------- bf16 mma.sync scores GEMM (approx pass) ----------------
// 128x128 block tile, 8 warps (4x2), warp = 32x64 via 2x8 m16n8k16 tiles.
#define LDK 40

__global__ void __launch_bounds__(256)
k_scores_mma() {
    __shared__ __nv_bfloat16 As[128 * LDK], Bs[128 * LDK];
    __shared__ float s_ainv[128], s_binv[128];
    int tid = threadIdx.x;
    int wid = tid >> 5, lane = tid & 31;
    int g = lane >> 2, t = lane & 3;
    int warp_m = wid >> 1, warp_n = wid & 1;
    int m0 = blockIdx.y * 128, n0 = blockIdx.x * 128;

    if (tid < 128) {
        s_ainv[tid] = g_invnq[g_atok_q[m0 + tid]];
        s_binv[tid] = g_invnq[g_btok_q[n0 + tid]];
    }

    float acc[2][8][4];
    #pragma unroll
    for (int mt = 0; mt < 2; mt++)
        #pragma unroll
        for (int nt = 0; nt < 8; nt++)
            #pragma unroll
            for (int j = 0; j < 4; j++) acc[mt][nt][j] = 0.f;

    for (int k0 = 0; k0 < C_; k0 += 32) {
        __syncthreads();
        #pragma unroll
        for (int i = 0; i < 4; i++) {
            int q = tid + i * 256;
            int r = q >> 3, u = q & 7;
            *(ull*)&As[r * LDK + u * 4] = *(const ull*)&g_abf[(size_t)(m0 + r) * C_ + k0 + u * 4];
            *(ull*)&Bs[r * LDK + u * 4] = *(const ull*)&g_bbf[(size_t)(n0 + r) * C_ + k0 + u * 4];
        }
        __syncthreads();
        #pragma unroll
        for (int ks = 0; ks < 2; ks++) {
            int koff = ks * 16;
            unsigned afr[2][4];
            #pragma unroll
            for (int mt = 0; mt < 2; mt++) {
                int r = warp_m * 32 + mt * 16 + g;
                afr[mt][0] = *(const unsigned*)&As[r * LDK + koff + t * 2];
                afr[mt][1] = *(const unsigned*)&As[(r + 8) * LDK + koff + t * 2];
                afr[mt][2] = *(const unsigned*)&As[r * LDK + koff + t * 2 + 8];
                afr[mt][3] = *(const unsigned*)&As[(r + 8) * LDK + koff + t * 2 + 8];
            }
            #pragma unroll
            for (int nt = 0; nt < 8; nt++) {
                int c = warp_n * 64 + nt * 8 + g;
                unsigned b0 = *(const unsigned*)&Bs[c * LDK + koff + t * 2];
                unsigned b1 = *(const unsigned*)&Bs[c * LDK + koff + t * 2 + 8];
                #pragma unroll
                for (int mt = 0; mt < 2; mt++) {
                    asm volatile(
                        "mma.sync.aligned.m16n8k16.row.col.f32.bf16.bf16.f32 "
                        "{%0,%1,%2,%3}, {%4,%5,%6,%7}, {%8,%9}, {%0,%1,%2,%3};"
                        : "+f"(acc[mt][nt][0]), "+f"(acc[mt][nt][1]),
                          "+f"(acc[mt][nt][2]), "+f"(acc[mt][nt][3])
                        : "r"(afr[mt][0]), "r"(afr[mt][1]),
                          "r"(afr[mt][2]), "r"(afr[mt][3]),
                          "r"(b0), "r"(b1));
                }
            }
        }
    }

    #pragma unroll
    for (int mt = 0; mt < 2; mt++) {
        int rloc0 = warp_m * 32 + mt * 16 + g;
        int rloc1 = rloc0 + 8;
        float aiv0 = s_ainv[rloc0], aiv1 = s_ainv[rloc1];
        float mx0 = -3.4e38f, mx1 = -3.4e38f;
        float* d0 = g_sc + (size_t)(m0 + rloc0) * NQ_DST + n0;
        float* d1 = g_sc + (size_t)(m0 + rloc1) * NQ_DST + n0;
        #pragma unroll
        for (int nt = 0; nt < 8; nt++) {
            int cloc = warp_n * 64 + nt * 8 + t * 2;
            float bi0 = s_binv[cloc], bi1 = s_binv[cloc + 1];
            float v00 = acc[mt][nt][0] * aiv0 * bi0;
            float v01 = acc[mt][nt][1] * aiv0 * bi1;
            float v10 = acc[mt][nt][2] * aiv1 * bi0;
            float v11 = acc[mt][nt][3] * aiv1 * bi1;
            *(float2*)(d0 + cloc) = make_float2(v00, v01);
            *(float2*)(d1 + cloc) = make_float2(v10, v11);
            mx0 = fmaxf(mx0, fmaxf(v00, v01));
            mx1 = fmaxf(mx1, fmaxf(v10, v11));
        }
        mx0 = fmaxf(mx0, __shfl_xor_sync(0xffffffffu, mx0, 1));
        mx0 = fmaxf(mx0, __shfl_xor_sync(0xffffffffu, mx0, 2));
        mx1 = fmaxf(mx1, __shfl_xor_sync(0xffffffffu, mx1, 1));
        mx1 = fmaxf(mx1, __shfl_xor_sync(0xffffffffu, mx1, 2));
        if (t == 0) {
            atomicMax(&g_apxmax[m0 + rloc0], fmono(mx0));
            atomicMax(&g_apxmax[m0 + rloc1], fmono(mx1));
        }
    }
}

// ---------------- exact refinement of rowmax/argmax ----------------
#define RMARGIN 0.01f
__global__ void __launch_bounds__(128)
k_refine(const float* __restrict__ X) {
    int row = blockIdx.x;
    int tid = threadIdx.x;
    float amax = unmono(g_apxmax[row]);
    float thr = amax - RMARGIN;
    int an = g_atok_q[row];
    float aiv = g_invnq[an];
    const float4* Xa = (const float4*)(X + (size_t)an * C_);
    const float* srow = g_sc + (size_t)row * NQ_DST;
    ull best = 0ull;
    for (int j = tid; j < NQ_DST; j += 128) {
        if (srow[j] >= thr) {
            int bn = g_btok_q[j];
            const float4* Xb = (const float4*)(X + (size_t)bn * C_);
            float s = 0.f;
            #pragma unroll 4
            for (int u = 0; u < C_ / 4; u++) {
                float4 a = Xa[u], b = Xb[u];
                s += a.x * b.x + a.y * b.y + a.z * b.z + a.w * b.w;
            }
            float val = s * aiv * g_invnq[bn];
            ull key = ((ull)fmono(val) << 32) | (ull)(0xFFFFFFFFu - (unsigned)j);
            if (key > best) best = key;
        }
    }
    #pragma unroll
    for (int o = 16; o > 0; o >>= 1) {
        ull u = __shfl_xor_sync(0xffffffffu, best, o);
        if (u > best) best = u;
    }
    __shared__ ull sred[4];
    if ((tid & 31) == 0) sred[tid >> 5] = best;
    __syncthreads();
    if (tid == 0) {
        ull b = sred[0];
        for (int i = 1; i < 4; i++) if (sred[i] > b) b = sred[i];
        g_nm_q[row] = b;
    }
}

// ---------------- tf32 mma GEMM: C[M,N] = alpha*A[M,K]@B[N,K]^T (+bias) ----------------
// 128x128 block tile, 8 warps (4x2), warp = 32x64 via 2x8 m16n8k8 tf32 tiles.
#define TLDK 20

__device__ __forceinline__ void
gemm_tf32_body(const float* __restrict__ A, int lda, const float* __restrict__ B, int ldb,
               float* __restrict__ Cm, int ldc, int M, int N, int K,
               const float* __restrict__ bias, float alpha) {
    __shared__ unsigned As[128 * TLDK], Bs[128 * TLDK];
    int tid = threadIdx.x;
    int wid = tid >> 5, lane = tid & 31;
    int g = lane >> 2, t = lane & 3;
    int warp_m = wid >> 1, warp_n = wid & 1;
    int m0 = blockIdx.y * 128, n0 = blockIdx.x * 128;

    float acc[2][8][4];
    #pragma unroll
    for (int mt = 0; mt < 2; mt++)
        #pragma unroll
        for (int nt = 0; nt < 8; nt++)
            #pragma unroll
            for (int j = 0; j < 4; j++) acc[mt][nt][j] = 0.f;

    for (int k0 = 0; k0 < K; k0 += 16) {
        __syncthreads();
        #pragma unroll
        for (int i = 0; i < 2; i++) {
            int c = tid + i * 256;
            int r = c >> 2, u = (c & 3) << 2;
            int mm = m0 + r;
            float4 va = make_float4(0.f, 0.f, 0.f, 0.f);
            if (mm < M) va = *(const float4*)(A + (size_t)mm * lda + k0 + u);
            As[r * TLDK + u + 0] = f2tf(va.x);
            As[r * TLDK + u + 1] = f2tf(va.y);
            As[r * TLDK + u + 2] = f2tf(va.z);
            As[r * TLDK + u + 3] = f2tf(va.w);
            int nn = n0 + r;
            float4 vb = make_float4(0.f, 0.f, 0.f, 0.f);
            if (nn < N) vb = *(const float4*)(B + (size_t)nn * ldb + k0 + u);
            Bs[r * TLDK + u + 0] = f2tf(vb.x);
            Bs[r * TLDK + u + 1] = f2tf(vb.y);
            Bs[r * TLDK + u + 2] = f2tf(vb.z);
            Bs[r * TLDK + u + 3] = f2tf(vb.w);
        }
        __syncthreads();
        #pragma unroll
        for (int ks = 0; ks < 2; ks++) {
            int koff = ks * 8;
            unsigned afr[2][4];
            #pragma unroll
            for (int mt = 0; mt < 2; mt++) {
                int r = warp_m * 32 + mt * 16 + g;
                afr[mt][0] = As[r * TLDK + koff + t];
                afr[mt][1] = As[(r + 8) * TLDK + koff + t];
                afr[mt][2] = As[r * TLDK + koff + t + 4];
                afr[mt][3] = As[(r + 8) * TLDK + koff + t + 4];
            }
            #pragma unroll
            for (int nt = 0; nt < 8; nt++) {
                int c = warp_n * 64 + nt * 8 + g;
                unsigned b0 = Bs[c * TLDK + koff + t];
                unsigned b1 = Bs[c * TLDK + koff + t + 4];
                #pragma unroll
                for (int mt = 0; mt < 2; mt++) {
                    asm volatile(
                        "mma.sync.aligned.m16n8k8.row.col.f32.tf32.tf32.f32 "
                        "{%0,%1,%2,%3}, {%4,%5,%6,%7}, {%8,%9}, {%0,%1,%2,%3};"
                        : "+f"(acc[mt][nt][0]), "+f"(acc[mt][nt][1]),
                          "+f"(acc[mt][nt][2]), "+f"(acc[mt][nt][3])
                        : "r"(afr[mt][0]), "r"(afr[mt][1]),
                          "r"(afr[mt][2]), "r"(afr[mt][3]),
                          "r"(b0), "r"(b1));
                }
            }
        }
    }

    #pragma unroll
    for (int mt = 0; mt < 2; mt++) {
        int r0 = m0 + warp_m * 32 + mt * 16 + g;
        int r1 = r0 + 8;
        #pragma unroll
        for (int nt = 0; nt < 8; nt++) {
            int nn = n0 + warp_n * 64 + nt * 8 + t * 2;
            if (nn >= N) continue;
            float b0v = bias ? bias[nn] : 0.f;
            float b1v = bias ? bias[nn + 1] : 0.f;
            if (r0 < M)
                *(float2*)(Cm + (size_t)r0 * ldc + nn) =
                    make_float2(acc[mt][nt][0] * alpha + b0v, acc[mt][nt][1] * alpha + b1v);
            if (r1 < M)
                *(float2*)(Cm + (size_t)r1 * ldc + nn) =
                    make_float2(acc[mt][nt][2] * alpha + b0v, acc[mt][nt][3] * alpha + b1v);
        }
    }
}

__global__ void __launch_bounds__(256)
k_gemm_tf32(const float* __restrict__ A, int lda, const float* __restrict__ B, int ldb,
            float* __restrict__ Cm, int ldc, int M, int N, int K,
            const float* __restrict__ bias, float alpha) {
    gemm_tf32_body(A, lda, B, ldb, Cm, ldc, M, N, K, bias, alpha);
}

__global__ void __launch_bounds__(256)
k_qk_tf32(float scale) {
    int h = blockIdx.z;
    gemm_tf32_body(g_qb + h * DH, C_, g_kv + h * DH, 2 * C_,
                   g_sc + (size_t)h * NQTOK * NKVTOK, NKVTOK,
                   NQTOK, NKVTOK, DH, nullptr, scale);
}

__global__ void __launch_bounds__(256)
k_av_tf32() {
    int h = blockIdx.z;
    gemm_tf32_body(g_sc + (size_t)h * NQTOK * NKVTOK, NKVTOK,
                   g_vt + (size_t)h * DH * NKVTOK, NKVTOK,
                   g_ao + h * DH, C_, NQTOK, DH, NKVTOK, nullptr, 1.f);
}

// ---------------- f32x2 packed GEMM (conv only): C = alpha*A@B^T (+bias) ----------------
#define BM 128
#define BN 128
#define BK 16
#define LDAS 132

__global__ void __launch_bounds__(256)
k_gemm2_nt(const float* __restrict__ A, int lda, const float* __restrict__ B, int ldb,
           float* __restrict__ Cm, int ldc, int M, int N, int K,
           const float* __restrict__ bias, float alpha) {
    __shared__ float As[BK][LDAS], Bs[BK][LDAS];
    int m0 = blockIdx.y * BM, n0 = blockIdx.x * BN;
    int tid = threadIdx.x;
    int tx = tid & 15, ty = tid >> 4;
    ull acc[8][4];
    #pragma unroll
    for (int i = 0; i < 8; i++)
        #pragma unroll
        for (int j = 0; j < 4; j++) acc[i][j] = 0ull;

    for (int k0 = 0; k0 < K; k0 += BK) {
        #pragma unroll
        for (int it = 0; it < 2; it++) {
            int c = tid + it * 256;
            int r = c >> 2, kq = (c & 3) << 2;
            int mm = m0 + r;
            float4 va = make_float4(0.f, 0.f, 0.f, 0.f);
            if (mm < M) va = *(const float4*)(A + (size_t)mm * lda + k0 + kq);
            As[kq + 0][r] = va.x; As[kq + 1][r] = va.y; As[kq + 2][r] = va.z; As[kq + 3][r] = va.w;
            int nn = n0 + r;
            float4 vb = make_float4(0.f, 0.f, 0.f, 0.f);
            if (nn < N) vb = *(const float4*)(B + (size_t)nn * ldb + k0 + kq);
            Bs[kq + 0][r] = vb.x; Bs[kq + 1][r] = vb.y; Bs[kq + 2][r] = vb.z; Bs[kq + 3][r] = vb.w;
        }
        __syncthreads();
        #pragma unroll
        for (int kk = 0; kk < BK; kk++) {
            float4 a0 = *(const float4*)&As[kk][ty * 8];
            float4 a1 = *(const float4*)&As[kk][ty * 8 + 4];
            longlong2 b0 = *(const longlong2*)&Bs[kk][tx * 8];
            longlong2 b1 = *(const longlong2*)&Bs[kk][tx * 8 + 4];
            float av[8] = {a0.x, a0.y, a0.z, a0.w, a1.x, a1.y, a1.z, a1.w};
            #pragma unroll
            for (int i = 0; i < 8; i++) {
                ull pa = pack2(av[i]);
                acc[i][0] = fma2(pa, (ull)b0.x, acc[i][0]);
                acc[i][1] = fma2(pa, (ull)b0.y, acc[i][1]);
                acc[i][2] = fma2(pa, (ull)b1.x, acc[i][2]);
                acc[i][3] = fma2(pa, (ull)b1.y, acc[i][3]);
            }
        }
        __syncthreads();
    }
    #pragma unroll
    for (int i = 0; i < 8; i++) {
        int mm = m0 + ty * 8 + i;
        if (mm >= M) continue;
        float v[8];
        #pragma unroll
        for (int j2 = 0; j2 < 4; j2++) { v[2 * j2] = lo32(acc[i][j2]); v[2 * j2 + 1] = hi32(acc[i][j2]); }
        int nb = n0 + tx * 8;
        if (nb + 8 <= N) {
            float4 o0, o1;
            o0.x = v[0] * alpha; o0.y = v[1] * alpha; o0.z = v[2] * alpha; o0.w = v[3] * alpha;
            o1.x = v[4] * alpha; o1.y = v[5] * alpha; o1.z = v[6] * alpha; o1.w = v[7] * alpha;
            if (bias) {
                o0.x += bias[nb + 0]; o0.y += bias[nb + 1]; o0.z += bias[nb + 2]; o0.w += bias[nb + 3];
                o1.x += bias[nb + 4]; o1.y += bias[nb + 5]; o1.z += bias[nb + 6]; o1.w += bias[nb + 7];
            }
            *(float4*)(Cm + (size_t)mm * ldc + nb) = o0;
            *(float4*)(Cm + (size_t)mm * ldc + nb + 4) = o1;
        } else {
            #pragma unroll
            for (int j = 0; j < 8; j++) {
                int nn = nb + j;
                if (nn < N) {
                    float o = v[j] * alpha;
                    if (bias) o += bias[nn];
                    Cm[(size_t)mm * ldc + nn] = o;
                }
            }
        }
    }
}

// ---------------- fused similarity GEMM + rowwise packed max/argmax (KV side) ----------------
__global__ void __launch_bounds__(256)
k_scores2(int w, const float* __restrict__ X) {
    BsmP p = getp(w);
    __shared__ float As[BK][LDAS], Bs[BK][LDAS];
    __shared__ int arow[128], brow[128];
    __shared__ float ainv[128], binv[128];
    int m0 = blockIdx.y * BM, n0 = blockIdx.x * BN;
    int tid = threadIdx.x;
    int tx = tid & 15, ty = tid >> 4;
    if (tid < 128) {
        int an = p.atok[m0 + tid];
        arow[tid] = an; ainv[tid] = p.invn[an];
        int bn = p.btok[n0 + tid];
        brow[tid] = bn; binv[tid] = p.invn[bn];
    }
    __syncthreads();
    ull acc[8][4];
    #pragma unroll
    for (int i = 0; i < 8; i++)
        #pragma unroll
        for (int j = 0; j < 4; j++) acc[i][j] = 0ull;

    for (int k0 = 0; k0 < C_; k0 += BK) {
        #pragma unroll
        for (int it = 0; it < 2; it++) {
            int c = tid + it * 256;
            int r = c >> 2, kq = (c & 3) << 2;
            float4 va = *(const float4*)(X + (size_t)arow[r] * C_ + k0 + kq);
            As[kq + 0][r] = va.x; As[kq + 1][r] = va.y; As[kq + 2][r] = va.z; As[kq + 3][r] = va.w;
            float4 vb = *(const float4*)(X + (size_t)brow[r] * C_ + k0 + kq);
            Bs[kq + 0][r] = vb.x; Bs[kq + 1][r] = vb.y; Bs[kq + 2][r] = vb.z; Bs[kq + 3][r] = vb.w;
        }
        __syncthreads();
        #pragma unroll
        for (int kk = 0; kk < BK; kk++) {
            float4 a0 = *(const float4*)&As[kk][ty * 8];
            float4 a1 = *(const float4*)&As[kk][ty * 8 + 4];
            longlong2 b0 = *(const longlong2*)&Bs[kk][tx * 8];
            longlong2 b1 = *(const longlong2*)&Bs[kk][tx * 8 + 4];
            float av[8] = {a0.x, a0.y, a0.z, a0.w, a1.x, a1.y, a1.z, a1.w};
            #pragma unroll
            for (int i = 0; i < 8; i++) {
                ull pa = pack2(av[i]);
                acc[i][0] = fma2(pa, (ull)b0.x, acc[i][0]);
                acc[i][1] = fma2(pa, (ull)b0.y, acc[i][1]);
                acc[i][2] = fma2(pa, (ull)b1.x, acc[i][2]);
                acc[i][3] = fma2(pa, (ull)b1.y, acc[i][3]);
            }
        }
        __syncthreads();
    }
    #pragma unroll
    for (int i = 0; i < 8; i++) {
        int row = ty * 8 + i;
        float aiv = ainv[row];
        ull best = 0ull;
        #pragma unroll
        for (int j2 = 0; j2 < 4; j2++) {
            int c0 = tx * 8 + 2 * j2;
            float lo = lo32(acc[i][j2]) * aiv * binv[c0];
            float hi = hi32(acc[i][j2]) * aiv * binv[c0 + 1];
            int g0 = n0 + c0;
            ull klo = ((ull)fmono(lo) << 32) | (ull)(0xFFFFFFFFu - (unsigned)g0);
            ull khi = ((ull)fmono(hi) << 32) | (ull)(0xFFFFFFFFu - (unsigned)(g0 + 1));
            ull kb = klo > khi ? klo : khi;
            if (kb > best) best = kb;
        }
        {
            ull o;
            o = __shfl_xor_sync(0xffffffffu, best, 8);  if (o > best) best = o;
            o = __shfl_xor_sync(0xffffffffu, best, 4);  if (o > best) best = o;
            o = __shfl_xor_sync(0xffffffffu, best, 2);  if (o > best) best = o;
            o = __shfl_xor_sync(0xffffffffu, best, 1);  if (o > best) best = o;
        }
        if (tx == 0) atomicMax(&p.nm[m0 + row], best);
    }
}

// ---------------- exact top-r radix select ----------------
__global__ void k_select(int w) {
    BsmP p = getp(w);
    __shared__ unsigned int hist[256];
    __shared__ ull s_pref, s_mask;
    __shared__ int s_need;
    if (threadIdx.x == 0) { s_pref = 0ull; s_mask = 0ull; s_need = p.R; }
    __syncthreads();
    for (int shift = 56; shift >= 0; shift -= 8) {
        hist[threadIdx.x] = 0u;
        __syncthreads();
        ull pref = s_pref, mask = s_mask;
        for (int m = threadIdx.x; m < p.NA; m += 256) {
            ull key = (p.nm[m] & 0xFFFFFFFF00000000ull) |
                      (ull)(0xFFFFFFFFu - (unsigned)m);
            if ((key & mask) == pref)
                atomicAdd(&hist[(unsigned)(key >> shift) & 255u], 1u);
        }
        __syncthreads();
        if (threadIdx.x == 0) {
            int need = s_need, cum = 0, d;
            for (d = 255; d >= 0; d--) {
                int h = (int)hist[d];
                if (cum + h >= need) break;
                cum += h;
            }
            s_need = need - cum;
            s_pref = s_pref | (((ull)d) << shift);
            s_mask = s_mask | (255ull << shift);
        }
        __syncthreads();
    }
    if (threadIdx.x == 0) *p.thr = s_pref;
}

__global__ void k_classify(int w) {
    BsmP p = getp(w);
    int m = blockIdx.x * blockDim.x + threadIdx.x;
    if (m >= p.NA) return;
    ull pk = p.nm[m];
    ull key = (pk & 0xFFFFFFFF00000000ull) | (ull)(0xFFFFFFFFu - (unsigned)m);
    if (key >= *p.thr) {
        int s = atomicAdd(p.csrc, 1);
        p.srcn[s] = p.atok[m];
        p.srcd[s] = (int)(0xFFFFFFFFu - (unsigned)(pk & 0xFFFFFFFFull));
    } else {
        int s = atomicAdd(p.cunm, 1);
        p.unm[s] = p.atok[m];
    }
}

// ---------------- merge ----------------
__global__ void k_minit(int w, const float* __restrict__ X) {
    BsmP p = getp(w); int j = blockIdx.x;
    int n = p.btok[j];
    for (int c = threadIdx.x; c < C_; c += blockDim.x)
        p.xm[(size_t)(p.UNM + j) * C_ + c] = X[(size_t)n * C_ + c];
    if (threadIdx.x == 0) p.cnt[j] = 1.f;
}
__global__ void k_maccum(int w, const float* __restrict__ X) {
    BsmP p = getp(w); int s = blockIdx.x;
    int n = p.srcn[s]; int dj = p.srcd[s];
    for (int c = threadIdx.x; c < C_; c += blockDim.x)
        atomicAdd(&p.xm[(size_t)(p.UNM + dj) * C_ + c], X[(size_t)n * C_ + c]);
    if (threadIdx.x == 0) atomicAdd(&p.cnt[dj], 1.f);
}
__global__ void k_mdiv(int w) {
    BsmP p = getp(w); int j = blockIdx.x;
    float inv = 1.f / p.cnt[j];
    for (int c = threadIdx.x; c < C_; c += blockDim.x)
        p.xm[(size_t)(p.UNM + j) * C_ + c] *= inv;
}
__global__ void k_mgather(int w, const float* __restrict__ X) {
    BsmP p = getp(w); int i = blockIdx.x;
    int n = p.unm[i];
    for (int c = threadIdx.x; c < C_; c += blockDim.x)
        p.xm[(size_t)i * C_ + c] = X[(size_t)n * C_ + c];
}

// ---------------- V transpose (per head) ----------------
__global__ void k_vt() {
    int t = blockIdx.x * blockDim.x + threadIdx.x;
    if (t >= NH * DH * NKVTOK) return;
    int h = t / (DH * NKVTOK);
    int d = (t / NKVTOK) % DH;
    int k = t % NKVTOK;
    g_vt[t] = g_kv[(size_t)k * (2 * C_) + C_ + h * DH + d];
}

// ---------------- softmax ----------------
__global__ void k_softmax() {
    size_t row = blockIdx.x;
    float* pp = g_sc + row * NKVTOK;
    float mx = -3.4e38f;
    for (int c = threadIdx.x; c < NKVTOK; c += 256) mx = fmaxf(mx, pp[c]);
    mx = blockReduce(mx, 1);
    float s = 0.f;
    for (int c = threadIdx.x; c < NKVTOK; c += 256) {
        float e = expf(pp[c] - mx); pp[c] = e; s += e;
    }
    s = blockReduce(s, 0);
    float inv = 1.f / s;
    for (int c = threadIdx.x; c < NKVTOK; c += 256) pp[c] *= inv;
}

// ---------------- unmerge ----------------
__global__ void k_unmerge_dst(const float* __restrict__ fp, float* __restrict__ out) {
    int j = blockIdx.x; int n = g_btok_q[j];
    for (int c = threadIdx.x; c < C_; c += blockDim.x)
        out[(size_t)n * C_ + c] = fp[(size_t)(UNMQ + j) * C_ + c];
}
__global__ void k_unmerge_unm(const float* __restrict__ fp, float* __restrict__ out) {
    int i = blockIdx.x; int n = g_unm_q[i];
    for (int c = threadIdx.x; c < C_; c += blockDim.x)
        out[(size_t)n * C_ + c] = fp[(size_t)i * C_ + c];
}
__global__ void k_unmerge_src(const float* __restrict__ fp, float* __restrict__ out) {
    int s = blockIdx.x; int n = g_srcn_q[s]; int dj = g_srcd_q[s];
    for (int c = threadIdx.x; c < C_; c += blockDim.x)
        out[(size_t)n * C_ + c] = fp[(size_t)(UNMQ + dj) * C_ + c];
}

// ---------------- host ----------------
extern "C" void kernel_launch(void* const* d_in, const int* in_sizes, int n_in,
                              void* d_out, int out_size) {
    const float* x   = (const float*)d_in[0];
    const float* srw = (const float*)d_in[1];
    const float* srb = (const float*)d_in[2];
    const float* lng = (const float*)d_in[3];
    const float* lnb = (const float*)d_in[4];
    const float* Wq  = (const float*)d_in[5];
    const float* Wkv = (const float*)d_in[6];
    const float* Wp  = (const float*)d_in[7];
    const float* bpb = (const float*)d_in[8];
    float* out = (float*)d_out;

    void *vp;
    float *p_xi2c, *p_wt, *p_xk, *p_xq, *p_xkm, *p_qb, *p_kv, *p_fp;
    cudaGetSymbolAddress(&vp, g_xi2c); p_xi2c = (float*)vp;
    cudaGetSymbolAddress(&vp, g_wt);   p_wt   = (float*)vp;
    cudaGetSymbolAddress(&vp, g_xk);   p_xk   = (float*)vp;
    cudaGetSymbolAddress(&vp, g_xq);   p_xq   = (float*)vp;
    cudaGetSymbolAddress(&vp, g_xkm);  p_xkm  = (float*)vp;
    cudaGetSymbolAddress(&vp, g_qb);   p_qb   = (float*)vp;
    cudaGetSymbolAddress(&vp, g_kv);   p_kv   = (float*)vp;
    cudaGetSymbolAddress(&vp, g_fp);   p_fp   = (float*)vp;
    float *p_ao; cudaGetSymbolAddress(&vp, g_ao); p_ao = (float*)vp;

    k_reset<<<(NQ_A + 255) / 256, 256>>>();
    k_tokmap<<<(NQ + 255) / 256, 256>>>(0, DQ, HQ, WQ);
    k_tokmap<<<(N2 + 255) / 256, 256>>>(1, D2, H2, W2);
    k_invn_x<<<NQ, 64>>>(x);
    k_wtrans<<<(C_ * KCONV + 255) / 256, 256>>>(srw);
    k_im2col<<<(N2 * KCONV + 255) / 256, 256>>>(x);

    // SR conv as GEMM (+bias, fp32 — feeds KV selection), then fused LN + inv-norm
    k_gemm2_nt<<<dim3(C_ / BN, N2 / BM), 256>>>(p_xi2c, KCONV, p_wt, KCONV,
                                                p_xk, C_, N2, C_, KCONV, srb, 1.f);
    k_ln<<<N2, 256>>>(lng, lnb);

    // Q-side BSM: bf16 mma.sync approx scores + exact refinement
    k_tobf_a<<<(NQ_A * (C_ / 4) + 255) / 256, 256>>>(x);
    k_tobf_b<<<(NQ_DST * (C_ / 4) + 255) / 256, 256>>>(x);
    k_scores_mma<<<dim3(NQ_DST / 128, NQ_A / 128), 256>>>();
    k_refine<<<NQ_A, 128>>>(x);
    k_select<<<1, 256>>>(0);
    k_classify<<<(NQ_A + 255) / 256, 256>>>(0);
    k_minit<<<NQ_DST, 256>>>(0, x);
    k_maccum<<<RQ, 256>>>(0, x);
    k_mdiv<<<NQ_DST, 256>>>(0);
    k_mgather<<<UNMQ, 256>>>(0, x);

    // KV-side BSM (small; exact fp32 path)
    k_scores2<<<dim3(NKV_DST / BN, NKV_A / BM), 256>>>(1, p_xk);
    k_select<<<1, 256>>>(1);
    k_classify<<<(NKV_A + 255) / 256, 256>>>(1);
    k_minit<<<NKV_DST, 256>>>(1, p_xk);
    k_maccum<<<RKV, 256>>>(1, p_xk);
    k_mdiv<<<NKV_DST, 256>>>(1);
    k_mgather<<<UNMKV, 256>>>(1, p_xk);

    // projections (tf32 mma — value path)
    k_gemm_tf32<<<dim3(C_ / 128, NQTOK / 128), 256>>>(p_xq, C_, Wq, C_,
                                                      p_qb, C_, NQTOK, C_, C_, nullptr, 1.f);
    k_gemm_tf32<<<dim3(2 * C_ / 128, NKVTOK / 128), 256>>>(p_xkm, C_, Wkv, C_,
                                                           p_kv, 2 * C_, NKVTOK, 2 * C_, C_, nullptr, 1.f);
    k_vt<<<(NH * DH * NKVTOK + 255) / 256, 256>>>();

    // attention (two-pass, batched over heads, tf32 mma)
    float scale = 1.0f / sqrtf((float)DH);
    k_qk_tf32<<<dim3(NKVTOK / 128, NQTOK / 128, NH), 256>>>(scale);
    k_softmax<<<NH * NQTOK, 256>>>();
    k_av_tf32<<<dim3(1, NQTOK / 128, NH), 256>>>();

    // output projection + bias (tf32), then unmerge scatter
    k_gemm_tf32<<<dim3(C_ / 128, NQTOK / 128), 256>>>(p_ao, C_, Wp, C_,
                                                      p_fp, C_, NQTOK, C_, C_, bpb, 1.f);
    k_unmerge_dst<<<NQ_DST, 256>>>(p_fp, out);
    k_unmerge_unm<<<UNMQ, 256>>>(p_fp, out);
    k_unmerge_src<<<RQ, 256>>>(p_fp, out);
}

// round 13
// speedup vs baseline: 2.0395x; 1.2545x over previous
#include <cuda_runtime.h>
#include <cuda_bf16.h>
#include <math.h>

#define C_ 768
#define DQ 16
#define HQ 32
#define WQ 32
#define NQ 16384
#define D2 8
#define H2 16
#define W2 16
#define N2 2048
#define KCONV 6144
#define KSPLIT 2048

#define NQ_DST 2048
#define NQ_A 14336
#define RQ 8192
#define UNMQ 6144
#define NQTOK 8192

#define NKV_DST 256
#define NKV_A 1792
#define RKV 1024
#define UNMKV 768
#define NKVTOK 1024

#define NH 8
#define DH 96

typedef unsigned long long ull;

// ---------------- scratch (static device memory; no allocations) ----------------
__device__ float g_xi2c[(size_t)N2 * KCONV];   // reused: 3 conv split-K partial buffers
__device__ float g_wt[(size_t)C_ * KCONV];
__device__ float g_xk[N2 * C_];
__device__ int g_gtab[N2 * 8];
__device__ float g_invnq[NQ];
__device__ float g_invnk[N2];
__device__ int g_atok_q[NQ_A];
__device__ int g_btok_q[NQ_DST];
__device__ int g_atok_k[NKV_A];
__device__ int g_btok_k[NKV_DST];
__device__ ull g_nm_q[NQ_A];
__device__ ull g_nm_k[NKV_A];
__device__ unsigned g_apxmax[NQ_A];
__device__ ull g_thr[2];
__device__ int g_srcn_q[RQ], g_srcd_q[RQ], g_unm_q[UNMQ];
__device__ int g_srcn_k[RKV], g_srcd_k[RKV], g_unm_k[UNMKV];
__device__ int g_ctr[4];
__device__ float g_cnt_q[NQ_DST], g_cnt_k[NKV_DST];
__device__ float g_xq[NQTOK * C_];
__device__ float g_xkm[NKVTOK * C_];
__device__ float g_qb[NQTOK * C_];
__device__ float g_kv[NKVTOK * 2 * C_];
__device__ float g_vt[NH * DH * NKVTOK];
__device__ float g_sc[(size_t)NH * NQTOK * NKVTOK];
__device__ float g_ao[NQTOK * C_];
__device__ float g_fp[NQTOK * C_];
__device__ __nv_bfloat16 g_abf[(size_t)NQ_A * C_];
__device__ __nv_bfloat16 g_bbf[(size_t)NQ_DST * C_];

// ---------------- f32x2 helpers ----------------
__device__ __forceinline__ ull fma2(ull a, ull b, ull c) {
    ull d;
    asm("fma.rn.f32x2 %0, %1, %2, %3;" : "=l"(d) : "l"(a), "l"(b), "l"(c));
    return d;
}
__device__ __forceinline__ ull pack2(float x) {
    ull d;
    asm("mov.b64 %0, {%1, %1};" : "=l"(d) : "r"(__float_as_uint(x)));
    return d;
}
__device__ __forceinline__ float lo32(ull v) { return __uint_as_float((unsigned)v); }
__device__ __forceinline__ float hi32(ull v) { return __uint_as_float((unsigned)(v >> 32)); }

__device__ __forceinline__ unsigned f2tf(float f) {
    unsigned r;
    asm("cvt.rna.tf32.f32 %0, %1;" : "=r"(r) : "f"(f));
    return r;
}

// ---------------- misc helpers ----------------
struct BsmP {
    int* atok; int* btok;
    ull* nm; ull* thr;
    int* srcn; int* srcd; int* unm;
    int* csrc; int* cunm;
    float* cnt; float* xm;
    const float* invn;
    int NA, NB, R, UNM;
};

__device__ __forceinline__ BsmP getp(int w) {
    BsmP p;
    if (w == 0) {
        p.atok = g_atok_q; p.btok = g_btok_q; p.nm = g_nm_q; p.thr = &g_thr[0];
        p.srcn = g_srcn_q; p.srcd = g_srcd_q; p.unm = g_unm_q;
        p.csrc = &g_ctr[0]; p.cunm = &g_ctr[1];
        p.cnt = g_cnt_q; p.xm = g_xq; p.invn = g_invnq;
        p.NA = NQ_A; p.NB = NQ_DST; p.R = RQ; p.UNM = UNMQ;
    } else {
        p.atok = g_atok_k; p.btok = g_btok_k; p.nm = g_nm_k; p.thr = &g_thr[1];
        p.srcn = g_srcn_k; p.srcd = g_srcd_k; p.unm = g_unm_k;
        p.csrc = &g_ctr[2]; p.cunm = &g_ctr[3];
        p.cnt = g_cnt_k; p.xm = g_xkm; p.invn = g_invnk;
        p.NA = NKV_A; p.NB = NKV_DST; p.R = RKV; p.UNM = UNMKV;
    }
    return p;
}

__device__ __forceinline__ unsigned int fmono(float f) {
    unsigned int b = __float_as_uint(f);
    return b ^ ((b & 0x80000000u) ? 0xFFFFFFFFu : 0x80000000u);
}
__device__ __forceinline__ float unmono(unsigned u) {
    unsigned b = (u & 0x80000000u) ? (u ^ 0x80000000u) : ~u;
    return __uint_as_float(b);
}

__device__ __forceinline__ float blockReduce(float v, int ismax) {
    __shared__ float sh[40];
    __syncthreads();
    #pragma unroll
    for (int o = 16; o > 0; o >>= 1) {
        float u = __shfl_down_sync(0xffffffffu, v, o);
        v = ismax ? fmaxf(v, u) : (v + u);
    }
    if ((threadIdx.x & 31) == 0) sh[threadIdx.x >> 5] = v;
    __syncthreads();
    if (threadIdx.x == 0) {
        int nw = (blockDim.x + 31) >> 5;
        float r = sh[0];
        for (int i = 1; i < nw; i++) r = ismax ? fmaxf(r, sh[i]) : (r + sh[i]);
        sh[39] = r;
    }
    __syncthreads();
    return sh[39];
}

__device__ __forceinline__ int dst_before(int z, int y, int x, int HH, int WW) {
    int planes = ((z + 1) >> 1) * ((HH >> 1) * (WW >> 1));
    int extra = 0;
    if ((z & 1) == 0) {
        extra = ((y + 1) >> 1) * (WW >> 1);
        if ((y & 1) == 0) extra += ((x + 1) >> 1);
    }
    return planes + extra;
}

// ---------------- setup kernels ----------------
__global__ void k_reset() {
    int t = blockIdx.x * blockDim.x + threadIdx.x;
    if (t < NQ_A) { g_nm_q[t] = 0ull; g_apxmax[t] = 0u; }
    if (t < NKV_A) g_nm_k[t] = 0ull;
    if (t < 4) g_ctr[t] = 0;
}

__global__ void k_tokmap(int w, int DD, int HH, int WW) {
    BsmP p = getp(w);
    int n = blockIdx.x * blockDim.x + threadIdx.x;
    int NN = DD * HH * WW;
    if (n >= NN) return;
    int z = n / (HH * WW); int rem = n % (HH * WW); int y = rem / WW; int x = rem % WW;
    int db = dst_before(z, y, x, HH, WW);
    bool isdst = (((z | y | x) & 1) == 0);
    if (isdst) p.btok[db] = n; else p.atok[n - db] = n;
}

__global__ void k_gtab() {
    int m = blockIdx.x * blockDim.x + threadIdx.x;
    if (m >= N2) return;
    int z2 = m / (H2 * W2), y2 = (m / W2) % H2, x2 = m % W2;
    #pragma unroll
    for (int d = 0; d < 8; d++) {
        int z = 2 * z2 + (d >> 2), y = 2 * y2 + ((d >> 1) & 1), xx = 2 * x2 + (d & 1);
        g_gtab[m * 8 + d] = (z * (HQ * WQ) + y * WQ + xx) * C_;
    }
}

__global__ void k_invn_x(const float* __restrict__ X) {
    int m = blockIdx.x;
    float ss = 0.f;
    const float4* row = (const float4*)(X + (size_t)m * C_);
    for (int c = threadIdx.x; c < C_ / 4; c += 64) {
        float4 v = row[c];
        ss += v.x * v.x + v.y * v.y + v.z * v.z + v.w * v.w;
    }
    ss = blockReduce(ss, 0);
    if (threadIdx.x == 0) g_invnq[m] = rsqrtf(ss);
}

__global__ void k_wtrans(const float* __restrict__ srw) {
    int t = blockIdx.x * blockDim.x + threadIdx.x;
    if (t >= C_ * KCONV) return;
    int o = t / KCONV, k = t % KCONV;
    int dzyx = k / C_, i = k % C_;
    g_wt[t] = srw[o * KCONV + i * 8 + dzyx];
}

// LN with split-K combine (+conv bias), in -> g_xk, plus inv-norm of LN output
__global__ void k_ln(const float* __restrict__ srb,
                     const float* __restrict__ g, const float* __restrict__ b) {
    int m = blockIdx.x;
    const float* p0 = g_xi2c;
    const float* p1 = g_xi2c + (size_t)N2 * C_;
    const float* p2 = g_xi2c + 2 * (size_t)N2 * C_;
    float s = 0.f, ss = 0.f;
    for (int c = threadIdx.x; c < C_; c += 256) {
        size_t idx = (size_t)m * C_ + c;
        float v = p0[idx] + p1[idx] + p2[idx] + srb[c];
        g_xk[idx] = v;
        s += v; ss += v * v;
    }
    s = blockReduce(s, 0);
    ss = blockReduce(ss, 0);
    float mean = s * (1.0f / C_);
    float var = ss * (1.0f / C_) - mean * mean;
    float rstd = rsqrtf(var + 1e-5f);
    float s2 = 0.f;
    for (int c = threadIdx.x; c < C_; c += 256) {
        float v = (g_xk[m * C_ + c] - mean) * rstd * g[c] + b[c];
        g_xk[m * C_ + c] = v;
        s2 += v * v;
    }
    s2 = blockReduce(s2, 0);
    if (threadIdx.x == 0) g_invnk[m] = rsqrtf(s2);
}

// bf16 copies of gathered a/b rows for the MMA scores GEMM
__global__ void k_tobf_a(const float* __restrict__ X) {
    int t = blockIdx.x * blockDim.x + threadIdx.x;
    if (t >= NQ_A * (C_ / 4)) return;
    int row = t / (C_ / 4), u = t % (C_ / 4);
    int an = g_atok_q[row];
    float4 v = ((const float4*)(X + (size_t)an * C_))[u];
    unsigned short s0 = __bfloat16_as_ushort(__float2bfloat16(v.x));
    unsigned short s1 = __bfloat16_as_ushort(__float2bfloat16(v.y));
    unsigned short s2 = __bfloat16_as_ushort(__float2bfloat16(v.z));
    unsigned short s3 = __bfloat16_as_ushort(__float2bfloat16(v.w));
    uint2 w;
    w.x = (unsigned)s0 | ((unsigned)s1 << 16);
    w.y = (unsigned)s2 | ((unsigned)s3 << 16);
    *(uint2*)(&g_abf[(size_t)row * C_ + u * 4]) = w;
}
__global__ void k_tobf_b(const float* __restrict__ X) {
    int t = blockIdx.x * blockDim.x + threadIdx.x;
    if (t >= NQ_DST * (C_ / 4)) return;
    int row = t / (C_ / 4), u = t % (C_ / 4);
    int bn = g_btok_q[row];
    float4 v = ((const float4*)(X + (size_t)bn * C_))[u];
    unsigned short s0 = __bfloat16_as_ushort(__float2bfloat16(v.x));
    unsigned short s1 = __bfloat16_as_ushort(__float2bfloat16(v.y));
    unsigned short s2 = __bfloat16_as_ushort(__float2bfloat16(v.z));
    unsigned short s3 = __bfloat16_as_ushort(__float2bfloat16(v.w));
    uint2 w;
    w.x = (unsigned)s0 | ((unsigned)s1 << 16);
    w.y = (unsigned)s2 | ((unsigned)s3 << 16);
    *(uint2*)(&g_bbf[(size_t)row * C_ + u * 4]) = w;
}

// ---------------- bf16 mma.sync scores GEMM (approx pass) ----------------
#define LDK 40

__global__ void __launch_bounds__(256)
k_scores_mma() {
    __shared__ __nv_bfloat16 As[128 * LDK], Bs[128 * LDK];
    __shared__ float s_ainv[128], s_binv[128];
    int tid = threadIdx.x;
    int wid = tid >> 5, lane = tid & 31;
    int g = lane >> 2, t = lane & 3;
    int warp_m = wid >> 1, warp_n = wid & 1;
    int m0 = blockIdx.y * 128, n0 = blockIdx.x * 128;

    if (tid < 128) {
        s_ainv[tid] = g_invnq[g_atok_q[m0 + tid]];
        s_binv[tid] = g_invnq[g_btok_q[n0 + tid]];
    }

    float acc[2][8][4];
    #pragma unroll
    for (int mt = 0; mt < 2; mt++)
        #pragma unroll
        for (int nt = 0; nt < 8; nt++)
            #pragma unroll
            for (int j = 0; j < 4; j++) acc[mt][nt][j] = 0.f;

    for (int k0 = 0; k0 < C_; k0 += 32) {
        __syncthreads();
        #pragma unroll
        for (int i = 0; i < 4; i++) {
            int q = tid + i * 256;
            int r = q >> 3, u = q & 7;
            *(ull*)&As[r * LDK + u * 4] = *(const ull*)&g_abf[(size_t)(m0 + r) * C_ + k0 + u * 4];
            *(ull*)&Bs[r * LDK + u * 4] = *(const ull*)&g_bbf[(size_t)(n0 + r) * C_ + k0 + u * 4];
        }
        __syncthreads();
        #pragma unroll
        for (int ks = 0; ks < 2; ks++) {
            int koff = ks * 16;
            unsigned afr[2][4];
            #pragma unroll
            for (int mt = 0; mt < 2; mt++) {
                int r = warp_m * 32 + mt * 16 + g;
                afr[mt][0] = *(const unsigned*)&As[r * LDK + koff + t * 2];
                afr[mt][1] = *(const unsigned*)&As[(r + 8) * LDK + koff + t * 2];
                afr[mt][2] = *(const unsigned*)&As[r * LDK + koff + t * 2 + 8];
                afr[mt][3] = *(const unsigned*)&As[(r + 8) * LDK + koff + t * 2 + 8];
            }
            #pragma unroll
            for (int nt = 0; nt < 8; nt++) {
                int c = warp_n * 64 + nt * 8 + g;
                unsigned b0 = *(const unsigned*)&Bs[c * LDK + koff + t * 2];
                unsigned b1 = *(const unsigned*)&Bs[c * LDK + koff + t * 2 + 8];
                #pragma unroll
                for (int mt = 0; mt < 2; mt++) {
                    asm volatile(
                        "mma.sync.aligned.m16n8k16.row.col.f32.bf16.bf16.f32 "
                        "{%0,%1,%2,%3}, {%4,%5,%6,%7}, {%8,%9}, {%0,%1,%2,%3};"
                        : "+f"(acc[mt][nt][0]), "+f"(acc[mt][nt][1]),
                          "+f"(acc[mt][nt][2]), "+f"(acc[mt][nt][3])
                        : "r"(afr[mt][0]), "r"(afr[mt][1]),
                          "r"(afr[mt][2]), "r"(afr[mt][3]),
                          "r"(b0), "r"(b1));
                }
            }
        }
    }

    #pragma unroll
    for (int mt = 0; mt < 2; mt++) {
        int rloc0 = warp_m * 32 + mt * 16 + g;
        int rloc1 = rloc0 + 8;
        float aiv0 = s_ainv[rloc0], aiv1 = s_ainv[rloc1];
        float mx0 = -3.4e38f, mx1 = -3.4e38f;
        float* d0 = g_sc + (size_t)(m0 + rloc0) * NQ_DST + n0;
        float* d1 = g_sc + (size_t)(m0 + rloc1) * NQ_DST + n0;
        #pragma unroll
        for (int nt = 0; nt < 8; nt++) {
            int cloc = warp_n * 64 + nt * 8 + t * 2;
            float bi0 = s_binv[cloc], bi1 = s_binv[cloc + 1];
            float v00 = acc[mt][nt][0] * aiv0 * bi0;
            float v01 = acc[mt][nt][1] * aiv0 * bi1;
            float v10 = acc[mt][nt][2] * aiv1 * bi0;
            float v11 = acc[mt][nt][3] * aiv1 * bi1;
            *(float2*)(d0 + cloc) = make_float2(v00, v01);
            *(float2*)(d1 + cloc) = make_float2(v10, v11);
            mx0 = fmaxf(mx0, fmaxf(v00, v01));
            mx1 = fmaxf(mx1, fmaxf(v10, v11));
        }
        mx0 = fmaxf(mx0, __shfl_xor_sync(0xffffffffu, mx0, 1));
        mx0 = fmaxf(mx0, __shfl_xor_sync(0xffffffffu, mx0, 2));
        mx1 = fmaxf(mx1, __shfl_xor_sync(0xffffffffu, mx1, 1));
        mx1 = fmaxf(mx1, __shfl_xor_sync(0xffffffffu, mx1, 2));
        if (t == 0) {
            atomicMax(&g_apxmax[m0 + rloc0], fmono(mx0));
            atomicMax(&g_apxmax[m0 + rloc1], fmono(mx1));
        }
    }
}

// ---------------- exact refinement of rowmax/argmax ----------------
#define RMARGIN 0.01f
__global__ void __launch_bounds__(128)
k_refine(const float* __restrict__ X) {
    int row = blockIdx.x;
    int tid = threadIdx.x;
    float amax = unmono(g_apxmax[row]);
    float thr = amax - RMARGIN;
    int an = g_atok_q[row];
    float aiv = g_invnq[an];
    const float4* Xa = (const float4*)(X + (size_t)an * C_);
    const float* srow = g_sc + (size_t)row * NQ_DST;
    ull best = 0ull;
    for (int j = tid; j < NQ_DST; j += 128) {
        if (srow[j] >= thr) {
            int bn = g_btok_q[j];
            const float4* Xb = (const float4*)(X + (size_t)bn * C_);
            float s = 0.f;
            #pragma unroll 4
            for (int u = 0; u < C_ / 4; u++) {
                float4 a = Xa[u], b = Xb[u];
                s += a.x * b.x + a.y * b.y + a.z * b.z + a.w * b.w;
            }
            float val = s * aiv * g_invnq[bn];
            ull key = ((ull)fmono(val) << 32) | (ull)(0xFFFFFFFFu - (unsigned)j);
            if (key > best) best = key;
        }
    }
    #pragma unroll
    for (int o = 16; o > 0; o >>= 1) {
        ull u = __shfl_xor_sync(0xffffffffu, best, o);
        if (u > best) best = u;
    }
    __shared__ ull sred[4];
    if ((tid & 31) == 0) sred[tid >> 5] = best;
    __syncthreads();
    if (tid == 0) {
        ull b = sred[0];
        for (int i = 1; i < 4; i++) if (sred[i] > b) b = sred[i];
        g_nm_q[row] = b;
    }
}

// ---------------- tf32 mma GEMM: C[M,N] = alpha*A[M,K]@B[N,K]^T (+bias), K%32==0 ----------------
#define TLDK 36

__device__ __forceinline__ void
gemm_tf32_body(const float* __restrict__ A, int lda, const float* __restrict__ B, int ldb,
               float* __restrict__ Cm, int ldc, int M, int N, int K,
               const float* __restrict__ bias, float alpha) {
    __shared__ unsigned As[128 * TLDK], Bs[128 * TLDK];
    int tid = threadIdx.x;
    int wid = tid >> 5, lane = tid & 31;
    int g = lane >> 2, t = lane & 3;
    int warp_m = wid >> 1, warp_n = wid & 1;
    int m0 = blockIdx.y * 128, n0 = blockIdx.x * 128;

    float acc[2][8][4];
    #pragma unroll
    for (int mt = 0; mt < 2; mt++)
        #pragma unroll
        for (int nt = 0; nt < 8; nt++)
            #pragma unroll
            for (int j = 0; j < 4; j++) acc[mt][nt][j] = 0.f;

    for (int k0 = 0; k0 < K; k0 += 32) {
        __syncthreads();
        #pragma unroll
        for (int i = 0; i < 4; i++) {
            int c = tid + i * 256;
            int r = c >> 3, u = (c & 7) << 2;
            int mm = m0 + r;
            float4 va = make_float4(0.f, 0.f, 0.f, 0.f);
            if (mm < M) va = *(const float4*)(A + (size_t)mm * lda + k0 + u);
            As[r * TLDK + u + 0] = f2tf(va.x);
            As[r * TLDK + u + 1] = f2tf(va.y);
            As[r * TLDK + u + 2] = f2tf(va.z);
            As[r * TLDK + u + 3] = f2tf(va.w);
            int nn = n0 + r;
            float4 vb = make_float4(0.f, 0.f, 0.f, 0.f);
            if (nn < N) vb = *(const float4*)(B + (size_t)nn * ldb + k0 + u);
            Bs[r * TLDK + u + 0] = f2tf(vb.x);
            Bs[r * TLDK + u + 1] = f2tf(vb.y);
            Bs[r * TLDK + u + 2] = f2tf(vb.z);
            Bs[r * TLDK + u + 3] = f2tf(vb.w);
        }
        __syncthreads();
        #pragma unroll
        for (int ks = 0; ks < 4; ks++) {
            int koff = ks * 8;
            unsigned afr[2][4];
            #pragma unroll
            for (int mt = 0; mt < 2; mt++) {
                int r = warp_m * 32 + mt * 16 + g;
                afr[mt][0] = As[r * TLDK + koff + t];
                afr[mt][1] = As[(r + 8) * TLDK + koff + t];
                afr[mt][2] = As[r * TLDK + koff + t + 4];
                afr[mt][3] = As[(r + 8) * TLDK + koff + t + 4];
            }
            #pragma unroll
            for (int nt = 0; nt < 8; nt++) {
                int c = warp_n * 64 + nt * 8 + g;
                unsigned b0 = Bs[c * TLDK + koff + t];
                unsigned b1 = Bs[c * TLDK + koff + t + 4];
                #pragma unroll
                for (int mt = 0; mt < 2; mt++) {
                    asm volatile(
                        "mma.sync.aligned.m16n8k8.row.col.f32.tf32.tf32.f32 "
                        "{%0,%1,%2,%3}, {%4,%5,%6,%7}, {%8,%9}, {%0,%1,%2,%3};"
                        : "+f"(acc[mt][nt][0]), "+f"(acc[mt][nt][1]),
                          "+f"(acc[mt][nt][2]), "+f"(acc[mt][nt][3])
                        : "r"(afr[mt][0]), "r"(afr[mt][1]),
                          "r"(afr[mt][2]), "r"(afr[mt][3]),
                          "r"(b0), "r"(b1));
                }
            }
        }
    }

    #pragma unroll
    for (int mt = 0; mt < 2; mt++) {
        int r0 = m0 + warp_m * 32 + mt * 16 + g;
        int r1 = r0 + 8;
        #pragma unroll
        for (int nt = 0; nt < 8; nt++) {
            int nn = n0 + warp_n * 64 + nt * 8 + t * 2;
            if (nn >= N) continue;
            float b0v = bias ? bias[nn] : 0.f;
            float b1v = bias ? bias[nn + 1] : 0.f;
            if (r0 < M)
                *(float2*)(Cm + (size_t)r0 * ldc + nn) =
                    make_float2(acc[mt][nt][0] * alpha + b0v, acc[mt][nt][1] * alpha + b1v);
            if (r1 < M)
                *(float2*)(Cm + (size_t)r1 * ldc + nn) =
                    make_float2(acc[mt][nt][2] * alpha + b0v, acc[mt][nt][3] * alpha + b1v);
        }
    }
}

__global__ void __launch_bounds__(256)
k_gemm_tf32(const float* __restrict__ A, int lda, const float* __restrict__ B, int ldb,
            float* __restrict__ Cm, int ldc, int M, int N, int K,
            const float* __restrict__ bias, float alpha) {
    gemm_tf32_body(A, lda, B, ldb, Cm, ldc, M, N, K, bias, alpha);
}

__global__ void __launch_bounds__(256)
k_qk_tf32(float scale) {
    int h = blockIdx.z;
    gemm_tf32_body(g_qb + h * DH, C_, g_kv + h * DH, 2 * C_,
                   g_sc + (size_t)h * NQTOK * NKVTOK, NKVTOK,
                   NQTOK, NKVTOK, DH, nullptr, scale);
}

__global__ void __launch_bounds__(256)
k_av_tf32() {
    int h = blockIdx.z;
    gemm_tf32_body(g_sc + (size_t)h * NQTOK * NKVTOK, NKVTOK,
                   g_vt + (size_t)h * DH * NKVTOK, NKVTOK,
                   g_ao + h * DH, C_, NQTOK, DH, NKVTOK, nullptr, 1.f);
}

// ---------------- f32x2 split-K conv GEMM with fused im2col ----------------
// C_p[m][o] = sum_{k in split p} A_gather[m][k] * Wt[o][k]; grid (C_/128, N2/128, 3)
#define BM 128
#define BN 128
#define BK 16
#define LDAS 132

__global__ void __launch_bounds__(256)
k_conv_sk(const float* __restrict__ x) {
    __shared__ float As[BK][LDAS], Bs[BK][LDAS];
    __shared__ int s_gt[128 * 8];
    int p = blockIdx.z;
    int koff = p * KSPLIT;
    int m0 = blockIdx.y * BM, n0 = blockIdx.x * BN;
    int tid = threadIdx.x;
    int tx = tid & 15, ty = tid >> 4;
    for (int i = tid; i < 128 * 8; i += 256)
        s_gt[i] = g_gtab[(m0 + (i >> 3)) * 8 + (i & 7)];
    __syncthreads();

    ull acc[8][4];
    #pragma unroll
    for (int i = 0; i < 8; i++)
        #pragma unroll
        for (int j = 0; j < 4; j++) acc[i][j] = 0ull;

    for (int k0 = 0; k0 < KSPLIT; k0 += BK) {
        #pragma unroll
        for (int it = 0; it < 2; it++) {
            int c = tid + it * 256;
            int r = c >> 2, kq = (c & 3) << 2;
            int kg = koff + k0 + kq;
            int dz = kg / C_;
            int ii = kg - dz * C_;
            float4 va = *(const float4*)(x + (size_t)s_gt[r * 8 + dz] + ii);
            As[kq + 0][r] = va.x; As[kq + 1][r] = va.y; As[kq + 2][r] = va.z; As[kq + 3][r] = va.w;
            float4 vb = *(const float4*)(g_wt + (size_t)(n0 + r) * KCONV + kg);
            Bs[kq + 0][r] = vb.x; Bs[kq + 1][r] = vb.y; Bs[kq + 2][r] = vb.z; Bs[kq + 3][r] = vb.w;
        }
        __syncthreads();
        #pragma unroll
        for (int kk = 0; kk < BK; kk++) {
            float4 a0 = *(const float4*)&As[kk][ty * 8];
            float4 a1 = *(const float4*)&As[kk][ty * 8 + 4];
            longlong2 b0 = *(const longlong2*)&Bs[kk][tx * 8];
            longlong2 b1 = *(const longlong2*)&Bs[kk][tx * 8 + 4];
            float av[8] = {a0.x, a0.y, a0.z, a0.w, a1.x, a1.y, a1.z, a1.w};
            #pragma unroll
            for (int i = 0; i < 8; i++) {
                ull pa = pack2(av[i]);
                acc[i][0] = fma2(pa, (ull)b0.x, acc[i][0]);
                acc[i][1] = fma2(pa, (ull)b0.y, acc[i][1]);
                acc[i][2] = fma2(pa, (ull)b1.x, acc[i][2]);
                acc[i][3] = fma2(pa, (ull)b1.y, acc[i][3]);
            }
        }
        __syncthreads();
    }
    float* outp = g_xi2c + (size_t)p * N2 * C_;
    #pragma unroll
    for (int i = 0; i < 8; i++) {
        int mm = m0 + ty * 8 + i;
        float v[8];
        #pragma unroll
        for (int j2 = 0; j2 < 4; j2++) { v[2 * j2] = lo32(acc[i][j2]); v[2 * j2 + 1] = hi32(acc[i][j2]); }
        int nb = n0 + tx * 8;
        *(float4*)(outp + (size_t)mm * C_ + nb) = make_float4(v[0], v[1], v[2], v[3]);
        *(float4*)(outp + (size_t)mm * C_ + nb + 4) = make_float4(v[4], v[5], v[6], v[7]);
    }
}

// ---------------- fused similarity GEMM + rowwise packed max/argmax (KV side, fp32) ----------------
__global__ void __launch_bounds__(256)
k_scores2(int w, const float* __restrict__ X) {
    BsmP p = getp(w);
    __shared__ float As[BK][LDAS], Bs[BK][LDAS];
    __shared__ int arow[128], brow[128];
    __shared__ float ainv[128], binv[128];
    int m0 = blockIdx.y * BM, n0 = blockIdx.x * BN;
    int tid = threadIdx.x;
    int tx = tid & 15, ty = tid >> 4;
    if (tid < 128) {
        int an = p.atok[m0 + tid];
        arow[tid] = an; ainv[tid] = p.invn[an];
        int bn = p.btok[n0 + tid];
        brow[tid] = bn; binv[tid] = p.invn[bn];
    }
    __syncthreads();
    ull acc[8][4];
    #pragma unroll
    for (int i = 0; i < 8; i++)
        #pragma unroll
        for (int j = 0; j < 4; j++) acc[i][j] = 0ull;

    for (int k0 = 0; k0 < C_; k0 += BK) {
        #pragma unroll
        for (int it = 0; it < 2; it++) {
            int c = tid + it * 256;
            int r = c >> 2, kq = (c & 3) << 2;
            float4 va = *(const float4*)(X + (size_t)arow[r] * C_ + k0 + kq);
            As[kq + 0][r] = va.x; As[kq + 1][r] = va.y; As[kq + 2][r] = va.z; As[kq + 3][r] = va.w;
            float4 vb = *(const float4*)(X + (size_t)brow[r] * C_ + k0 + kq);
            Bs[kq + 0][r] = vb.x; Bs[kq + 1][r] = vb.y; Bs[kq + 2][r] = vb.z; Bs[kq + 3][r] = vb.w;
        }
        __syncthreads();
        #pragma unroll
        for (int kk = 0; kk < BK; kk++) {
            float4 a0 = *(const float4*)&As[kk][ty * 8];
            float4 a1 = *(const float4*)&As[kk][ty * 8 + 4];
            longlong2 b0 = *(const longlong2*)&Bs[kk][tx * 8];
            longlong2 b1 = *(const longlong2*)&Bs[kk][tx * 8 + 4];
            float av[8] = {a0.x, a0.y, a0.z, a0.w, a1.x, a1.y, a1.z, a1.w};
            #pragma unroll
            for (int i = 0; i < 8; i++) {
                ull pa = pack2(av[i]);
                acc[i][0] = fma2(pa, (ull)b0.x, acc[i][0]);
                acc[i][1] = fma2(pa, (ull)b0.y, acc[i][1]);
                acc[i][2] = fma2(pa, (ull)b1.x, acc[i][2]);
                acc[i][3] = fma2(pa, (ull)b1.y, acc[i][3]);
            }
        }
        __syncthreads();
    }
    #pragma unroll
    for (int i = 0; i < 8; i++) {
        int row = ty * 8 + i;
        float aiv = ainv[row];
        ull best = 0ull;
        #pragma unroll
        for (int j2 = 0; j2 < 4; j2++) {
            int c0 = tx * 8 + 2 * j2;
            float lo = lo32(acc[i][j2]) * aiv * binv[c0];
            float hi = hi32(acc[i][j2]) * aiv * binv[c0 + 1];
            int g0 = n0 + c0;
            ull klo = ((ull)fmono(lo) << 32) | (ull)(0xFFFFFFFFu - (unsigned)g0);
            ull khi = ((ull)fmono(hi) << 32) | (ull)(0xFFFFFFFFu - (unsigned)(g0 + 1));
            ull kb = klo > khi ? klo : khi;
            if (kb > best) best = kb;
        }
        {
            ull o;
            o = __shfl_xor_sync(0xffffffffu, best, 8);  if (o > best) best = o;
            o = __shfl_xor_sync(0xffffffffu, best, 4);  if (o > best) best = o;
            o = __shfl_xor_sync(0xffffffffu, best, 2);  if (o > best) best = o;
            o = __shfl_xor_sync(0xffffffffu, best, 1);  if (o > best) best = o;
        }
        if (tx == 0) atomicMax(&p.nm[m0 + row], best);
    }
}

// ---------------- exact top-r radix select ----------------
__global__ void k_select(int w) {
    BsmP p = getp(w);
    __shared__ unsigned int hist[256];
    __shared__ ull s_pref, s_mask;
    __shared__ int s_need;
    if (threadIdx.x == 0) { s_pref = 0ull; s_mask = 0ull; s_need = p.R; }
    __syncthreads();
    for (int shift = 56; shift >= 0; shift -= 8) {
        hist[threadIdx.x] = 0u;
        __syncthreads();
        ull pref = s_pref, mask = s_mask;
        for (int m = threadIdx.x; m < p.NA; m += 256) {
            ull key = (p.nm[m] & 0xFFFFFFFF00000000ull) |
                      (ull)(0xFFFFFFFFu - (unsigned)m);
            if ((key & mask) == pref)
                atomicAdd(&hist[(unsigned)(key >> shift) & 255u], 1u);
        }
        __syncthreads();
        if (threadIdx.x == 0) {
            int need = s_need, cum = 0, d;
            for (d = 255; d >= 0; d--) {
                int h = (int)hist[d];
                if (cum + h >= need) break;
                cum += h;
            }
            s_need = need - cum;
            s_pref = s_pref | (((ull)d) << shift);
            s_mask = s_mask | (255ull << shift);
        }
        __syncthreads();
    }
    if (threadIdx.x == 0) *p.thr = s_pref;
}

__global__ void k_classify(int w) {
    BsmP p = getp(w);
    int m = blockIdx.x * blockDim.x + threadIdx.x;
    if (m >= p.NA) return;
    ull pk = p.nm[m];
    ull key = (pk & 0xFFFFFFFF00000000ull) | (ull)(0xFFFFFFFFu - (unsigned)m);
    if (key >= *p.thr) {
        int s = atomicAdd(p.csrc, 1);
        p.srcn[s] = p.atok[m];
        p.srcd[s] = (int)(0xFFFFFFFFu - (unsigned)(pk & 0xFFFFFFFFull));
    } else {
        int s = atomicAdd(p.cunm, 1);
        p.unm[s] = p.atok[m];
    }
}

// ---------------- merge ----------------
__global__ void k_minit(int w, const float* __restrict__ X) {
    BsmP p = getp(w); int j = blockIdx.x;
    int n = p.btok[j];
    for (int c = threadIdx.x; c < C_; c += blockDim.x)
        p.xm[(size_t)(p.UNM + j) * C_ + c] = X[(size_t)n * C_ + c];
    if (threadIdx.x == 0) p.cnt[j] = 1.f;
}
__global__ void k_maccum(int w, const float* __restrict__ X) {
    BsmP p = getp(w); int s = blockIdx.x;
    int n = p.srcn[s]; int dj = p.srcd[s];
    for (int c = threadIdx.x; c < C_; c += blockDim.x)
        atomicAdd(&p.xm[(size_t)(p.UNM + dj) * C_ + c], X[(size_t)n * C_ + c]);
    if (threadIdx.x == 0) atomicAdd(&p.cnt[dj], 1.f);
}
__global__ void k_mdiv(int w) {
    BsmP p = getp(w); int j = blockIdx.x;
    float inv = 1.f / p.cnt[j];
    for (int c = threadIdx.x; c < C_; c += blockDim.x)
        p.xm[(size_t)(p.UNM + j) * C_ + c] *= inv;
}
__global__ void k_mgather(int w, const float* __restrict__ X) {
    BsmP p = getp(w); int i = blockIdx.x;
    int n = p.unm[i];
    for (int c = threadIdx.x; c < C_; c += blockDim.x)
        p.xm[(size_t)i * C_ + c] = X[(size_t)n * C_ + c];
}

// ---------------- V transpose (per head) ----------------
__global__ void k_vt() {
    int t = blockIdx.x * blockDim.x + threadIdx.x;
    if (t >= NH * DH * NKVTOK) return;
    int h = t / (DH * NKVTOK);
    int d = (t / NKVTOK) % DH;
    int k = t % NKVTOK;
    g_vt[t] = g_kv[(size_t)k * (2 * C_) + C_ + h * DH + d];
}

// ---------------- softmax ----------------
__global__ void k_softmax() {
    size_t row = blockIdx.x;
    float* pp = g_sc + row * NKVTOK;
    float mx = -3.4e38f;
    for (int c = threadIdx.x; c < NKVTOK; c += 256) mx = fmaxf(mx, pp[c]);
    mx = blockReduce(mx, 1);
    float s = 0.f;
    for (int c = threadIdx.x; c < NKVTOK; c += 256) {
        float e = expf(pp[c] - mx); pp[c] = e; s += e;
    }
    s = blockReduce(s, 0);
    float inv = 1.f / s;
    for (int c = threadIdx.x; c < NKVTOK; c += 256) pp[c] *= inv;
}

// ---------------- unmerge ----------------
__global__ void k_unmerge_dst(const float* __restrict__ fp, float* __restrict__ out) {
    int j = blockIdx.x; int n = g_btok_q[j];
    for (int c = threadIdx.x; c < C_; c += blockDim.x)
        out[(size_t)n * C_ + c] = fp[(size_t)(UNMQ + j) * C_ + c];
}
__global__ void k_unmerge_unm(const float* __restrict__ fp, float* __restrict__ out) {
    int i = blockIdx.x; int n = g_unm_q[i];
    for (int c = threadIdx.x; c < C_; c += blockDim.x)
        out[(size_t)n * C_ + c] = fp[(size_t)i * C_ + c];
}
__global__ void k_unmerge_src(const float* __restrict__ fp, float* __restrict__ out) {
    int s = blockIdx.x; int n = g_srcn_q[s]; int dj = g_srcd_q[s];
    for (int c = threadIdx.x; c < C_; c += blockDim.x)
        out[(size_t)n * C_ + c] = fp[(size_t)(UNMQ + dj) * C_ + c];
}

// ---------------- host ----------------
extern "C" void kernel_launch(void* const* d_in, const int* in_sizes, int n_in,
                              void* d_out, int out_size) {
    const float* x   = (const float*)d_in[0];
    const float* srw = (const float*)d_in[1];
    const float* srb = (const float*)d_in[2];
    const float* lng = (const float*)d_in[3];
    const float* lnb = (const float*)d_in[4];
    const float* Wq  = (const float*)d_in[5];
    const float* Wkv = (const float*)d_in[6];
    const float* Wp  = (const float*)d_in[7];
    const float* bpb = (const float*)d_in[8];
    float* out = (float*)d_out;

    void *vp;
    float *p_xk, *p_xq, *p_xkm, *p_qb, *p_kv, *p_fp, *p_ao;
    cudaGetSymbolAddress(&vp, g_xk);   p_xk   = (float*)vp;
    cudaGetSymbolAddress(&vp, g_xq);   p_xq   = (float*)vp;
    cudaGetSymbolAddress(&vp, g_xkm);  p_xkm  = (float*)vp;
    cudaGetSymbolAddress(&vp, g_qb);   p_qb   = (float*)vp;
    cudaGetSymbolAddress(&vp, g_kv);   p_kv   = (float*)vp;
    cudaGetSymbolAddress(&vp, g_fp);   p_fp   = (float*)vp;
    cudaGetSymbolAddress(&vp, g_ao);   p_ao   = (float*)vp;

    k_reset<<<(NQ_A + 255) / 256, 256>>>();
    k_tokmap<<<(NQ + 255) / 256, 256>>>(0, DQ, HQ, WQ);
    k_tokmap<<<(N2 + 255) / 256, 256>>>(1, D2, H2, W2);
    k_gtab<<<(N2 + 255) / 256, 256>>>();
    k_invn_x<<<NQ, 64>>>(x);
    k_wtrans<<<(C_ * KCONV + 255) / 256, 256>>>(srw);

    // SR conv: split-K x3 f32x2 GEMM with fused im2col, then LN combines partials + bias
    k_conv_sk<<<dim3(C_ / BN, N2 / BM, 3), 256>>>(x);
    k_ln<<<N2, 256>>>(srb, lng, lnb);

    // Q-side BSM: bf16 mma.sync approx scores + exact refinement
    k_tobf_a<<<(NQ_A * (C_ / 4) + 255) / 256, 256>>>(x);
    k_tobf_b<<<(NQ_DST * (C_ / 4) + 255) / 256, 256>>>(x);
    k_scores_mma<<<dim3(NQ_DST / 128, NQ_A / 128), 256>>>();
    k_refine<<<NQ_A, 128>>>(x);
    k_select<<<1, 256>>>(0);
    k_classify<<<(NQ_A + 255) / 256, 256>>>(0);
    k_minit<<<NQ_DST, 256>>>(0, x);
    k_maccum<<<RQ, 256>>>(0, x);
    k_mdiv<<<NQ_DST, 256>>>(0);
    k_mgather<<<UNMQ, 256>>>(0, x);

    // KV-side BSM (small; exact fp32 path)
    k_scores2<<<dim3(NKV_DST / BN, NKV_A / BM), 256>>>(1, p_xk);
    k_select<<<1, 256>>>(1);
    k_classify<<<(NKV_A + 255) / 256, 256>>>(1);
    k_minit<<<NKV_DST, 256>>>(1, p_xk);
    k_maccum<<<RKV, 256>>>(1, p_xk);
    k_mdiv<<<NKV_DST, 256>>>(1);
    k_mgather<<<UNMKV, 256>>>(1, p_xk);

    // projections (tf32 mma — value path)
    k_gemm_tf32<<<dim3(C_ / 128, NQTOK / 128), 256>>>(p_xq, C_, Wq, C_,
                                                      p_qb, C_, NQTOK, C_, C_, nullptr, 1.f);
    k_gemm_tf32<<<dim3(2 * C_ / 128, NKVTOK / 128), 256>>>(p_xkm, C_, Wkv, C_,
                                                           p_kv, 2 * C_, NKVTOK, 2 * C_, C_, nullptr, 1.f);
    k_vt<<<(NH * DH * NKVTOK + 255) / 256, 256>>>();

    // attention (two-pass, batched over heads, tf32 mma)
    float scale = 1.0f / sqrtf((float)DH);
    k_qk_tf32<<<dim3(NKVTOK / 128, NQTOK / 128, NH), 256>>>(scale);
    k_softmax<<<NH * NQTOK, 256>>>();
    k_av_tf32<<<dim3(1, NQTOK / 128, NH), 256>>>();

    // output projection + bias (tf32), then unmerge scatter
    k_gemm_tf32<<<dim3(C_ / 128, NQTOK / 128), 256>>>(p_ao, C_, Wp, C_,
                                                      p_fp, C_, NQTOK, C_, C_, bpb, 1.f);
    k_unmerge_dst<<<NQ_DST, 256>>>(p_fp, out);
    k_unmerge_unm<<<UNMQ, 256>>>(p_fp, out);
    k_unmerge_src<<<RQ, 256>>>(p_fp, out);
}

// round 15
// speedup vs baseline: 2.1066x; 1.0329x over previous
#include <cuda_runtime.h>
#include <cuda_bf16.h>
#include <math.h>

#define C_ 768
#define DQ 16
#define HQ 32
#define WQ 32
#define NQ 16384
#define D2 8
#define H2 16
#define W2 16
#define N2 2048
#define KCONV 6144
#define KSPLIT 2048

#define NQ_DST 2048
#define NQ_A 14336
#define RQ 8192
#define UNMQ 6144
#define NQTOK 8192

#define NKV_DST 256
#define NKV_A 1792
#define RKV 1024
#define UNMKV 768
#define NKVTOK 1024

#define NH 8
#define DH 96

typedef unsigned long long ull;

// ---------------- scratch (static device memory; no allocations) ----------------
__device__ float g_xi2c[(size_t)N2 * KCONV];   // reused: 3 conv split-K partial buffers
__device__ float g_wt[(size_t)C_ * KCONV];
__device__ float g_xk[N2 * C_];
__device__ int g_gtab[N2 * 8];
__device__ float g_invnq[NQ];
__device__ float g_invnk[N2];
__device__ int g_atok_q[NQ_A];
__device__ int g_btok_q[NQ_DST];
__device__ int g_atok_k[NKV_A];
__device__ int g_btok_k[NKV_DST];
__device__ ull g_nm_q[NQ_A];
__device__ ull g_nm_k[NKV_A];
__device__ unsigned g_apxmax[NQ_A];
__device__ ull g_thr[2];
__device__ int g_srcn_q[RQ], g_srcd_q[RQ], g_unm_q[UNMQ];
__device__ int g_srcn_k[RKV], g_srcd_k[RKV], g_unm_k[UNMKV];
__device__ int g_ctr[4];
__device__ float g_cnt_q[NQ_DST], g_cnt_k[NKV_DST];
__device__ float g_xq[NQTOK * C_];
__device__ float g_xkm[NKVTOK * C_];
__device__ float g_qb[NQTOK * C_];
__device__ float g_kv[NKVTOK * 2 * C_];
__device__ float g_vt[NH * DH * NKVTOK];
__device__ float g_sc[(size_t)NH * NQTOK * NKVTOK];
__device__ float g_ao[NQTOK * C_];
__device__ float g_fp[NQTOK * C_];
__device__ __nv_bfloat16 g_abf[(size_t)NQ_A * C_];
__device__ __nv_bfloat16 g_bbf[(size_t)NQ_DST * C_];

// ---------------- f32x2 helpers ----------------
__device__ __forceinline__ ull fma2(ull a, ull b, ull c) {
    ull d;
    asm("fma.rn.f32x2 %0, %1, %2, %3;" : "=l"(d) : "l"(a), "l"(b), "l"(c));
    return d;
}
__device__ __forceinline__ ull pack2(float x) {
    ull d;
    asm("mov.b64 %0, {%1, %1};" : "=l"(d) : "r"(__float_as_uint(x)));
    return d;
}
__device__ __forceinline__ float lo32(ull v) { return __uint_as_float((unsigned)v); }
__device__ __forceinline__ float hi32(ull v) { return __uint_as_float((unsigned)(v >> 32)); }
__device__ __forceinline__ unsigned ulo32(ull v) { return (unsigned)v; }
__device__ __forceinline__ unsigned uhi32(ull v) { return (unsigned)(v >> 32); }

__device__ __forceinline__ unsigned f2tf(float f) {
    unsigned r;
    asm("cvt.rna.tf32.f32 %0, %1;" : "=r"(r) : "f"(f));
    return r;
}

// ---------------- misc helpers ----------------
struct BsmP {
    int* atok; int* btok;
    ull* nm; ull* thr;
    int* srcn; int* srcd; int* unm;
    int* csrc; int* cunm;
    float* cnt; float* xm;
    const float* invn;
    int NA, NB, R, UNM;
};

__device__ __forceinline__ BsmP getp(int w) {
    BsmP p;
    if (w == 0) {
        p.atok = g_atok_q; p.btok = g_btok_q; p.nm = g_nm_q; p.thr = &g_thr[0];
        p.srcn = g_srcn_q; p.srcd = g_srcd_q; p.unm = g_unm_q;
        p.csrc = &g_ctr[0]; p.cunm = &g_ctr[1];
        p.cnt = g_cnt_q; p.xm = g_xq; p.invn = g_invnq;
        p.NA = NQ_A; p.NB = NQ_DST; p.R = RQ; p.UNM = UNMQ;
    } else {
        p.atok = g_atok_k; p.btok = g_btok_k; p.nm = g_nm_k; p.thr = &g_thr[1];
        p.srcn = g_srcn_k; p.srcd = g_srcd_k; p.unm = g_unm_k;
        p.csrc = &g_ctr[2]; p.cunm = &g_ctr[3];
        p.cnt = g_cnt_k; p.xm = g_xkm; p.invn = g_invnk;
        p.NA = NKV_A; p.NB = NKV_DST; p.R = RKV; p.UNM = UNMKV;
    }
    return p;
}

__device__ __forceinline__ unsigned int fmono(float f) {
    unsigned int b = __float_as_uint(f);
    return b ^ ((b & 0x80000000u) ? 0xFFFFFFFFu : 0x80000000u);
}
__device__ __forceinline__ float unmono(unsigned u) {
    unsigned b = (u & 0x80000000u) ? (u ^ 0x80000000u) : ~u;
    return __uint_as_float(b);
}

__device__ __forceinline__ float blockReduce(float v, int ismax) {
    __shared__ float sh[40];
    __syncthreads();
    #pragma unroll
    for (int o = 16; o > 0; o >>= 1) {
        float u = __shfl_down_sync(0xffffffffu, v, o);
        v = ismax ? fmaxf(v, u) : (v + u);
    }
    if ((threadIdx.x & 31) == 0) sh[threadIdx.x >> 5] = v;
    __syncthreads();
    if (threadIdx.x == 0) {
        int nw = (blockDim.x + 31) >> 5;
        float r = sh[0];
        for (int i = 1; i < nw; i++) r = ismax ? fmaxf(r, sh[i]) : (r + sh[i]);
        sh[39] = r;
    }
    __syncthreads();
    return sh[39];
}

__device__ __forceinline__ int dst_before(int z, int y, int x, int HH, int WW) {
    int planes = ((z + 1) >> 1) * ((HH >> 1) * (WW >> 1));
    int extra = 0;
    if ((z & 1) == 0) {
        extra = ((y + 1) >> 1) * (WW >> 1);
        if ((y & 1) == 0) extra += ((x + 1) >> 1);
    }
    return planes + extra;
}

// ---------------- setup kernels ----------------
__global__ void k_reset() {
    int t = blockIdx.x * blockDim.x + threadIdx.x;
    if (t < NQ_A) { g_nm_q[t] = 0ull; g_apxmax[t] = 0u; }
    if (t < NKV_A) g_nm_k[t] = 0ull;
    if (t < 4) g_ctr[t] = 0;
}

__global__ void k_tokmap(int w, int DD, int HH, int WW) {
    BsmP p = getp(w);
    int n = blockIdx.x * blockDim.x + threadIdx.x;
    int NN = DD * HH * WW;
    if (n >= NN) return;
    int z = n / (HH * WW); int rem = n % (HH * WW); int y = rem / WW; int x = rem % WW;
    int db = dst_before(z, y, x, HH, WW);
    bool isdst = (((z | y | x) & 1) == 0);
    if (isdst) p.btok[db] = n; else p.atok[n - db] = n;
}

__global__ void k_gtab() {
    int m = blockIdx.x * blockDim.x + threadIdx.x;
    if (m >= N2) return;
    int z2 = m / (H2 * W2), y2 = (m / W2) % H2, x2 = m % W2;
    #pragma unroll
    for (int d = 0; d < 8; d++) {
        int z = 2 * z2 + (d >> 2), y = 2 * y2 + ((d >> 1) & 1), xx = 2 * x2 + (d & 1);
        g_gtab[m * 8 + d] = (z * (HQ * WQ) + y * WQ + xx) * C_;
    }
}

__global__ void k_invn_x(const float* __restrict__ X) {
    int m = blockIdx.x;
    float ss = 0.f;
    const float4* row = (const float4*)(X + (size_t)m * C_);
    for (int c = threadIdx.x; c < C_ / 4; c += 64) {
        float4 v = row[c];
        ss += v.x * v.x + v.y * v.y + v.z * v.z + v.w * v.w;
    }
    ss = blockReduce(ss, 0);
    if (threadIdx.x == 0) g_invnq[m] = rsqrtf(ss);
}

__global__ void k_wtrans(const float* __restrict__ srw) {
    int t = blockIdx.x * blockDim.x + threadIdx.x;
    if (t >= C_ * KCONV) return;
    int o = t / KCONV, k = t % KCONV;
    int dzyx = k / C_, i = k % C_;
    g_wt[t] = srw[o * KCONV + i * 8 + dzyx];
}

// LN with split-K combine (+conv bias), in -> g_xk, plus inv-norm of LN output
__global__ void k_ln(const float* __restrict__ srb,
                     const float* __restrict__ g, const float* __restrict__ b) {
    int m = blockIdx.x;
    const float* p0 = g_xi2c;
    const float* p1 = g_xi2c + (size_t)N2 * C_;
    const float* p2 = g_xi2c + 2 * (size_t)N2 * C_;
    float s = 0.f, ss = 0.f;
    for (int c = threadIdx.x; c < C_; c += 256) {
        size_t idx = (size_t)m * C_ + c;
        float v = p0[idx] + p1[idx] + p2[idx] + srb[c];
        g_xk[idx] = v;
        s += v; ss += v * v;
    }
    s = blockReduce(s, 0);
    ss = blockReduce(ss, 0);
    float mean = s * (1.0f / C_);
    float var = ss * (1.0f / C_) - mean * mean;
    float rstd = rsqrtf(var + 1e-5f);
    float s2 = 0.f;
    for (int c = threadIdx.x; c < C_; c += 256) {
        float v = (g_xk[m * C_ + c] - mean) * rstd * g[c] + b[c];
        g_xk[m * C_ + c] = v;
        s2 += v * v;
    }
    s2 = blockReduce(s2, 0);
    if (threadIdx.x == 0) g_invnk[m] = rsqrtf(s2);
}

// bf16 copies of gathered a/b rows for the MMA scores GEMM
__global__ void k_tobf_a(const float* __restrict__ X) {
    int t = blockIdx.x * blockDim.x + threadIdx.x;
    if (t >= NQ_A * (C_ / 4)) return;
    int row = t / (C_ / 4), u = t % (C_ / 4);
    int an = g_atok_q[row];
    float4 v = ((const float4*)(X + (size_t)an * C_))[u];
    unsigned short s0 = __bfloat16_as_ushort(__float2bfloat16(v.x));
    unsigned short s1 = __bfloat16_as_ushort(__float2bfloat16(v.y));
    unsigned short s2 = __bfloat16_as_ushort(__float2bfloat16(v.z));
    unsigned short s3 = __bfloat16_as_ushort(__float2bfloat16(v.w));
    uint2 w;
    w.x = (unsigned)s0 | ((unsigned)s1 << 16);
    w.y = (unsigned)s2 | ((unsigned)s3 << 16);
    *(uint2*)(&g_abf[(size_t)row * C_ + u * 4]) = w;
}
__global__ void k_tobf_b(const float* __restrict__ X) {
    int t = blockIdx.x * blockDim.x + threadIdx.x;
    if (t >= NQ_DST * (C_ / 4)) return;
    int row = t / (C_ / 4), u = t % (C_ / 4);
    int bn = g_btok_q[row];
    float4 v = ((const float4*)(X + (size_t)bn * C_))[u];
    unsigned short s0 = __bfloat16_as_ushort(__float2bfloat16(v.x));
    unsigned short s1 = __bfloat16_as_ushort(__float2bfloat16(v.y));
    unsigned short s2 = __bfloat16_as_ushort(__float2bfloat16(v.z));
    unsigned short s3 = __bfloat16_as_ushort(__float2bfloat16(v.w));
    uint2 w;
    w.x = (unsigned)s0 | ((unsigned)s1 << 16);
    w.y = (unsigned)s2 | ((unsigned)s3 << 16);
    *(uint2*)(&g_bbf[(size_t)row * C_ + u * 4]) = w;
}

// ---------------- bf16 mma.sync scores GEMM (approx pass) ----------------
#define LDK 40

__global__ void __launch_bounds__(256)
k_scores_mma() {
    __shared__ __nv_bfloat16 As[128 * LDK], Bs[128 * LDK];
    __shared__ float s_ainv[128], s_binv[128];
    int tid = threadIdx.x;
    int wid = tid >> 5, lane = tid & 31;
    int g = lane >> 2, t = lane & 3;
    int warp_m = wid >> 1, warp_n = wid & 1;
    int m0 = blockIdx.y * 128, n0 = blockIdx.x * 128;

    if (tid < 128) {
        s_ainv[tid] = g_invnq[g_atok_q[m0 + tid]];
        s_binv[tid] = g_invnq[g_btok_q[n0 + tid]];
    }

    float acc[2][8][4];
    #pragma unroll
    for (int mt = 0; mt < 2; mt++)
        #pragma unroll
        for (int nt = 0; nt < 8; nt++)
            #pragma unroll
            for (int j = 0; j < 4; j++) acc[mt][nt][j] = 0.f;

    for (int k0 = 0; k0 < C_; k0 += 32) {
        __syncthreads();
        #pragma unroll
        for (int i = 0; i < 4; i++) {
            int q = tid + i * 256;
            int r = q >> 3, u = q & 7;
            *(ull*)&As[r * LDK + u * 4] = *(const ull*)&g_abf[(size_t)(m0 + r) * C_ + k0 + u * 4];
            *(ull*)&Bs[r * LDK + u * 4] = *(const ull*)&g_bbf[(size_t)(n0 + r) * C_ + k0 + u * 4];
        }
        __syncthreads();
        #pragma unroll
        for (int ks = 0; ks < 2; ks++) {
            int koff = ks * 16;
            unsigned afr[2][4];
            #pragma unroll
            for (int mt = 0; mt < 2; mt++) {
                int r = warp_m * 32 + mt * 16 + g;
                afr[mt][0] = *(const unsigned*)&As[r * LDK + koff + t * 2];
                afr[mt][1] = *(const unsigned*)&As[(r + 8) * LDK + koff + t * 2];
                afr[mt][2] = *(const unsigned*)&As[r * LDK + koff + t * 2 + 8];
                afr[mt][3] = *(const unsigned*)&As[(r + 8) * LDK + koff + t * 2 + 8];
            }
            #pragma unroll
            for (int nt = 0; nt < 8; nt++) {
                int c = warp_n * 64 + nt * 8 + g;
                unsigned b0 = *(const unsigned*)&Bs[c * LDK + koff + t * 2];
                unsigned b1 = *(const unsigned*)&Bs[c * LDK + koff + t * 2 + 8];
                #pragma unroll
                for (int mt = 0; mt < 2; mt++) {
                    asm volatile(
                        "mma.sync.aligned.m16n8k16.row.col.f32.bf16.bf16.f32 "
                        "{%0,%1,%2,%3}, {%4,%5,%6,%7}, {%8,%9}, {%0,%1,%2,%3};"
                        : "+f"(acc[mt][nt][0]), "+f"(acc[mt][nt][1]),
                          "+f"(acc[mt][nt][2]), "+f"(acc[mt][nt][3])
                        : "r"(afr[mt][0]), "r"(afr[mt][1]),
                          "r"(afr[mt][2]), "r"(afr[mt][3]),
                          "r"(b0), "r"(b1));
                }
            }
        }
    }

    #pragma unroll
    for (int mt = 0; mt < 2; mt++) {
        int rloc0 = warp_m * 32 + mt * 16 + g;
        int rloc1 = rloc0 + 8;
        float aiv0 = s_ainv[rloc0], aiv1 = s_ainv[rloc1];
        float mx0 = -3.4e38f, mx1 = -3.4e38f;
        float* d0 = g_sc + (size_t)(m0 + rloc0) * NQ_DST + n0;
        float* d1 = g_sc + (size_t)(m0 + rloc1) * NQ_DST + n0;
        #pragma unroll
        for (int nt = 0; nt < 8; nt++) {
            int cloc = warp_n * 64 + nt * 8 + t * 2;
            float bi0 = s_binv[cloc], bi1 = s_binv[cloc + 1];
            float v00 = acc[mt][nt][0] * aiv0 * bi0;
            float v01 = acc[mt][nt][1] * aiv0 * bi1;
            float v10 = acc[mt][nt][2] * aiv1 * bi0;
            float v11 = acc[mt][nt][3] * aiv1 * bi1;
            *(float2*)(d0 + cloc) = make_float2(v00, v01);
            *(float2*)(d1 + cloc) = make_float2(v10, v11);
            mx0 = fmaxf(mx0, fmaxf(v00, v01));
            mx1 = fmaxf(mx1, fmaxf(v10, v11));
        }
        mx0 = fmaxf(mx0, __shfl_xor_sync(0xffffffffu, mx0, 1));
        mx0 = fmaxf(mx0, __shfl_xor_sync(0xffffffffu, mx0, 2));
        mx1 = fmaxf(mx1, __shfl_xor_sync(0xffffffffu, mx1, 1));
        mx1 = fmaxf(mx1, __shfl_xor_sync(0xffffffffu, mx1, 2));
        if (t == 0) {
            atomicMax(&g_apxmax[m0 + rloc0], fmono(mx0));
            atomicMax(&g_apxmax[m0 + rloc1], fmono(mx1));
        }
    }
}

// ---------------- exact refinement of rowmax/argmax ----------------
#define RMARGIN 0.01f
__global__ void __launch_bounds__(128)
k_refine(const float* __restrict__ X) {
    int row = blockIdx.x;
    int tid = threadIdx.x;
    float amax = unmono(g_apxmax[row]);
    float thr = amax - RMARGIN;
    int an = g_atok_q[row];
    float aiv = g_invnq[an];
    const float4* Xa = (const float4*)(X + (size_t)an * C_);
    const float* srow = g_sc + (size_t)row * NQ_DST;
    ull best = 0ull;
    for (int j = tid; j < NQ_DST; j += 128) {
        if (srow[j] >= thr) {
            int bn = g_btok_q[j];
            const float4* Xb = (const float4*)(X + (size_t)bn * C_);
            float s = 0.f;
            #pragma unroll 4
            for (int u = 0; u < C_ / 4; u++) {
                float4 a = Xa[u], b = Xb[u];
                s += a.x * b.x + a.y * b.y + a.z * b.z + a.w * b.w;
            }
            float val = s * aiv * g_invnq[bn];
            ull key = ((ull)fmono(val) << 32) | (ull)(0xFFFFFFFFu - (unsigned)j);
            if (key > best) best = key;
        }
    }
    #pragma unroll
    for (int o = 16; o > 0; o >>= 1) {
        ull u = __shfl_xor_sync(0xffffffffu, best, o);
        if (u > best) best = u;
    }
    __shared__ ull sred[4];
    if ((tid & 31) == 0) sred[tid >> 5] = best;
    __syncthreads();
    if (tid == 0) {
        ull b = sred[0];
        for (int i = 1; i < 4; i++) if (sred[i] > b) b = sred[i];
        g_nm_q[row] = b;
    }
}

// ---------------- tf32 mma GEMM: C[M,N] = alpha*A[M,K]@B[N,K]^T (+bias), K%32==0 ----------------
// k-permuted SMEM layout: within each 8-k group, pos = (k&3)*2 + ((k>>2)&1),
// so fragment pairs (k=t, k=t+4) are adjacent -> LDS.64 fragment loads.
#define TLDK 40

__device__ __forceinline__ void
gemm_tf32_body(const float* __restrict__ A, int lda, const float* __restrict__ B, int ldb,
               float* __restrict__ Cm, int ldc, int M, int N, int K,
               const float* __restrict__ bias, float alpha) {
    __shared__ unsigned As[128 * TLDK], Bs[128 * TLDK];
    int tid = threadIdx.x;
    int wid = tid >> 5, lane = tid & 31;
    int g = lane >> 2, t = lane & 3;
    int warp_m = wid >> 1, warp_n = wid & 1;
    int m0 = blockIdx.y * 128, n0 = blockIdx.x * 128;

    float acc[2][8][4];
    #pragma unroll
    for (int mt = 0; mt < 2; mt++)
        #pragma unroll
        for (int nt = 0; nt < 8; nt++)
            #pragma unroll
            for (int j = 0; j < 4; j++) acc[mt][nt][j] = 0.f;

    for (int k0 = 0; k0 < K; k0 += 32) {
        __syncthreads();
        #pragma unroll
        for (int i = 0; i < 4; i++) {
            int c = tid + i * 256;
            int r = c >> 3, u = (c & 7) << 2;
            int pb = r * TLDK + ((u >> 3) << 3) + ((u >> 2) & 1);
            int mm = m0 + r;
            float4 va = make_float4(0.f, 0.f, 0.f, 0.f);
            if (mm < M) va = *(const float4*)(A + (size_t)mm * lda + k0 + u);
            As[pb + 0] = f2tf(va.x);
            As[pb + 2] = f2tf(va.y);
            As[pb + 4] = f2tf(va.z);
            As[pb + 6] = f2tf(va.w);
            int nn = n0 + r;
            float4 vb = make_float4(0.f, 0.f, 0.f, 0.f);
            if (nn < N) vb = *(const float4*)(B + (size_t)nn * ldb + k0 + u);
            Bs[pb + 0] = f2tf(vb.x);
            Bs[pb + 2] = f2tf(vb.y);
            Bs[pb + 4] = f2tf(vb.z);
            Bs[pb + 6] = f2tf(vb.w);
        }
        __syncthreads();
        #pragma unroll
        for (int ks = 0; ks < 4; ks++) {
            int koff = ks * 8 + t * 2;
            unsigned afr[2][4];
            #pragma unroll
            for (int mt = 0; mt < 2; mt++) {
                int r = warp_m * 32 + mt * 16 + g;
                ull A0 = *(const ull*)&As[r * TLDK + koff];
                ull A1 = *(const ull*)&As[(r + 8) * TLDK + koff];
                afr[mt][0] = ulo32(A0);
                afr[mt][2] = uhi32(A0);
                afr[mt][1] = ulo32(A1);
                afr[mt][3] = uhi32(A1);
            }
            #pragma unroll
            for (int nt = 0; nt < 8; nt++) {
                int c = warp_n * 64 + nt * 8 + g;
                ull Bv = *(const ull*)&Bs[c * TLDK + koff];
                unsigned b0 = ulo32(Bv), b1 = uhi32(Bv);
                #pragma unroll
                for (int mt = 0; mt < 2; mt++) {
                    asm volatile(
                        "mma.sync.aligned.m16n8k8.row.col.f32.tf32.tf32.f32 "
                        "{%0,%1,%2,%3}, {%4,%5,%6,%7}, {%8,%9}, {%0,%1,%2,%3};"
                        : "+f"(acc[mt][nt][0]), "+f"(acc[mt][nt][1]),
                          "+f"(acc[mt][nt][2]), "+f"(acc[mt][nt][3])
                        : "r"(afr[mt][0]), "r"(afr[mt][1]),
                          "r"(afr[mt][2]), "r"(afr[mt][3]),
                          "r"(b0), "r"(b1));
                }
            }
        }
    }

    #pragma unroll
    for (int mt = 0; mt < 2; mt++) {
        int r0 = m0 + warp_m * 32 + mt * 16 + g;
        int r1 = r0 + 8;
        #pragma unroll
        for (int nt = 0; nt < 8; nt++) {
            int nn = n0 + warp_n * 64 + nt * 8 + t * 2;
            if (nn >= N) continue;
            float b0v = bias ? bias[nn] : 0.f;
            float b1v = bias ? bias[nn + 1] : 0.f;
            if (r0 < M)
                *(float2*)(Cm + (size_t)r0 * ldc + nn) =
                    make_float2(acc[mt][nt][0] * alpha + b0v, acc[mt][nt][1] * alpha + b1v);
            if (r1 < M)
                *(float2*)(Cm + (size_t)r1 * ldc + nn) =
                    make_float2(acc[mt][nt][2] * alpha + b0v, acc[mt][nt][3] * alpha + b1v);
        }
    }
}

__global__ void __launch_bounds__(256)
k_gemm_tf32(const float* __restrict__ A, int lda, const float* __restrict__ B, int ldb,
            float* __restrict__ Cm, int ldc, int M, int N, int K,
            const float* __restrict__ bias, float alpha) {
    gemm_tf32_body(A, lda, B, ldb, Cm, ldc, M, N, K, bias, alpha);
}

__global__ void __launch_bounds__(256)
k_qk_tf32(float scale) {
    int h = blockIdx.z;
    gemm_tf32_body(g_qb + h * DH, C_, g_kv + h * DH, 2 * C_,
                   g_sc + (size_t)h * NQTOK * NKVTOK, NKVTOK,
                   NQTOK, NKVTOK, DH, nullptr, scale);
}

__global__ void __launch_bounds__(256)
k_av_tf32() {
    int h = blockIdx.z;
    gemm_tf32_body(g_sc + (size_t)h * NQTOK * NKVTOK, NKVTOK,
                   g_vt + (size_t)h * DH * NKVTOK, NKVTOK,
                   g_ao + h * DH, C_, NQTOK, DH, NKVTOK, nullptr, 1.f);
}

// ---------------- f32x2 split-K conv GEMM with fused im2col ----------------
#define BM 128
#define BN 128
#define BK 16
#define LDAS 132

__global__ void __launch_bounds__(256)
k_conv_sk(const float* __restrict__ x) {
    __shared__ float As[BK][LDAS], Bs[BK][LDAS];
    __shared__ int s_gt[128 * 8];
    int p = blockIdx.z;
    int koff = p * KSPLIT;
    int m0 = blockIdx.y * BM, n0 = blockIdx.x * BN;
    int tid = threadIdx.x;
    int tx = tid & 15, ty = tid >> 4;
    for (int i = tid; i < 128 * 8; i += 256)
        s_gt[i] = g_gtab[(m0 + (i >> 3)) * 8 + (i & 7)];
    __syncthreads();

    ull acc[8][4];
    #pragma unroll
    for (int i = 0; i < 8; i++)
        #pragma unroll
        for (int j = 0; j < 4; j++) acc[i][j] = 0ull;

    for (int k0 = 0; k0 < KSPLIT; k0 += BK) {
        #pragma unroll
        for (int it = 0; it < 2; it++) {
            int c = tid + it * 256;
            int r = c >> 2, kq = (c & 3) << 2;
            int kg = koff + k0 + kq;
            int dz = kg / C_;
            int ii = kg - dz * C_;
            float4 va = *(const float4*)(x + (size_t)s_gt[r * 8 + dz] + ii);
            As[kq + 0][r] = va.x; As[kq + 1][r] = va.y; As[kq + 2][r] = va.z; As[kq + 3][r] = va.w;
            float4 vb = *(const float4*)(g_wt + (size_t)(n0 + r) * KCONV + kg);
            Bs[kq + 0][r] = vb.x; Bs[kq + 1][r] = vb.y; Bs[kq + 2][r] = vb.z; Bs[kq + 3][r] = vb.w;
        }
        __syncthreads();
        #pragma unroll
        for (int kk = 0; kk < BK; kk++) {
            float4 a0 = *(const float4*)&As[kk][ty * 8];
            float4 a1 = *(const float4*)&As[kk][ty * 8 + 4];
            longlong2 b0 = *(const longlong2*)&Bs[kk][tx * 8];
            longlong2 b1 = *(const longlong2*)&Bs[kk][tx * 8 + 4];
            float av[8] = {a0.x, a0.y, a0.z, a0.w, a1.x, a1.y, a1.z, a1.w};
            #pragma unroll
            for (int i = 0; i < 8; i++) {
                ull pa = pack2(av[i]);
                acc[i][0] = fma2(pa, (ull)b0.x, acc[i][0]);
                acc[i][1] = fma2(pa, (ull)b0.y, acc[i][1]);
                acc[i][2] = fma2(pa, (ull)b1.x, acc[i][2]);
                acc[i][3] = fma2(pa, (ull)b1.y, acc[i][3]);
            }
        }
        __syncthreads();
    }
    float* outp = g_xi2c + (size_t)p * N2 * C_;
    #pragma unroll
    for (int i = 0; i < 8; i++) {
        int mm = m0 + ty * 8 + i;
        float v[8];
        #pragma unroll
        for (int j2 = 0; j2 < 4; j2++) { v[2 * j2] = lo32(acc[i][j2]); v[2 * j2 + 1] = hi32(acc[i][j2]); }
        int nb = n0 + tx * 8;
        *(float4*)(outp + (size_t)mm * C_ + nb) = make_float4(v[0], v[1], v[2], v[3]);
        *(float4*)(outp + (size_t)mm * C_ + nb + 4) = make_float4(v[4], v[5], v[6], v[7]);
    }
}

// ---------------- fused similarity GEMM + rowwise packed max/argmax (KV side, fp32) ----------------
__global__ void __launch_bounds__(256)
k_scores2(int w, const float* __restrict__ X) {
    BsmP p = getp(w);
    __shared__ float As[BK][LDAS], Bs[BK][LDAS];
    __shared__ int arow[128], brow[128];
    __shared__ float ainv[128], binv[128];
    int m0 = blockIdx.y * BM, n0 = blockIdx.x * BN;
    int tid = threadIdx.x;
    int tx = tid & 15, ty = tid >> 4;
    if (tid < 128) {
        int an = p.atok[m0 + tid];
        arow[tid] = an; ainv[tid] = p.invn[an];
        int bn = p.btok[n0 + tid];
        brow[tid] = bn; binv[tid] = p.invn[bn];
    }
    __syncthreads();
    ull acc[8][4];
    #pragma unroll
    for (int i = 0; i < 8; i++)
        #pragma unroll
        for (int j = 0; j < 4; j++) acc[i][j] = 0ull;

    for (int k0 = 0; k0 < C_; k0 += BK) {
        #pragma unroll
        for (int it = 0; it < 2; it++) {
            int c = tid + it * 256;
            int r = c >> 2, kq = (c & 3) << 2;
            float4 va = *(const float4*)(X + (size_t)arow[r] * C_ + k0 + kq);
            As[kq + 0][r] = va.x; As[kq + 1][r] = va.y; As[kq + 2][r] = va.z; As[kq + 3][r] = va.w;
            float4 vb = *(const float4*)(X + (size_t)brow[r] * C_ + k0 + kq);
            Bs[kq + 0][r] = vb.x; Bs[kq + 1][r] = vb.y; Bs[kq + 2][r] = vb.z; Bs[kq + 3][r] = vb.w;
        }
        __syncthreads();
        #pragma unroll
        for (int kk = 0; kk < BK; kk++) {
            float4 a0 = *(const float4*)&As[kk][ty * 8];
            float4 a1 = *(const float4*)&As[kk][ty * 8 + 4];
            longlong2 b0 = *(const longlong2*)&Bs[kk][tx * 8];
            longlong2 b1 = *(const longlong2*)&Bs[kk][tx * 8 + 4];
            float av[8] = {a0.x, a0.y, a0.z, a0.w, a1.x, a1.y, a1.z, a1.w};
            #pragma unroll
            for (int i = 0; i < 8; i++) {
                ull pa = pack2(av[i]);
                acc[i][0] = fma2(pa, (ull)b0.x, acc[i][0]);
                acc[i][1] = fma2(pa, (ull)b0.y, acc[i][1]);
                acc[i][2] = fma2(pa, (ull)b1.x, acc[i][2]);
                acc[i][3] = fma2(pa, (ull)b1.y, acc[i][3]);
            }
        }
        __syncthreads();
    }
    #pragma unroll
    for (int i = 0; i < 8; i++) {
        int row = ty * 8 + i;
        float aiv = ainv[row];
        ull best = 0ull;
        #pragma unroll
        for (int j2 = 0; j2 < 4; j2++) {
            int c0 = tx * 8 + 2 * j2;
            float lo = lo32(acc[i][j2]) * aiv * binv[c0];
            float hi = hi32(acc[i][j2]) * aiv * binv[c0 + 1];
            int g0 = n0 + c0;
            ull klo = ((ull)fmono(lo) << 32) | (ull)(0xFFFFFFFFu - (unsigned)g0);
            ull khi = ((ull)fmono(hi) << 32) | (ull)(0xFFFFFFFFu - (unsigned)(g0 + 1));
            ull kb = klo > khi ? klo : khi;
            if (kb > best) best = kb;
        }
        {
            ull o;
            o = __shfl_xor_sync(0xffffffffu, best, 8);  if (o > best) best = o;
            o = __shfl_xor_sync(0xffffffffu, best, 4);  if (o > best) best = o;
            o = __shfl_xor_sync(0xffffffffu, best, 2);  if (o > best) best = o;
            o = __shfl_xor_sync(0xffffffffu, best, 1);  if (o > best) best = o;
        }
        if (tx == 0) atomicMax(&p.nm[m0 + row], best);
    }
}

// ---------------- exact top-r radix select ----------------
__global__ void k_select(int w) {
    BsmP p = getp(w);
    __shared__ unsigned int hist[256];
    __shared__ ull s_pref, s_mask;
    __shared__ int s_need;
    if (threadIdx.x == 0) { s_pref = 0ull; s_mask = 0ull; s_need = p.R; }
    __syncthreads();
    for (int shift = 56; shift >= 0; shift -= 8) {
        hist[threadIdx.x] = 0u;
        __syncthreads();
        ull pref = s_pref, mask = s_mask;
        for (int m = threadIdx.x; m < p.NA; m += 256) {
            ull key = (p.nm[m] & 0xFFFFFFFF00000000ull) |
                      (ull)(0xFFFFFFFFu - (unsigned)m);
            if ((key & mask) == pref)
                atomicAdd(&hist[(unsigned)(key >> shift) & 255u], 1u);
        }
        __syncthreads();
        if (threadIdx.x == 0) {
            int need = s_need, cum = 0, d;
            for (d = 255; d >= 0; d--) {
                int h = (int)hist[d];
                if (cum + h >= need) break;
                cum += h;
            }
            s_need = need - cum;
            s_pref = s_pref | (((ull)d) << shift);
            s_mask = s_mask | (255ull << shift);
        }
        __syncthreads();
    }
    if (threadIdx.x == 0) *p.thr = s_pref;
}

__global__ void k_classify(int w) {
    BsmP p = getp(w);
    int m = blockIdx.x * blockDim.x + threadIdx.x;
    if (m >= p.NA) return;
    ull pk = p.nm[m];
    ull key = (pk & 0xFFFFFFFF00000000ull) | (ull)(0xFFFFFFFFu - (unsigned)m);
    if (key >= *p.thr) {
        int s = atomicAdd(p.csrc, 1);
        p.srcn[s] = p.atok[m];
        p.srcd[s] = (int)(0xFFFFFFFFu - (unsigned)(pk & 0xFFFFFFFFull));
    } else {
        int s = atomicAdd(p.cunm, 1);
        p.unm[s] = p.atok[m];
    }
}

// ---------------- merge ----------------
__global__ void k_minit(int w, const float* __restrict__ X) {
    BsmP p = getp(w); int j = blockIdx.x;
    int n = p.btok[j];
    for (int c = threadIdx.x; c < C_; c += blockDim.x)
        p.xm[(size_t)(p.UNM + j) * C_ + c] = X[(size_t)n * C_ + c];
    if (threadIdx.x == 0) p.cnt[j] = 1.f;
}
__global__ void k_maccum(int w, const float* __restrict__ X) {
    BsmP p = getp(w); int s = blockIdx.x;
    int n = p.srcn[s]; int dj = p.srcd[s];
    for (int c = threadIdx.x; c < C_; c += blockDim.x)
        atomicAdd(&p.xm[(size_t)(p.UNM + dj) * C_ + c], X[(size_t)n * C_ + c]);
    if (threadIdx.x == 0) atomicAdd(&p.cnt[dj], 1.f);
}
__global__ void k_mdiv(int w) {
    BsmP p = getp(w); int j = blockIdx.x;
    float inv = 1.f / p.cnt[j];
    for (int c = threadIdx.x; c < C_; c += blockDim.x)
        p.xm[(size_t)(p.UNM + j) * C_ + c] *= inv;
}
__global__ void k_mgather(int w, const float* __restrict__ X) {
    BsmP p = getp(w); int i = blockIdx.x;
    int n = p.unm[i];
    for (int c = threadIdx.x; c < C_; c += blockDim.x)
        p.xm[(size_t)i * C_ + c] = X[(size_t)n * C_ + c];
}

// ---------------- V transpose (per head) ----------------
__global__ void k_vt() {
    int t = blockIdx.x * blockDim.x + threadIdx.x;
    if (t >= NH * DH * NKVTOK) return;
    int h = t / (DH * NKVTOK);
    int d = (t / NKVTOK) % DH;
    int k = t % NKVTOK;
    g_vt[t] = g_kv[(size_t)k * (2 * C_) + C_ + h * DH + d];
}

// ---------------- softmax ----------------
__global__ void k_softmax() {
    size_t row = blockIdx.x;
    float* pp = g_sc + row * NKVTOK;
    float mx = -3.4e38f;
    for (int c = threadIdx.x; c < NKVTOK; c += 256) mx = fmaxf(mx, pp[c]);
    mx = blockReduce(mx, 1);
    float s = 0.f;
    for (int c = threadIdx.x; c < NKVTOK; c += 256) {
        float e = expf(pp[c] - mx); pp[c] = e; s += e;
    }
    s = blockReduce(s, 0);
    float inv = 1.f / s;
    for (int c = threadIdx.x; c < NKVTOK; c += 256) pp[c] *= inv;
}

// ---------------- unmerge ----------------
__global__ void k_unmerge_dst(const float* __restrict__ fp, float* __restrict__ out) {
    int j = blockIdx.x; int n = g_btok_q[j];
    for (int c = threadIdx.x; c < C_; c += blockDim.x)
        out[(size_t)n * C_ + c] = fp[(size_t)(UNMQ + j) * C_ + c];
}
__global__ void k_unmerge_unm(const float* __restrict__ fp, float* __restrict__ out) {
    int i = blockIdx.x; int n = g_unm_q[i];
    for (int c = threadIdx.x; c < C_; c += blockDim.x)
        out[(size_t)n * C_ + c] = fp[(size_t)i * C_ + c];
}
__global__ void k_unmerge_src(const float* __restrict__ fp, float* __restrict__ out) {
    int s = blockIdx.x; int n = g_srcn_q[s]; int dj = g_srcd_q[s];
    for (int c = threadIdx.x; c < C_; c += blockDim.x)
        out[(size_t)n * C_ + c] = fp[(size_t)(UNMQ + dj) * C_ + c];
}

// ---------------- host ----------------
extern "C" void kernel_launch(void* const* d_in, const int* in_sizes, int n_in,
                              void* d_out, int out_size) {
    const float* x   = (const float*)d_in[0];
    const float* srw = (const float*)d_in[1];
    const float* srb = (const float*)d_in[2];
    const float* lng = (const float*)d_in[3];
    const float* lnb = (const float*)d_in[4];
    const float* Wq  = (const float*)d_in[5];
    const float* Wkv = (const float*)d_in[6];
    const float* Wp  = (const float*)d_in[7];
    const float* bpb = (const float*)d_in[8];
    float* out = (float*)d_out;

    void *vp;
    float *p_xk, *p_xq, *p_xkm, *p_qb, *p_kv, *p_fp, *p_ao;
    cudaGetSymbolAddress(&vp, g_xk);   p_xk   = (float*)vp;
    cudaGetSymbolAddress(&vp, g_xq);   p_xq   = (float*)vp;
    cudaGetSymbolAddress(&vp, g_xkm);  p_xkm  = (float*)vp;
    cudaGetSymbolAddress(&vp, g_qb);   p_qb   = (float*)vp;
    cudaGetSymbolAddress(&vp, g_kv);   p_kv   = (float*)vp;
    cudaGetSymbolAddress(&vp, g_fp);   p_fp   = (float*)vp;
    cudaGetSymbolAddress(&vp, g_ao);   p_ao   = (float*)vp;

    k_reset<<<(NQ_A + 255) / 256, 256>>>();
    k_tokmap<<<(NQ + 255) / 256, 256>>>(0, DQ, HQ, WQ);
    k_tokmap<<<(N2 + 255) / 256, 256>>>(1, D2, H2, W2);
    k_gtab<<<(N2 + 255) / 256, 256>>>();
    k_invn_x<<<NQ, 64>>>(x);
    k_wtrans<<<(C_ * KCONV + 255) / 256, 256>>>(srw);

    // SR conv: split-K x3 f32x2 GEMM with fused im2col, then LN combines partials + bias
    k_conv_sk<<<dim3(C_ / BN, N2 / BM, 3), 256>>>(x);
    k_ln<<<N2, 256>>>(srb, lng, lnb);

    // Q-side BSM: bf16 mma.sync approx scores + exact refinement
    k_tobf_a<<<(NQ_A * (C_ / 4) + 255) / 256, 256>>>(x);
    k_tobf_b<<<(NQ_DST * (C_ / 4) + 255) / 256, 256>>>(x);
    k_scores_mma<<<dim3(NQ_DST / 128, NQ_A / 128), 256>>>();
    k_refine<<<NQ_A, 128>>>(x);
    k_select<<<1, 256>>>(0);
    k_classify<<<(NQ_A + 255) / 256, 256>>>(0);
    k_minit<<<NQ_DST, 256>>>(0, x);
    k_maccum<<<RQ, 256>>>(0, x);
    k_mdiv<<<NQ_DST, 256>>>(0);
    k_mgather<<<UNMQ, 256>>>(0, x);

    // KV-side BSM (small; exact fp32 path)
    k_scores2<<<dim3(NKV_DST / BN, NKV_A / BM), 256>>>(1, p_xk);
    k_select<<<1, 256>>>(1);
    k_classify<<<(NKV_A + 255) / 256, 256>>>(1);
    k_minit<<<NKV_DST, 256>>>(1, p_xk);
    k_maccum<<<RKV, 256>>>(1, p_xk);
    k_mdiv<<<NKV_DST, 256>>>(1);
    k_mgather<<<UNMKV, 256>>>(1, p_xk);

    // projections (tf32 mma — value path)
    k_gemm_tf32<<<dim3(C_ / 128, NQTOK / 128), 256>>>(p_xq, C_, Wq, C_,
                                                      p_qb, C_, NQTOK, C_, C_, nullptr, 1.f);
    k_gemm_tf32<<<dim3(2 * C_ / 128, NKVTOK / 128), 256>>>(p_xkm, C_, Wkv, C_,
                                                           p_kv, 2 * C_, NKVTOK, 2 * C_, C_, nullptr, 1.f);
    k_vt<<<(NH * DH * NKVTOK + 255) / 256, 256>>>();

    // attention (two-pass, batched over heads, tf32 mma)
    float scale = 1.0f / sqrtf((float)DH);
    k_qk_tf32<<<dim3(NKVTOK / 128, NQTOK / 128, NH), 256>>>(scale);
    k_softmax<<<NH * NQTOK, 256>>>();
    k_av_tf32<<<dim3(1, NQTOK / 128, NH), 256>>>();

    // output projection + bias (tf32), then unmerge scatter
    k_gemm_tf32<<<dim3(C_ / 128, NQTOK / 128), 256>>>(p_ao, C_, Wp, C_,
                                                      p_fp, C_, NQTOK, C_, C_, bpb, 1.f);
    k_unmerge_dst<<<NQ_DST, 256>>>(p_fp, out);
    k_unmerge_unm<<<UNMQ, 256>>>(p_fp, out);
    k_unmerge_src<<<RQ, 256>>>(p_fp, out);
}